// round 9
// baseline (speedup 1.0000x reference)
#include <cuda_runtime.h>
#include <cstdint>

#define N_ATOMS 100000
#define N_ATOMS_PAD 102400   // multiple of 4096 for the scan
#define N_EDGES 400000
#define N_MOLS  4096
#define ATOM_FDIM 133
#define BOND_FDIM 14
#define HIDDEN 300
#define N_LABELS 12
#define NPAD 320        // padded hidden width
#define KX 144          // padded atom feature dim (multiple of 16)
#define KE 16           // padded bond feature dim
#define KH 304          // padded hidden as K-dim (multiple of 16)

#define BM 128
#define BN 160
#define BK 16
#define AS_STRIDE 20    // floats; banks (20*fr+fc)%32 all-distinct
#define BS_STRIDE2 164  // float2; (fc*164+fr) mod 16 == fc*4+fr -> both LDS.64 phases conflict-free

// ------------------------- scratch (static, no allocs) -------------------------
__device__ float g_xpad[(size_t)N_ATOMS * KX];
__device__ float g_hv  [(size_t)N_ATOMS * NPAD];
__device__ float g_hv2 [(size_t)N_ATOMS * NPAD];
__device__ float g_P   [(size_t)N_ATOMS * NPAD];
__device__ float g_agg [(size_t)N_ATOMS * NPAD];
__device__ float g_mol [(size_t)N_MOLS * NPAD];
__device__ float g_ffn [(size_t)N_MOLS * NPAD];

// packed-pair weights: row r=(k/8)*4+fc holds float2(W[k0+fc][n], W[k0+fc+4][n])
__device__ float g_atomWp[KX * NPAD];
__device__ float g_WiTopp[KH * NPAD];
__device__ float g_Wop   [2 * KH * NPAD];
__device__ float g_ffn1p [KH * NPAD];
__device__ float g_WiBot [KE * NPAD];     // row-major [14+pad][320] for gather
__device__ float g_atomB[NPAD];
__device__ float g_WoB  [NPAD];
__device__ float g_ffn1B[NPAD];
__device__ float g_zeros[NPAD];   // stays zero

// CSR scratch
__device__ int g_counts[N_ATOMS_PAD];
__device__ int g_rowptr[N_ATOMS_PAD + 1];
__device__ int g_cursor[N_ATOMS];
__device__ int g_esrc[N_EDGES];
__device__ int g_eid [N_EDGES];
__device__ int g_molptr[N_MOLS + 1];
__device__ float g_eacsr[(size_t)N_EDGES * 16];   // edge_attr permuted to CSR order, padded to 16

// ------------------------- helpers -------------------------
__device__ __forceinline__ float tf32r(float x) {
    asm("cvt.rna.tf32.f32 %0, %0;" : "+f"(x));
    return x;
}
__device__ __forceinline__ uint32_t smem_u32(const void* p) {
    return (uint32_t)__cvta_generic_to_shared(p);
}

// ------------------------- repack: zero-padded copy (+optional tf32 round) ------------
__global__ void repack(float* __restrict__ dst, const float* __restrict__ src,
                       int dstR, int dstC, int srcR, int srcC, int srcRow0, int doRound) {
    int idx = blockIdx.x * blockDim.x + threadIdx.x;
    if (idx >= dstR * dstC) return;
    int r = idx / dstC, c = idx - r * dstC;
    float v = 0.f;
    if (r < srcR && c < srcC) v = src[(size_t)(r + srcRow0) * srcC + c];
    dst[idx] = doRound ? tf32r(v) : v;
}

// packed-pair weight repack: dst row (k/8)*4+fc, element n = (W[k][n], W[k+4][n]) tf32-rounded
__global__ void repackP(float2* __restrict__ dst, const float* __restrict__ src,
                        int Ktot, int kValid, int srcC, int srcRow0) {
    int idx = blockIdx.x * blockDim.x + threadIdx.x;
    int total = (Ktot >> 3) * 4 * NPAD;
    if (idx >= total) return;
    int row = idx / NPAD, n = idx - row * NPAD;
    int kb = row >> 2, fc = row & 3;
    int klo = kb * 8 + fc, khi = klo + 4;
    float vlo = 0.f, vhi = 0.f;
    if (klo < kValid && n < srcC) vlo = tf32r(src[(size_t)(klo + srcRow0) * srcC + n]);
    if (khi < kValid && n < srcC) vhi = tf32r(src[(size_t)(khi + srcRow0) * srcC + n]);
    dst[idx] = make_float2(vlo, vhi);
}

__global__ void zeroI(int* __restrict__ p, int n) {
    int i = blockIdx.x * blockDim.x + threadIdx.x;
    if (i < n) p[i] = 0;
}

// ------------------------- CSR build -------------------------
__global__ void hist_dst(const int* __restrict__ dst, int* __restrict__ counts) {
    int e = blockIdx.x * blockDim.x + threadIdx.x;
    if (e < N_EDGES) atomicAdd(&counts[dst[e]], 1);
}

__global__ __launch_bounds__(1024)
void scan_counts(const int* __restrict__ counts, int* __restrict__ rowptr) {
    __shared__ int warp_sums[32];
    __shared__ int s_carry;
    const int tid = threadIdx.x;
    const int lane = tid & 31, wid = tid >> 5;
    if (tid == 0) s_carry = 0;
    __syncthreads();
    for (int base = 0; base < N_ATOMS_PAD; base += 4096) {
        int4 v = *(const int4*)(counts + base + tid * 4);
        int tsum = v.x + v.y + v.z + v.w;
        int val = tsum;
        #pragma unroll
        for (int off = 1; off < 32; off <<= 1) {
            int t = __shfl_up_sync(~0u, val, off);
            if (lane >= off) val += t;
        }
        if (lane == 31) warp_sums[wid] = val;
        __syncthreads();
        if (wid == 0) {
            int w = warp_sums[lane];
            #pragma unroll
            for (int off = 1; off < 32; off <<= 1) {
                int t = __shfl_up_sync(~0u, w, off);
                if (lane >= off) w += t;
            }
            warp_sums[lane] = w;
        }
        __syncthreads();
        int carry = s_carry;
        int excl = carry + (wid ? warp_sums[wid - 1] : 0) + (val - tsum);
        int idx = base + tid * 4;
        rowptr[idx + 0] = excl;
        rowptr[idx + 1] = excl + v.x;
        rowptr[idx + 2] = excl + v.x + v.y;
        rowptr[idx + 3] = excl + v.x + v.y + v.z;
        __syncthreads();
        if (tid == 0) s_carry = carry + warp_sums[31];
        __syncthreads();
    }
    if (threadIdx.x == 0) rowptr[N_ATOMS_PAD] = s_carry;
}

__global__ void copy_cursor(const int* __restrict__ rowptr, int* __restrict__ cursor) {
    int i = blockIdx.x * blockDim.x + threadIdx.x;
    if (i < N_ATOMS) cursor[i] = rowptr[i];
}

__global__ void fill_csr(const int* __restrict__ src, const int* __restrict__ dst,
                         int* __restrict__ cursor,
                         int* __restrict__ esrc, int* __restrict__ eid) {
    int e = blockIdx.x * blockDim.x + threadIdx.x;
    if (e >= N_EDGES) return;
    int d = dst[e];
    int pos = atomicAdd(&cursor[d], 1);
    esrc[pos] = src[e];
    eid[pos]  = e;
}

// permute edge_attr into CSR order (padded to 16 floats/row)
__global__ void permute_ea(const float* __restrict__ ea, const int* __restrict__ eid,
                           float* __restrict__ eacsr) {
    int idx = blockIdx.x * blockDim.x + threadIdx.x;
    if (idx >= N_EDGES * 16) return;
    int p = idx >> 4, c = idx & 15;
    float v = 0.f;
    if (c < BOND_FDIM) v = ea[(size_t)eid[p] * BOND_FDIM + c];
    eacsr[idx] = v;
}

__global__ void build_molptr(const int* __restrict__ batch, int* __restrict__ molptr) {
    int i = blockIdx.x * blockDim.x + threadIdx.x;
    if (i >= N_ATOMS) return;
    int b = batch[i];
    int bp = (i == 0) ? -1 : batch[i - 1];
    for (int m = bp + 1; m <= b; m++) molptr[m] = i;
    if (i == N_ATOMS - 1)
        for (int m = b + 1; m <= N_MOLS; m++) molptr[m] = N_ATOMS;
}

// ------------------------- tf32 tensor-core GEMM -------------------------
// C[M x 320] = round_tf32(relu?(A @ W + bias)).
// A = virtual concat of A1 (K1 cols) and A2 (K2 cols); inputs pre-rounded.
// W in packed-pair layout Wp (float2 rows of NPAD).
// Block tile 128x160, BK=16, cp.async double-buffered.
// 512 threads: 16 warps in 4(m) x 4(n); warp tile 32x40 (2 m16-tiles x 5 n8-tiles).
__global__ __launch_bounds__(512)
void gemm_tf32(const float* __restrict__ A1, int lda1, int K1,
               const float* __restrict__ A2, int lda2, int K2,
               const float2* __restrict__ Wp, const float* __restrict__ bias,
               float* __restrict__ C, int M, int doRelu) {
    __shared__ float  As[2][BM][AS_STRIDE];        // m-major
    __shared__ float2 Bs[2][8][BS_STRIDE2];        // packed k-pairs, rows = ks*4+fc

    const int tid  = threadIdx.x;
    const int lane = tid & 31;
    const int wid  = tid >> 5;
    const int wm0  = (wid >> 2) * 32;   // 0,32,64,96
    const int wn0  = (wid & 3) * 40;    // 0,40,80,120
    const int row0 = blockIdx.x * BM;
    const int n0   = blockIdx.y * BN;
    const int fr = lane >> 2;
    const int fc = lane & 3;
    const int Ktot = K1 + K2;
    const int niter = Ktot / BK;

    float acc[2][5][4];
    #pragma unroll
    for (int mt = 0; mt < 2; mt++)
        #pragma unroll
        for (int nt = 0; nt < 5; nt++)
            #pragma unroll
            for (int i = 0; i < 4; i++) acc[mt][nt][i] = 0.f;

    // ---- async staging of tile k0 into buffer buf ----
    auto stage = [&](int k0, int buf) {
        const float* Asrc; int lda, kb;
        if (k0 < K1) { Asrc = A1; lda = lda1; kb = k0; }
        else         { Asrc = A2; lda = lda2; kb = k0 - K1; }
        // A tile: 128 rows x 16 k = 512 16B-chunks, 1 per thread
        {
            int m = tid >> 2, kq = (tid & 3) << 2;
            int g = row0 + m;
            const float* src = Asrc + (size_t)g * lda + kb + kq;
            uint32_t dst = smem_u32(&As[buf][m][kq]);
            int ss = (g < M) ? 16 : 0;
            asm volatile("cp.async.cg.shared.global [%0], [%1], 16, %2;"
                         :: "r"(dst), "l"(src), "r"(ss));
        }
        // B tile (packed): 8 rows x 160 float2 = 640 16B-chunks
        #pragma unroll
        for (int j = 0; j < 2; j++) {
            int chunk = tid + j * 512;
            if (chunk < 640) {
                int rp = chunk / 80, col2 = (chunk - rp * 80) << 1;
                const float2* src = Wp + (size_t)((k0 >> 3) * 4 + rp) * NPAD + n0 + col2;
                uint32_t dst = smem_u32(&Bs[buf][rp][col2]);
                asm volatile("cp.async.cg.shared.global [%0], [%1], 16;"
                             :: "r"(dst), "l"(src));
            }
        }
        asm volatile("cp.async.commit_group;");
    };

    stage(0, 0);

    for (int it = 0; it < niter; it++) {
        int buf = it & 1;
        bool more = (it + 1 < niter);
        if (more) stage((it + 1) * BK, buf ^ 1);
        if (more) asm volatile("cp.async.wait_group 1;");
        else      asm volatile("cp.async.wait_group 0;");
        __syncthreads();

        #pragma unroll
        for (int ks = 0; ks < 2; ks++) {
            const int kk = ks * 8;
            uint32_t a[2][4], b[5][2];
            #pragma unroll
            for (int mt = 0; mt < 2; mt++) {
                int mr = wm0 + mt * 16 + fr;
                a[mt][0] = __float_as_uint(As[buf][mr][kk + fc]);
                a[mt][1] = __float_as_uint(As[buf][mr + 8][kk + fc]);
                a[mt][2] = __float_as_uint(As[buf][mr][kk + fc + 4]);
                a[mt][3] = __float_as_uint(As[buf][mr + 8][kk + fc + 4]);
            }
            #pragma unroll
            for (int nt = 0; nt < 5; nt++) {
                int nc = wn0 + nt * 8 + fr;
                float2 bv = Bs[buf][ks * 4 + fc][nc];
                b[nt][0] = __float_as_uint(bv.x);
                b[nt][1] = __float_as_uint(bv.y);
            }
            #pragma unroll
            for (int mt = 0; mt < 2; mt++)
                #pragma unroll
                for (int nt = 0; nt < 5; nt++)
                    asm volatile(
                        "mma.sync.aligned.m16n8k8.row.col.f32.tf32.tf32.f32 "
                        "{%0,%1,%2,%3}, {%4,%5,%6,%7}, {%8,%9}, {%0,%1,%2,%3};"
                        : "+f"(acc[mt][nt][0]), "+f"(acc[mt][nt][1]),
                          "+f"(acc[mt][nt][2]), "+f"(acc[mt][nt][3])
                        : "r"(a[mt][0]), "r"(a[mt][1]), "r"(a[mt][2]), "r"(a[mt][3]),
                          "r"(b[nt][0]), "r"(b[nt][1]));
        }
        __syncthreads();
    }

    // epilogue: bias + relu? + tf32 round
    #pragma unroll
    for (int mt = 0; mt < 2; mt++) {
        int r = row0 + wm0 + mt * 16 + fr;
        #pragma unroll
        for (int nt = 0; nt < 5; nt++) {
            int cbase = n0 + wn0 + nt * 8 + (fc << 1);
            float2 bv = *(const float2*)&bias[cbase];
            if (r < M) {
                float2 v = make_float2(acc[mt][nt][0] + bv.x, acc[mt][nt][1] + bv.y);
                if (doRelu) { v.x = fmaxf(v.x, 0.f); v.y = fmaxf(v.y, 0.f); }
                v.x = tf32r(v.x); v.y = tf32r(v.y);
                *(float2*)(C + (size_t)r * NPAD + cbase) = v;
            }
            if (r + 8 < M) {
                float2 v = make_float2(acc[mt][nt][2] + bv.x, acc[mt][nt][3] + bv.y);
                if (doRelu) { v.x = fmaxf(v.x, 0.f); v.y = fmaxf(v.y, 0.f); }
                v.x = tf32r(v.x); v.y = tf32r(v.y);
                *(float2*)(C + (size_t)(r + 8) * NPAD + cbase) = v;
            }
        }
    }
}

// ------------------------- CSR gather: agg[v] = sum_in relu(P[src] + eacsr[p] @ WiBot) -----
// 2 warps per atom: each warp owns a 160-column half-row.
__global__ __launch_bounds__(256)
void gather_agg(const float* __restrict__ P, const float* __restrict__ eacsr,
                const float* __restrict__ WiBot,
                const int* __restrict__ rowptr, const int* __restrict__ esrc,
                float* __restrict__ agg) {
    __shared__ float Ws[14 * NPAD];
    for (int i = threadIdx.x; i < 14 * NPAD; i += 256) Ws[i] = WiBot[i];
    __syncthreads();

    int gw = (blockIdx.x * 256 + threadIdx.x) >> 5;   // global warp id
    int v  = gw >> 1;
    int jh = (gw & 1) * 160;                          // column-half offset
    int lane = threadIdx.x & 31;
    if (v >= N_ATOMS) return;
    int beg = rowptr[v], end = rowptr[v + 1];

    float acc[5];
    #pragma unroll
    for (int j = 0; j < 5; j++) acc[j] = 0.f;

    for (int p = beg; p < end; p++) {
        int s = esrc[p];
        float eav = (lane < 16) ? eacsr[(size_t)p * 16 + lane] : 0.f;
        float ef[14];
        #pragma unroll
        for (int f = 0; f < 14; f++) ef[f] = __shfl_sync(~0u, eav, f);
        const float* Pr = P + (size_t)s * NPAD + jh;
        #pragma unroll
        for (int j = 0; j < 5; j++) {
            float m = Pr[lane + 32 * j];
            #pragma unroll
            for (int f = 0; f < 14; f++)
                m = fmaf(ef[f], Ws[f * NPAD + jh + lane + 32 * j], m);
            acc[j] += fmaxf(m, 0.f);
        }
    }
    float* ag = agg + (size_t)v * NPAD + jh;
    #pragma unroll
    for (int j = 0; j < 5; j++) ag[lane + 32 * j] = tf32r(acc[j]);
}

// ------------------------- molecule pooling (contiguous ranges) -------
__global__ void mol_sum(const float* __restrict__ hv, const int* __restrict__ molptr,
                        float* __restrict__ mol) {
    int m = (blockIdx.x * blockDim.x + threadIdx.x) >> 5;
    int lane = threadIdx.x & 31;
    if (m >= N_MOLS) return;
    int beg = molptr[m], end = molptr[m + 1];
    float acc[10];
    #pragma unroll
    for (int j = 0; j < 10; j++) acc[j] = 0.f;
    for (int a = beg; a < end; a++) {
        const float* hr = hv + (size_t)a * NPAD;
        #pragma unroll
        for (int j = 0; j < 10; j++) acc[j] += hr[lane + 32 * j];
    }
    float* mr = mol + (size_t)m * NPAD;
    #pragma unroll
    for (int j = 0; j < 10; j++) mr[lane + 32 * j] = tf32r(acc[j]);
}

// ------------------------- final: out = ffn @ ffn2 + b2 -------------------------
__global__ void finalk(const float* __restrict__ F, const float* __restrict__ W2,
                       const float* __restrict__ b2, float* __restrict__ out) {
    int w = (blockIdx.x * blockDim.x + threadIdx.x) >> 5;
    int lane = threadIdx.x & 31;
    if (w >= N_MOLS) return;
    float acc = (lane < 12) ? b2[lane] : 0.f;
    const float* f = F + (size_t)w * NPAD;
    for (int j = 0; j < HIDDEN; j++) {
        float fv = __ldg(f + j);
        if (lane < 12) acc = fmaf(fv, W2[j * 12 + lane], acc);
    }
    if (lane < 12) out[w * 12 + lane] = acc;
}

// ------------------------- host launch -------------------------
static inline dim3 rep_grid(int n) { return dim3((n + 255) / 256); }

extern "C" void kernel_launch(void* const* d_in, const int* in_sizes, int n_in,
                              void* d_out, int out_size) {
    const float* x      = (const float*)d_in[0];
    const int*   ei     = (const int*)  d_in[1];   // [2, N_EDGES]
    const float* ea     = (const float*)d_in[2];
    const int*   batch  = (const int*)  d_in[3];
    const float* atom_W = (const float*)d_in[4];
    const float* atom_b = (const float*)d_in[5];
    // d_in[6], d_in[7]: bond_W / bond_b  -> dead code
    const float* Wi     = (const float*)d_in[8];
    // d_in[9]: Wh -> dead code
    const float* Wo     = (const float*)d_in[10];
    const float* Wo_b   = (const float*)d_in[11];
    const float* ffn1_W = (const float*)d_in[12];
    const float* ffn1_b = (const float*)d_in[13];
    const float* ffn2_W = (const float*)d_in[14];
    const float* ffn2_b = (const float*)d_in[15];
    float* out = (float*)d_out;

    float *p_xpad, *p_hv, *p_hv2, *p_P, *p_agg, *p_mol, *p_ffn;
    float *p_atomWp, *p_WiTopp, *p_Wop, *p_ffn1p, *p_WiBot;
    float *p_atomB, *p_WoB, *p_ffn1B, *p_zeros, *p_eacsr;
    int *p_counts, *p_rowptr, *p_cursor, *p_esrc, *p_eid, *p_molptr;
    cudaGetSymbolAddress((void**)&p_xpad,  g_xpad);
    cudaGetSymbolAddress((void**)&p_hv,    g_hv);
    cudaGetSymbolAddress((void**)&p_hv2,   g_hv2);
    cudaGetSymbolAddress((void**)&p_P,     g_P);
    cudaGetSymbolAddress((void**)&p_agg,   g_agg);
    cudaGetSymbolAddress((void**)&p_mol,   g_mol);
    cudaGetSymbolAddress((void**)&p_ffn,   g_ffn);
    cudaGetSymbolAddress((void**)&p_atomWp, g_atomWp);
    cudaGetSymbolAddress((void**)&p_WiTopp, g_WiTopp);
    cudaGetSymbolAddress((void**)&p_Wop,    g_Wop);
    cudaGetSymbolAddress((void**)&p_ffn1p,  g_ffn1p);
    cudaGetSymbolAddress((void**)&p_WiBot,  g_WiBot);
    cudaGetSymbolAddress((void**)&p_atomB, g_atomB);
    cudaGetSymbolAddress((void**)&p_WoB,   g_WoB);
    cudaGetSymbolAddress((void**)&p_ffn1B, g_ffn1B);
    cudaGetSymbolAddress((void**)&p_zeros, g_zeros);
    cudaGetSymbolAddress((void**)&p_eacsr, g_eacsr);
    cudaGetSymbolAddress((void**)&p_counts, g_counts);
    cudaGetSymbolAddress((void**)&p_rowptr, g_rowptr);
    cudaGetSymbolAddress((void**)&p_cursor, g_cursor);
    cudaGetSymbolAddress((void**)&p_esrc,   g_esrc);
    cudaGetSymbolAddress((void**)&p_eid,    g_eid);
    cudaGetSymbolAddress((void**)&p_molptr, g_molptr);

    const int* e_src = ei;
    const int* e_dst = ei + N_EDGES;

    // ---- repack inputs / weights (x pre-rounded; weights packed-pair + pre-rounded) ----
    repack<<<rep_grid(N_ATOMS * KX), 256>>>(p_xpad, x, N_ATOMS, KX, N_ATOMS, ATOM_FDIM, 0, 1);
    repackP<<<rep_grid(KX / 2 * NPAD), 256>>>((float2*)p_atomWp, atom_W, KX, ATOM_FDIM, HIDDEN, 0);
    repackP<<<rep_grid(KH / 2 * NPAD), 256>>>((float2*)p_WiTopp, Wi, KH, HIDDEN, HIDDEN, 0);
    repackP<<<rep_grid(KH / 2 * NPAD), 256>>>((float2*)p_Wop, Wo, KH, HIDDEN, HIDDEN, 0);
    repackP<<<rep_grid(KH / 2 * NPAD), 256>>>((float2*)p_Wop + (KH / 8) * 4 * NPAD, Wo,
                                              KH, HIDDEN, HIDDEN, HIDDEN);
    repackP<<<rep_grid(KH / 2 * NPAD), 256>>>((float2*)p_ffn1p, ffn1_W, KH, HIDDEN, HIDDEN, 0);
    repack<<<rep_grid(KE * NPAD), 256>>>(p_WiBot, Wi, KE, NPAD, BOND_FDIM, HIDDEN, HIDDEN, 1);
    repack<<<rep_grid(NPAD), 256>>>(p_atomB, atom_b, 1, NPAD, 1, HIDDEN, 0, 0);
    repack<<<rep_grid(NPAD), 256>>>(p_WoB, Wo_b, 1, NPAD, 1, HIDDEN, 0, 0);
    repack<<<rep_grid(NPAD), 256>>>(p_ffn1B, ffn1_b, 1, NPAD, 1, HIDDEN, 0, 0);

    // ---- CSR build (by dst) + ea permute + mol boundaries ----
    zeroI<<<rep_grid(N_ATOMS_PAD), 256>>>(p_counts, N_ATOMS_PAD);
    hist_dst<<<rep_grid(N_EDGES), 256>>>(e_dst, p_counts);
    scan_counts<<<1, 1024>>>(p_counts, p_rowptr);
    copy_cursor<<<rep_grid(N_ATOMS), 256>>>(p_rowptr, p_cursor);
    fill_csr<<<rep_grid(N_EDGES), 256>>>(e_src, e_dst, p_cursor, p_esrc, p_eid);
    permute_ea<<<rep_grid(N_EDGES * 16), 256>>>(ea, p_eid, p_eacsr);
    build_molptr<<<rep_grid(N_ATOMS), 256>>>(batch, p_molptr);

    dim3 gAtom((N_ATOMS + BM - 1) / BM, NPAD / BN);
    dim3 gMol ((N_MOLS  + BM - 1) / BM, NPAD / BN);

    // h_v = relu(x @ atom_W + atom_b)
    gemm_tf32<<<gAtom, 512>>>(p_xpad, KX, KX, nullptr, 0, 0,
                              (const float2*)p_atomWp, p_atomB, p_hv, N_ATOMS, 1);

    int gather_blocks = (N_ATOMS * 2 * 32 + 255) / 256;

    float* cur = p_hv;
    float* nxt = p_hv2;
    for (int d = 0; d < 3; d++) {
        // P = h_v @ Wi_top
        gemm_tf32<<<gAtom, 512>>>(cur, NPAD, KH, nullptr, 0, 0,
                                  (const float2*)p_WiTopp, p_zeros, p_P, N_ATOMS, 0);
        // agg[v] = sum over in-edges of relu(P[src] + edge_attr @ WiBot)
        gather_agg<<<gather_blocks, 256>>>(p_P, p_eacsr, p_WiBot, p_rowptr, p_esrc, p_agg);
        // h_v = relu([h_v, agg] @ Wo + Wo_b)
        gemm_tf32<<<gAtom, 512>>>(cur, NPAD, KH, p_agg, NPAD, KH,
                                  (const float2*)p_Wop, p_WoB, nxt, N_ATOMS, 1);
        float* t = cur; cur = nxt; nxt = t;
    }

    // mol_repr = segment_sum(h_v, batch)
    mol_sum<<<(N_MOLS * 32 + 255) / 256, 256>>>(cur, p_molptr, p_mol);
    // ffn = relu(mol @ ffn1 + b1)
    gemm_tf32<<<gMol, 512>>>(p_mol, NPAD, KH, nullptr, 0, 0,
                             (const float2*)p_ffn1p, p_ffn1B, p_ffn, N_MOLS, 1);
    // out = ffn @ ffn2 + b2
    finalk<<<(N_MOLS * 32 + 255) / 256, 256>>>(p_ffn, ffn2_W, ffn2_b, out);
}

// round 10
// speedup vs baseline: 1.2386x; 1.2386x over previous
#include <cuda_runtime.h>
#include <cstdint>

#define N_ATOMS 100000
#define N_ATOMS_PAD 102400   // multiple of 4096 for the scan
#define N_EDGES 400000
#define N_MOLS  4096
#define ATOM_FDIM 133
#define BOND_FDIM 14
#define HIDDEN 300
#define N_LABELS 12
#define NPAD 320        // padded hidden width
#define KX 144          // padded atom feature dim (multiple of 16)
#define KE 16           // padded bond feature dim
#define KH 304          // padded hidden as K-dim (multiple of 16)

#define BM 64
#define BN 160
#define BK 16
#define AS_STRIDE 20    // floats; banks (20*fr+fc)%32 all-distinct
#define BS_STRIDE2 164  // float2; (fc*164+fr) mod 16 == fc*4+fr -> both LDS.64 phases conflict-free

// ------------------------- scratch (static, no allocs) -------------------------
__device__ float g_xpad[(size_t)N_ATOMS * KX];
__device__ float g_hv  [(size_t)N_ATOMS * NPAD];
__device__ float g_hv2 [(size_t)N_ATOMS * NPAD];
__device__ float g_P   [(size_t)N_ATOMS * NPAD];
__device__ float g_agg [(size_t)N_ATOMS * NPAD];
__device__ float g_mol [(size_t)N_MOLS * NPAD];
__device__ float g_ffn [(size_t)N_MOLS * NPAD];

// packed-pair weights: row r=(k/8)*4+fc holds float2(W[k0+fc][n], W[k0+fc+4][n])
__device__ float g_atomWp[KX * NPAD];
__device__ float g_WiTopp[KH * NPAD];
__device__ float g_Wop   [2 * KH * NPAD];
__device__ float g_ffn1p [KH * NPAD];
__device__ float g_WiBot [KE * NPAD];     // row-major [14+pad][320] for gather
__device__ float g_atomB[NPAD];
__device__ float g_WoB  [NPAD];
__device__ float g_ffn1B[NPAD];
__device__ float g_zeros[NPAD];   // stays zero

// CSR scratch
__device__ int g_counts[N_ATOMS_PAD];
__device__ int g_rowptr[N_ATOMS_PAD + 1];
__device__ int g_cursor[N_ATOMS];
__device__ int g_esrc[N_EDGES];
__device__ int g_eid [N_EDGES];
__device__ int g_molptr[N_MOLS + 1];
__device__ float g_eacsr[(size_t)N_EDGES * 16];   // edge_attr permuted to CSR order, padded to 16

// ------------------------- helpers -------------------------
__device__ __forceinline__ float tf32r(float x) {
    asm("cvt.rna.tf32.f32 %0, %0;" : "+f"(x));
    return x;
}
__device__ __forceinline__ uint32_t smem_u32(const void* p) {
    return (uint32_t)__cvta_generic_to_shared(p);
}

// ------------------------- repack: zero-padded copy (+optional tf32 round) ------------
__global__ void repack(float* __restrict__ dst, const float* __restrict__ src,
                       int dstR, int dstC, int srcR, int srcC, int srcRow0, int doRound) {
    int idx = blockIdx.x * blockDim.x + threadIdx.x;
    if (idx >= dstR * dstC) return;
    int r = idx / dstC, c = idx - r * dstC;
    float v = 0.f;
    if (r < srcR && c < srcC) v = src[(size_t)(r + srcRow0) * srcC + c];
    dst[idx] = doRound ? tf32r(v) : v;
}

// packed-pair weight repack: dst row (k/8)*4+fc, element n = (W[k][n], W[k+4][n]) tf32-rounded
__global__ void repackP(float2* __restrict__ dst, const float* __restrict__ src,
                        int Ktot, int kValid, int srcC, int srcRow0) {
    int idx = blockIdx.x * blockDim.x + threadIdx.x;
    int total = (Ktot >> 3) * 4 * NPAD;
    if (idx >= total) return;
    int row = idx / NPAD, n = idx - row * NPAD;
    int kb = row >> 2, fc = row & 3;
    int klo = kb * 8 + fc, khi = klo + 4;
    float vlo = 0.f, vhi = 0.f;
    if (klo < kValid && n < srcC) vlo = tf32r(src[(size_t)(klo + srcRow0) * srcC + n]);
    if (khi < kValid && n < srcC) vhi = tf32r(src[(size_t)(khi + srcRow0) * srcC + n]);
    dst[idx] = make_float2(vlo, vhi);
}

__global__ void zeroI(int* __restrict__ p, int n) {
    int i = blockIdx.x * blockDim.x + threadIdx.x;
    if (i < n) p[i] = 0;
}

// ------------------------- CSR build -------------------------
__global__ void hist_dst(const int* __restrict__ dst, int* __restrict__ counts) {
    int e = blockIdx.x * blockDim.x + threadIdx.x;
    if (e < N_EDGES) atomicAdd(&counts[dst[e]], 1);
}

__global__ __launch_bounds__(1024)
void scan_counts(const int* __restrict__ counts, int* __restrict__ rowptr) {
    __shared__ int warp_sums[32];
    __shared__ int s_carry;
    const int tid = threadIdx.x;
    const int lane = tid & 31, wid = tid >> 5;
    if (tid == 0) s_carry = 0;
    __syncthreads();
    for (int base = 0; base < N_ATOMS_PAD; base += 4096) {
        int4 v = *(const int4*)(counts + base + tid * 4);
        int tsum = v.x + v.y + v.z + v.w;
        int val = tsum;
        #pragma unroll
        for (int off = 1; off < 32; off <<= 1) {
            int t = __shfl_up_sync(~0u, val, off);
            if (lane >= off) val += t;
        }
        if (lane == 31) warp_sums[wid] = val;
        __syncthreads();
        if (wid == 0) {
            int w = warp_sums[lane];
            #pragma unroll
            for (int off = 1; off < 32; off <<= 1) {
                int t = __shfl_up_sync(~0u, w, off);
                if (lane >= off) w += t;
            }
            warp_sums[lane] = w;
        }
        __syncthreads();
        int carry = s_carry;
        int excl = carry + (wid ? warp_sums[wid - 1] : 0) + (val - tsum);
        int idx = base + tid * 4;
        rowptr[idx + 0] = excl;
        rowptr[idx + 1] = excl + v.x;
        rowptr[idx + 2] = excl + v.x + v.y;
        rowptr[idx + 3] = excl + v.x + v.y + v.z;
        __syncthreads();
        if (tid == 0) s_carry = carry + warp_sums[31];
        __syncthreads();
    }
    if (threadIdx.x == 0) rowptr[N_ATOMS_PAD] = s_carry;
}

__global__ void copy_cursor(const int* __restrict__ rowptr, int* __restrict__ cursor) {
    int i = blockIdx.x * blockDim.x + threadIdx.x;
    if (i < N_ATOMS) cursor[i] = rowptr[i];
}

__global__ void fill_csr(const int* __restrict__ src, const int* __restrict__ dst,
                         int* __restrict__ cursor,
                         int* __restrict__ esrc, int* __restrict__ eid) {
    int e = blockIdx.x * blockDim.x + threadIdx.x;
    if (e >= N_EDGES) return;
    int d = dst[e];
    int pos = atomicAdd(&cursor[d], 1);
    esrc[pos] = src[e];
    eid[pos]  = e;
}

// permute edge_attr into CSR order (padded to 16 floats/row)
__global__ void permute_ea(const float* __restrict__ ea, const int* __restrict__ eid,
                           float* __restrict__ eacsr) {
    int idx = blockIdx.x * blockDim.x + threadIdx.x;
    if (idx >= N_EDGES * 16) return;
    int p = idx >> 4, c = idx & 15;
    float v = 0.f;
    if (c < BOND_FDIM) v = ea[(size_t)eid[p] * BOND_FDIM + c];
    eacsr[idx] = v;
}

__global__ void build_molptr(const int* __restrict__ batch, int* __restrict__ molptr) {
    int i = blockIdx.x * blockDim.x + threadIdx.x;
    if (i >= N_ATOMS) return;
    int b = batch[i];
    int bp = (i == 0) ? -1 : batch[i - 1];
    for (int m = bp + 1; m <= b; m++) molptr[m] = i;
    if (i == N_ATOMS - 1)
        for (int m = b + 1; m <= N_MOLS; m++) molptr[m] = N_ATOMS;
}

// ------------------------- tf32 tensor-core GEMM -------------------------
// C[M x 320] = round_tf32(relu?(A @ W + bias)).
// A = virtual concat of A1 (K1 cols) and A2 (K2 cols); inputs pre-rounded.
// W in packed-pair layout Wp (float2 rows of NPAD).
// Block tile 64x160, BK=16, cp.async double-buffered.
// 128 threads: 4 warps in 1(m) x 4(n); warp tile 64x40 (4 m16-tiles x 5 n8-tiles).
// Small CTA keeps the proven 64x40 warp tile while fitting ~3 CTAs/SM for latency hiding.
__global__ __launch_bounds__(128)
void gemm_tf32(const float* __restrict__ A1, int lda1, int K1,
               const float* __restrict__ A2, int lda2, int K2,
               const float2* __restrict__ Wp, const float* __restrict__ bias,
               float* __restrict__ C, int M, int doRelu) {
    __shared__ float  As[2][BM][AS_STRIDE];        // m-major
    __shared__ float2 Bs[2][8][BS_STRIDE2];        // packed k-pairs, rows = ks*4+fc

    const int tid  = threadIdx.x;
    const int lane = tid & 31;
    const int wid  = tid >> 5;            // 0..3
    const int wn0  = wid * 40;            // 0,40,80,120
    const int row0 = blockIdx.x * BM;
    const int n0   = blockIdx.y * BN;
    const int fr = lane >> 2;
    const int fc = lane & 3;
    const int Ktot = K1 + K2;
    const int niter = Ktot / BK;

    float acc[4][5][4];
    #pragma unroll
    for (int mt = 0; mt < 4; mt++)
        #pragma unroll
        for (int nt = 0; nt < 5; nt++)
            #pragma unroll
            for (int i = 0; i < 4; i++) acc[mt][nt][i] = 0.f;

    // ---- async staging of tile k0 into buffer buf ----
    auto stage = [&](int k0, int buf) {
        const float* Asrc; int lda, kb;
        if (k0 < K1) { Asrc = A1; lda = lda1; kb = k0; }
        else         { Asrc = A2; lda = lda2; kb = k0 - K1; }
        // A tile: 64 rows x 16 k = 256 16B-chunks, 2 per thread
        #pragma unroll
        for (int j = 0; j < 2; j++) {
            int chunk = tid + j * 128;
            int m = chunk >> 2, kq = (chunk & 3) << 2;
            int g = row0 + m;
            const float* src = Asrc + (size_t)g * lda + kb + kq;
            uint32_t dst = smem_u32(&As[buf][m][kq]);
            int ss = (g < M) ? 16 : 0;
            asm volatile("cp.async.cg.shared.global [%0], [%1], 16, %2;"
                         :: "r"(dst), "l"(src), "r"(ss));
        }
        // B tile (packed): 8 rows x 160 float2 = 640 16B-chunks, 5 per thread
        #pragma unroll
        for (int j = 0; j < 5; j++) {
            int chunk = tid + j * 128;
            int rp = chunk / 80, col2 = (chunk - rp * 80) << 1;
            const float2* src = Wp + (size_t)((k0 >> 3) * 4 + rp) * NPAD + n0 + col2;
            uint32_t dst = smem_u32(&Bs[buf][rp][col2]);
            asm volatile("cp.async.cg.shared.global [%0], [%1], 16;"
                         :: "r"(dst), "l"(src));
        }
        asm volatile("cp.async.commit_group;");
    };

    stage(0, 0);

    for (int it = 0; it < niter; it++) {
        int buf = it & 1;
        bool more = (it + 1 < niter);
        if (more) stage((it + 1) * BK, buf ^ 1);
        if (more) asm volatile("cp.async.wait_group 1;");
        else      asm volatile("cp.async.wait_group 0;");
        __syncthreads();

        #pragma unroll
        for (int ks = 0; ks < 2; ks++) {
            const int kk = ks * 8;
            uint32_t a[4][4], b[5][2];
            #pragma unroll
            for (int mt = 0; mt < 4; mt++) {
                int mr = mt * 16 + fr;
                a[mt][0] = __float_as_uint(As[buf][mr][kk + fc]);
                a[mt][1] = __float_as_uint(As[buf][mr + 8][kk + fc]);
                a[mt][2] = __float_as_uint(As[buf][mr][kk + fc + 4]);
                a[mt][3] = __float_as_uint(As[buf][mr + 8][kk + fc + 4]);
            }
            #pragma unroll
            for (int nt = 0; nt < 5; nt++) {
                int nc = wn0 + nt * 8 + fr;
                float2 bv = Bs[buf][ks * 4 + fc][nc];
                b[nt][0] = __float_as_uint(bv.x);
                b[nt][1] = __float_as_uint(bv.y);
            }
            #pragma unroll
            for (int mt = 0; mt < 4; mt++)
                #pragma unroll
                for (int nt = 0; nt < 5; nt++)
                    asm volatile(
                        "mma.sync.aligned.m16n8k8.row.col.f32.tf32.tf32.f32 "
                        "{%0,%1,%2,%3}, {%4,%5,%6,%7}, {%8,%9}, {%0,%1,%2,%3};"
                        : "+f"(acc[mt][nt][0]), "+f"(acc[mt][nt][1]),
                          "+f"(acc[mt][nt][2]), "+f"(acc[mt][nt][3])
                        : "r"(a[mt][0]), "r"(a[mt][1]), "r"(a[mt][2]), "r"(a[mt][3]),
                          "r"(b[nt][0]), "r"(b[nt][1]));
        }
        __syncthreads();
    }

    // epilogue: bias + relu? + tf32 round
    #pragma unroll
    for (int mt = 0; mt < 4; mt++) {
        int r = row0 + mt * 16 + fr;
        #pragma unroll
        for (int nt = 0; nt < 5; nt++) {
            int cbase = n0 + wn0 + nt * 8 + (fc << 1);
            float2 bv = *(const float2*)&bias[cbase];
            if (r < M) {
                float2 v = make_float2(acc[mt][nt][0] + bv.x, acc[mt][nt][1] + bv.y);
                if (doRelu) { v.x = fmaxf(v.x, 0.f); v.y = fmaxf(v.y, 0.f); }
                v.x = tf32r(v.x); v.y = tf32r(v.y);
                *(float2*)(C + (size_t)r * NPAD + cbase) = v;
            }
            if (r + 8 < M) {
                float2 v = make_float2(acc[mt][nt][2] + bv.x, acc[mt][nt][3] + bv.y);
                if (doRelu) { v.x = fmaxf(v.x, 0.f); v.y = fmaxf(v.y, 0.f); }
                v.x = tf32r(v.x); v.y = tf32r(v.y);
                *(float2*)(C + (size_t)(r + 8) * NPAD + cbase) = v;
            }
        }
    }
}

// ------------------------- CSR gather: agg[v] = sum_in relu(P[src] + eacsr[p] @ WiBot) -----
__global__ __launch_bounds__(256)
void gather_agg(const float* __restrict__ P, const float* __restrict__ eacsr,
                const float* __restrict__ WiBot,
                const int* __restrict__ rowptr, const int* __restrict__ esrc,
                float* __restrict__ agg) {
    __shared__ float Ws[14 * NPAD];
    for (int i = threadIdx.x; i < 14 * NPAD; i += 256) Ws[i] = WiBot[i];
    __syncthreads();

    int v = (blockIdx.x * 256 + threadIdx.x) >> 5;
    int lane = threadIdx.x & 31;
    if (v >= N_ATOMS) return;
    int beg = rowptr[v], end = rowptr[v + 1];

    float acc[10];
    #pragma unroll
    for (int j = 0; j < 10; j++) acc[j] = 0.f;

    for (int p = beg; p < end; p++) {
        int s = esrc[p];
        float eav = (lane < 16) ? eacsr[(size_t)p * 16 + lane] : 0.f;
        float ef[14];
        #pragma unroll
        for (int f = 0; f < 14; f++) ef[f] = __shfl_sync(~0u, eav, f);
        const float* Pr = P + (size_t)s * NPAD;
        #pragma unroll
        for (int j = 0; j < 10; j++) {
            float m = Pr[lane + 32 * j];
            #pragma unroll
            for (int f = 0; f < 14; f++)
                m = fmaf(ef[f], Ws[f * NPAD + lane + 32 * j], m);
            acc[j] += fmaxf(m, 0.f);
        }
    }
    float* ag = agg + (size_t)v * NPAD;
    #pragma unroll
    for (int j = 0; j < 10; j++) ag[lane + 32 * j] = tf32r(acc[j]);
}

// ------------------------- molecule pooling (contiguous ranges) -------
__global__ void mol_sum(const float* __restrict__ hv, const int* __restrict__ molptr,
                        float* __restrict__ mol) {
    int m = (blockIdx.x * blockDim.x + threadIdx.x) >> 5;
    int lane = threadIdx.x & 31;
    if (m >= N_MOLS) return;
    int beg = molptr[m], end = molptr[m + 1];
    float acc[10];
    #pragma unroll
    for (int j = 0; j < 10; j++) acc[j] = 0.f;
    for (int a = beg; a < end; a++) {
        const float* hr = hv + (size_t)a * NPAD;
        #pragma unroll
        for (int j = 0; j < 10; j++) acc[j] += hr[lane + 32 * j];
    }
    float* mr = mol + (size_t)m * NPAD;
    #pragma unroll
    for (int j = 0; j < 10; j++) mr[lane + 32 * j] = tf32r(acc[j]);
}

// ------------------------- final: out = ffn @ ffn2 + b2 -------------------------
__global__ void finalk(const float* __restrict__ F, const float* __restrict__ W2,
                       const float* __restrict__ b2, float* __restrict__ out) {
    int w = (blockIdx.x * blockDim.x + threadIdx.x) >> 5;
    int lane = threadIdx.x & 31;
    if (w >= N_MOLS) return;
    float acc = (lane < 12) ? b2[lane] : 0.f;
    const float* f = F + (size_t)w * NPAD;
    for (int j = 0; j < HIDDEN; j++) {
        float fv = __ldg(f + j);
        if (lane < 12) acc = fmaf(fv, W2[j * 12 + lane], acc);
    }
    if (lane < 12) out[w * 12 + lane] = acc;
}

// ------------------------- host launch -------------------------
static inline dim3 rep_grid(int n) { return dim3((n + 255) / 256); }

extern "C" void kernel_launch(void* const* d_in, const int* in_sizes, int n_in,
                              void* d_out, int out_size) {
    const float* x      = (const float*)d_in[0];
    const int*   ei     = (const int*)  d_in[1];   // [2, N_EDGES]
    const float* ea     = (const float*)d_in[2];
    const int*   batch  = (const int*)  d_in[3];
    const float* atom_W = (const float*)d_in[4];
    const float* atom_b = (const float*)d_in[5];
    // d_in[6], d_in[7]: bond_W / bond_b  -> dead code
    const float* Wi     = (const float*)d_in[8];
    // d_in[9]: Wh -> dead code
    const float* Wo     = (const float*)d_in[10];
    const float* Wo_b   = (const float*)d_in[11];
    const float* ffn1_W = (const float*)d_in[12];
    const float* ffn1_b = (const float*)d_in[13];
    const float* ffn2_W = (const float*)d_in[14];
    const float* ffn2_b = (const float*)d_in[15];
    float* out = (float*)d_out;

    float *p_xpad, *p_hv, *p_hv2, *p_P, *p_agg, *p_mol, *p_ffn;
    float *p_atomWp, *p_WiTopp, *p_Wop, *p_ffn1p, *p_WiBot;
    float *p_atomB, *p_WoB, *p_ffn1B, *p_zeros, *p_eacsr;
    int *p_counts, *p_rowptr, *p_cursor, *p_esrc, *p_eid, *p_molptr;
    cudaGetSymbolAddress((void**)&p_xpad,  g_xpad);
    cudaGetSymbolAddress((void**)&p_hv,    g_hv);
    cudaGetSymbolAddress((void**)&p_hv2,   g_hv2);
    cudaGetSymbolAddress((void**)&p_P,     g_P);
    cudaGetSymbolAddress((void**)&p_agg,   g_agg);
    cudaGetSymbolAddress((void**)&p_mol,   g_mol);
    cudaGetSymbolAddress((void**)&p_ffn,   g_ffn);
    cudaGetSymbolAddress((void**)&p_atomWp, g_atomWp);
    cudaGetSymbolAddress((void**)&p_WiTopp, g_WiTopp);
    cudaGetSymbolAddress((void**)&p_Wop,    g_Wop);
    cudaGetSymbolAddress((void**)&p_ffn1p,  g_ffn1p);
    cudaGetSymbolAddress((void**)&p_WiBot,  g_WiBot);
    cudaGetSymbolAddress((void**)&p_atomB, g_atomB);
    cudaGetSymbolAddress((void**)&p_WoB,   g_WoB);
    cudaGetSymbolAddress((void**)&p_ffn1B, g_ffn1B);
    cudaGetSymbolAddress((void**)&p_zeros, g_zeros);
    cudaGetSymbolAddress((void**)&p_eacsr, g_eacsr);
    cudaGetSymbolAddress((void**)&p_counts, g_counts);
    cudaGetSymbolAddress((void**)&p_rowptr, g_rowptr);
    cudaGetSymbolAddress((void**)&p_cursor, g_cursor);
    cudaGetSymbolAddress((void**)&p_esrc,   g_esrc);
    cudaGetSymbolAddress((void**)&p_eid,    g_eid);
    cudaGetSymbolAddress((void**)&p_molptr, g_molptr);

    const int* e_src = ei;
    const int* e_dst = ei + N_EDGES;

    // ---- repack inputs / weights (x pre-rounded; weights packed-pair + pre-rounded) ----
    repack<<<rep_grid(N_ATOMS * KX), 256>>>(p_xpad, x, N_ATOMS, KX, N_ATOMS, ATOM_FDIM, 0, 1);
    repackP<<<rep_grid(KX / 2 * NPAD), 256>>>((float2*)p_atomWp, atom_W, KX, ATOM_FDIM, HIDDEN, 0);
    repackP<<<rep_grid(KH / 2 * NPAD), 256>>>((float2*)p_WiTopp, Wi, KH, HIDDEN, HIDDEN, 0);
    repackP<<<rep_grid(KH / 2 * NPAD), 256>>>((float2*)p_Wop, Wo, KH, HIDDEN, HIDDEN, 0);
    repackP<<<rep_grid(KH / 2 * NPAD), 256>>>((float2*)p_Wop + (KH / 8) * 4 * NPAD, Wo,
                                              KH, HIDDEN, HIDDEN, HIDDEN);
    repackP<<<rep_grid(KH / 2 * NPAD), 256>>>((float2*)p_ffn1p, ffn1_W, KH, HIDDEN, HIDDEN, 0);
    repack<<<rep_grid(KE * NPAD), 256>>>(p_WiBot, Wi, KE, NPAD, BOND_FDIM, HIDDEN, HIDDEN, 1);
    repack<<<rep_grid(NPAD), 256>>>(p_atomB, atom_b, 1, NPAD, 1, HIDDEN, 0, 0);
    repack<<<rep_grid(NPAD), 256>>>(p_WoB, Wo_b, 1, NPAD, 1, HIDDEN, 0, 0);
    repack<<<rep_grid(NPAD), 256>>>(p_ffn1B, ffn1_b, 1, NPAD, 1, HIDDEN, 0, 0);

    // ---- CSR build (by dst) + ea permute + mol boundaries ----
    zeroI<<<rep_grid(N_ATOMS_PAD), 256>>>(p_counts, N_ATOMS_PAD);
    hist_dst<<<rep_grid(N_EDGES), 256>>>(e_dst, p_counts);
    scan_counts<<<1, 1024>>>(p_counts, p_rowptr);
    copy_cursor<<<rep_grid(N_ATOMS), 256>>>(p_rowptr, p_cursor);
    fill_csr<<<rep_grid(N_EDGES), 256>>>(e_src, e_dst, p_cursor, p_esrc, p_eid);
    permute_ea<<<rep_grid(N_EDGES * 16), 256>>>(ea, p_eid, p_eacsr);
    build_molptr<<<rep_grid(N_ATOMS), 256>>>(batch, p_molptr);

    dim3 gAtom((N_ATOMS + BM - 1) / BM, NPAD / BN);
    dim3 gMol ((N_MOLS  + BM - 1) / BM, NPAD / BN);

    // h_v = relu(x @ atom_W + atom_b)
    gemm_tf32<<<gAtom, 128>>>(p_xpad, KX, KX, nullptr, 0, 0,
                              (const float2*)p_atomWp, p_atomB, p_hv, N_ATOMS, 1);

    int gather_blocks = (N_ATOMS * 32 + 255) / 256;

    float* cur = p_hv;
    float* nxt = p_hv2;
    for (int d = 0; d < 3; d++) {
        // P = h_v @ Wi_top
        gemm_tf32<<<gAtom, 128>>>(cur, NPAD, KH, nullptr, 0, 0,
                                  (const float2*)p_WiTopp, p_zeros, p_P, N_ATOMS, 0);
        // agg[v] = sum over in-edges of relu(P[src] + edge_attr @ WiBot)
        gather_agg<<<gather_blocks, 256>>>(p_P, p_eacsr, p_WiBot, p_rowptr, p_esrc, p_agg);
        // h_v = relu([h_v, agg] @ Wo + Wo_b)
        gemm_tf32<<<gAtom, 128>>>(cur, NPAD, KH, p_agg, NPAD, KH,
                                  (const float2*)p_Wop, p_WoB, nxt, N_ATOMS, 1);
        float* t = cur; cur = nxt; nxt = t;
    }

    // mol_repr = segment_sum(h_v, batch)
    mol_sum<<<(N_MOLS * 32 + 255) / 256, 256>>>(cur, p_molptr, p_mol);
    // ffn = relu(mol @ ffn1 + b1)
    gemm_tf32<<<gMol, 128>>>(p_mol, NPAD, KH, nullptr, 0, 0,
                             (const float2*)p_ffn1p, p_ffn1B, p_ffn, N_MOLS, 1);
    // out = ffn @ ffn2 + b2
    finalk<<<(N_MOLS * 32 + 255) / 256, 256>>>(p_ffn, ffn2_W, ffn2_b, out);
}

// round 11
// speedup vs baseline: 1.2735x; 1.0281x over previous
#include <cuda_runtime.h>
#include <cstdint>

#define N_ATOMS 100000
#define N_ATOMS_PAD 102400   // multiple of 4096 for the scan
#define N_EDGES 400000
#define N_MOLS  4096
#define ATOM_FDIM 133
#define BOND_FDIM 14
#define HIDDEN 300
#define N_LABELS 12
#define NPAD 320        // padded hidden width
#define KX 144          // padded atom feature dim (multiple of 16)
#define KE 16           // padded bond feature dim
#define KH 304          // padded hidden as K-dim (multiple of 16)

#define BM 64
#define BN 160
#define BK 16
#define AS_STRIDE 20    // floats; banks (20*fr+fc)%32 all-distinct
#define BS_STRIDE2 164  // float2; (fc*164+fr) mod 16 == fc*4+fr -> both LDS.64 phases conflict-free

// ------------------------- scratch (static, no allocs) -------------------------
__device__ float g_xpad[(size_t)N_ATOMS * KX];
__device__ float g_hv  [(size_t)N_ATOMS * NPAD];
__device__ float g_hv2 [(size_t)N_ATOMS * NPAD];
__device__ float g_P   [(size_t)N_ATOMS * NPAD];
__device__ float g_agg [(size_t)N_ATOMS * NPAD];
__device__ float g_mol [(size_t)N_MOLS * NPAD];
__device__ float g_ffn [(size_t)N_MOLS * NPAD];

// packed-pair weights: row r=(k/8)*4+fc holds float2(W[k0+fc][n], W[k0+fc+4][n])
__device__ float g_atomWp[KX * NPAD];
__device__ float g_WiTopp[KH * NPAD];
__device__ float g_Wop   [2 * KH * NPAD];
__device__ float g_ffn1p [KH * NPAD];
__device__ float g_WiBot [KE * NPAD];     // row-major [14+pad][320] for gather
__device__ float g_atomB[NPAD];
__device__ float g_WoB  [NPAD];
__device__ float g_ffn1B[NPAD];
__device__ float g_zeros[NPAD];   // stays zero (static zero-init)

// CSR scratch
__device__ int g_counts[N_ATOMS_PAD];
__device__ int g_rowptr[N_ATOMS_PAD + 1];
__device__ int g_cursor[N_ATOMS];
__device__ int g_esrc[N_EDGES];
__device__ int g_eid [N_EDGES];
__device__ int g_molptr[N_MOLS + 1];
__device__ float g_eacsr[(size_t)N_EDGES * 16];   // edge_attr permuted to CSR order, padded to 16

// ------------------------- helpers -------------------------
__device__ __forceinline__ float tf32r(float x) {
    asm("cvt.rna.tf32.f32 %0, %0;" : "+f"(x));
    return x;
}
__device__ __forceinline__ uint32_t smem_u32(const void* p) {
    return (uint32_t)__cvta_generic_to_shared(p);
}

// ------------------------- repack: zero-padded copy (+optional tf32 round) ------------
__global__ void repack(float* __restrict__ dst, const float* __restrict__ src,
                       int dstR, int dstC, int srcR, int srcC, int srcRow0, int doRound) {
    int idx = blockIdx.x * blockDim.x + threadIdx.x;
    if (idx >= dstR * dstC) return;
    int r = idx / dstC, c = idx - r * dstC;
    float v = 0.f;
    if (r < srcR && c < srcC) v = src[(size_t)(r + srcRow0) * srcC + c];
    dst[idx] = doRound ? tf32r(v) : v;
}

// packed-pair weight repack: dst row (k/8)*4+fc, element n = (W[k][n], W[k+4][n]) tf32-rounded
__global__ void repackP(float2* __restrict__ dst, const float* __restrict__ src,
                        int Ktot, int kValid, int srcC, int srcRow0) {
    int idx = blockIdx.x * blockDim.x + threadIdx.x;
    int total = (Ktot >> 3) * 4 * NPAD;
    if (idx >= total) return;
    int row = idx / NPAD, n = idx - row * NPAD;
    int kb = row >> 2, fc = row & 3;
    int klo = kb * 8 + fc, khi = klo + 4;
    float vlo = 0.f, vhi = 0.f;
    if (klo < kValid && n < srcC) vlo = tf32r(src[(size_t)(klo + srcRow0) * srcC + n]);
    if (khi < kValid && n < srcC) vhi = tf32r(src[(size_t)(khi + srcRow0) * srcC + n]);
    dst[idx] = make_float2(vlo, vhi);
}

__global__ void zeroI(int* __restrict__ p, int n) {
    int i = blockIdx.x * blockDim.x + threadIdx.x;
    if (i < n) p[i] = 0;
}

// ------------------------- CSR build -------------------------
__global__ void hist_dst(const int* __restrict__ dst, int* __restrict__ counts) {
    int e = blockIdx.x * blockDim.x + threadIdx.x;
    if (e < N_EDGES) atomicAdd(&counts[dst[e]], 1);
}

__global__ __launch_bounds__(1024)
void scan_counts(const int* __restrict__ counts, int* __restrict__ rowptr) {
    __shared__ int warp_sums[32];
    __shared__ int s_carry;
    const int tid = threadIdx.x;
    const int lane = tid & 31, wid = tid >> 5;
    if (tid == 0) s_carry = 0;
    __syncthreads();
    for (int base = 0; base < N_ATOMS_PAD; base += 4096) {
        int4 v = *(const int4*)(counts + base + tid * 4);
        int tsum = v.x + v.y + v.z + v.w;
        int val = tsum;
        #pragma unroll
        for (int off = 1; off < 32; off <<= 1) {
            int t = __shfl_up_sync(~0u, val, off);
            if (lane >= off) val += t;
        }
        if (lane == 31) warp_sums[wid] = val;
        __syncthreads();
        if (wid == 0) {
            int w = warp_sums[lane];
            #pragma unroll
            for (int off = 1; off < 32; off <<= 1) {
                int t = __shfl_up_sync(~0u, w, off);
                if (lane >= off) w += t;
            }
            warp_sums[lane] = w;
        }
        __syncthreads();
        int carry = s_carry;
        int excl = carry + (wid ? warp_sums[wid - 1] : 0) + (val - tsum);
        int idx = base + tid * 4;
        rowptr[idx + 0] = excl;
        rowptr[idx + 1] = excl + v.x;
        rowptr[idx + 2] = excl + v.x + v.y;
        rowptr[idx + 3] = excl + v.x + v.y + v.z;
        __syncthreads();
        if (tid == 0) s_carry = carry + warp_sums[31];
        __syncthreads();
    }
    if (threadIdx.x == 0) rowptr[N_ATOMS_PAD] = s_carry;
}

__global__ void copy_cursor(const int* __restrict__ rowptr, int* __restrict__ cursor) {
    int i = blockIdx.x * blockDim.x + threadIdx.x;
    if (i < N_ATOMS) cursor[i] = rowptr[i];
}

__global__ void fill_csr(const int* __restrict__ src, const int* __restrict__ dst,
                         int* __restrict__ cursor,
                         int* __restrict__ esrc, int* __restrict__ eid) {
    int e = blockIdx.x * blockDim.x + threadIdx.x;
    if (e >= N_EDGES) return;
    int d = dst[e];
    int pos = atomicAdd(&cursor[d], 1);
    esrc[pos] = src[e];
    eid[pos]  = e;
}

// permute edge_attr into CSR order (padded to 16 floats/row)
__global__ void permute_ea(const float* __restrict__ ea, const int* __restrict__ eid,
                           float* __restrict__ eacsr) {
    int idx = blockIdx.x * blockDim.x + threadIdx.x;
    if (idx >= N_EDGES * 16) return;
    int p = idx >> 4, c = idx & 15;
    float v = 0.f;
    if (c < BOND_FDIM) v = ea[(size_t)eid[p] * BOND_FDIM + c];
    eacsr[idx] = v;
}

__global__ void build_molptr(const int* __restrict__ batch, int* __restrict__ molptr) {
    int i = blockIdx.x * blockDim.x + threadIdx.x;
    if (i >= N_ATOMS) return;
    int b = batch[i];
    int bp = (i == 0) ? -1 : batch[i - 1];
    for (int m = bp + 1; m <= b; m++) molptr[m] = i;
    if (i == N_ATOMS - 1)
        for (int m = b + 1; m <= N_MOLS; m++) molptr[m] = N_ATOMS;
}

// ------------------------- tf32 tensor-core GEMM -------------------------
// C[M x 320] = round_tf32(relu?(A @ W + bias)).
// A = virtual concat of A1 (K1 cols) and A2 (K2 cols); inputs pre-rounded.
// W in packed-pair layout Wp (float2 rows of NPAD).
// Block tile 64x160, BK=16, cp.async TRIPLE-buffered, ONE sync per k-iter.
// 128 threads: 4 warps in 1(m) x 4(n); warp tile 64x40 (4 m16-tiles x 5 n8-tiles).
__global__ __launch_bounds__(128)
void gemm_tf32(const float* __restrict__ A1, int lda1, int K1,
               const float* __restrict__ A2, int lda2, int K2,
               const float2* __restrict__ Wp, const float* __restrict__ bias,
               float* __restrict__ C, int M, int doRelu) {
    __shared__ float  As[3][BM][AS_STRIDE];        // m-major
    __shared__ float2 Bs[3][8][BS_STRIDE2];        // packed k-pairs, rows = ks*4+fc

    const int tid  = threadIdx.x;
    const int lane = tid & 31;
    const int wid  = tid >> 5;            // 0..3
    const int wn0  = wid * 40;            // 0,40,80,120
    const int row0 = blockIdx.x * BM;
    const int n0   = blockIdx.y * BN;
    const int fr = lane >> 2;
    const int fc = lane & 3;
    const int Ktot = K1 + K2;
    const int niter = Ktot / BK;

    float acc[4][5][4];
    #pragma unroll
    for (int mt = 0; mt < 4; mt++)
        #pragma unroll
        for (int nt = 0; nt < 5; nt++)
            #pragma unroll
            for (int i = 0; i < 4; i++) acc[mt][nt][i] = 0.f;

    // ---- async staging of tile k0 into buffer buf ----
    auto stage = [&](int k0, int buf) {
        const float* Asrc; int lda, kb;
        if (k0 < K1) { Asrc = A1; lda = lda1; kb = k0; }
        else         { Asrc = A2; lda = lda2; kb = k0 - K1; }
        // A tile: 64 rows x 16 k = 256 16B-chunks, 2 per thread
        #pragma unroll
        for (int j = 0; j < 2; j++) {
            int chunk = tid + j * 128;
            int m = chunk >> 2, kq = (chunk & 3) << 2;
            int g = row0 + m;
            const float* src = Asrc + (size_t)g * lda + kb + kq;
            uint32_t dst = smem_u32(&As[buf][m][kq]);
            int ss = (g < M) ? 16 : 0;
            asm volatile("cp.async.cg.shared.global [%0], [%1], 16, %2;"
                         :: "r"(dst), "l"(src), "r"(ss));
        }
        // B tile (packed): 8 rows x 160 float2 = 640 16B-chunks, 5 per thread
        #pragma unroll
        for (int j = 0; j < 5; j++) {
            int chunk = tid + j * 128;
            int rp = chunk / 80, col2 = (chunk - rp * 80) << 1;
            const float2* src = Wp + (size_t)((k0 >> 3) * 4 + rp) * NPAD + n0 + col2;
            uint32_t dst = smem_u32(&Bs[buf][rp][col2]);
            asm volatile("cp.async.cg.shared.global [%0], [%1], 16;"
                         :: "r"(dst), "l"(src));
        }
        asm volatile("cp.async.commit_group;");
    };

    stage(0, 0);
    if (niter > 1) stage(BK, 1);

    for (int it = 0; it < niter; it++) {
        int buf = it % 3;
        // wait until tile `it` is resident (tile it+1's group may still be pending)
        if (it + 1 < niter) asm volatile("cp.async.wait_group 1;");
        else                asm volatile("cp.async.wait_group 0;");
        __syncthreads();   // all warps done with compute(it-1); buffer (it+2)%3 free
        if (it + 2 < niter) stage((it + 2) * BK, (it + 2) % 3);

        #pragma unroll
        for (int ks = 0; ks < 2; ks++) {
            const int kk = ks * 8;
            uint32_t a[4][4], b[5][2];
            #pragma unroll
            for (int mt = 0; mt < 4; mt++) {
                int mr = mt * 16 + fr;
                a[mt][0] = __float_as_uint(As[buf][mr][kk + fc]);
                a[mt][1] = __float_as_uint(As[buf][mr + 8][kk + fc]);
                a[mt][2] = __float_as_uint(As[buf][mr][kk + fc + 4]);
                a[mt][3] = __float_as_uint(As[buf][mr + 8][kk + fc + 4]);
            }
            #pragma unroll
            for (int nt = 0; nt < 5; nt++) {
                int nc = wn0 + nt * 8 + fr;
                float2 bv = Bs[buf][ks * 4 + fc][nc];
                b[nt][0] = __float_as_uint(bv.x);
                b[nt][1] = __float_as_uint(bv.y);
            }
            #pragma unroll
            for (int mt = 0; mt < 4; mt++)
                #pragma unroll
                for (int nt = 0; nt < 5; nt++)
                    asm volatile(
                        "mma.sync.aligned.m16n8k8.row.col.f32.tf32.tf32.f32 "
                        "{%0,%1,%2,%3}, {%4,%5,%6,%7}, {%8,%9}, {%0,%1,%2,%3};"
                        : "+f"(acc[mt][nt][0]), "+f"(acc[mt][nt][1]),
                          "+f"(acc[mt][nt][2]), "+f"(acc[mt][nt][3])
                        : "r"(a[mt][0]), "r"(a[mt][1]), "r"(a[mt][2]), "r"(a[mt][3]),
                          "r"(b[nt][0]), "r"(b[nt][1]));
        }
    }

    // epilogue: bias + relu? + tf32 round
    #pragma unroll
    for (int mt = 0; mt < 4; mt++) {
        int r = row0 + mt * 16 + fr;
        #pragma unroll
        for (int nt = 0; nt < 5; nt++) {
            int cbase = n0 + wn0 + nt * 8 + (fc << 1);
            float2 bv = *(const float2*)&bias[cbase];
            if (r < M) {
                float2 v = make_float2(acc[mt][nt][0] + bv.x, acc[mt][nt][1] + bv.y);
                if (doRelu) { v.x = fmaxf(v.x, 0.f); v.y = fmaxf(v.y, 0.f); }
                v.x = tf32r(v.x); v.y = tf32r(v.y);
                *(float2*)(C + (size_t)r * NPAD + cbase) = v;
            }
            if (r + 8 < M) {
                float2 v = make_float2(acc[mt][nt][2] + bv.x, acc[mt][nt][3] + bv.y);
                if (doRelu) { v.x = fmaxf(v.x, 0.f); v.y = fmaxf(v.y, 0.f); }
                v.x = tf32r(v.x); v.y = tf32r(v.y);
                *(float2*)(C + (size_t)(r + 8) * NPAD + cbase) = v;
            }
        }
    }
}

// ------------------------- CSR gather: agg[v] = sum_in relu(P[src] + eacsr[p] @ WiBot) -----
__global__ __launch_bounds__(256)
void gather_agg(const float* __restrict__ P, const float* __restrict__ eacsr,
                const float* __restrict__ WiBot,
                const int* __restrict__ rowptr, const int* __restrict__ esrc,
                float* __restrict__ agg) {
    __shared__ float Ws[14 * NPAD];
    for (int i = threadIdx.x; i < 14 * NPAD; i += 256) Ws[i] = WiBot[i];
    __syncthreads();

    int v = (blockIdx.x * 256 + threadIdx.x) >> 5;
    int lane = threadIdx.x & 31;
    if (v >= N_ATOMS) return;
    int beg = rowptr[v], end = rowptr[v + 1];

    float acc[10];
    #pragma unroll
    for (int j = 0; j < 10; j++) acc[j] = 0.f;

    for (int p = beg; p < end; p++) {
        int s = esrc[p];
        float eav = (lane < 16) ? eacsr[(size_t)p * 16 + lane] : 0.f;
        float ef[14];
        #pragma unroll
        for (int f = 0; f < 14; f++) ef[f] = __shfl_sync(~0u, eav, f);
        const float* Pr = P + (size_t)s * NPAD;
        #pragma unroll
        for (int j = 0; j < 10; j++) {
            float m = Pr[lane + 32 * j];
            #pragma unroll
            for (int f = 0; f < 14; f++)
                m = fmaf(ef[f], Ws[f * NPAD + lane + 32 * j], m);
            acc[j] += fmaxf(m, 0.f);
        }
    }
    float* ag = agg + (size_t)v * NPAD;
    #pragma unroll
    for (int j = 0; j < 10; j++) ag[lane + 32 * j] = tf32r(acc[j]);
}

// ------------------------- molecule pooling (contiguous ranges) -------
__global__ void mol_sum(const float* __restrict__ hv, const int* __restrict__ molptr,
                        float* __restrict__ mol) {
    int m = (blockIdx.x * blockDim.x + threadIdx.x) >> 5;
    int lane = threadIdx.x & 31;
    if (m >= N_MOLS) return;
    int beg = molptr[m], end = molptr[m + 1];
    float acc[10];
    #pragma unroll
    for (int j = 0; j < 10; j++) acc[j] = 0.f;
    for (int a = beg; a < end; a++) {
        const float* hr = hv + (size_t)a * NPAD;
        #pragma unroll
        for (int j = 0; j < 10; j++) acc[j] += hr[lane + 32 * j];
    }
    float* mr = mol + (size_t)m * NPAD;
    #pragma unroll
    for (int j = 0; j < 10; j++) mr[lane + 32 * j] = tf32r(acc[j]);
}

// ------------------------- final: out = ffn @ ffn2 + b2 -------------------------
__global__ void finalk(const float* __restrict__ F, const float* __restrict__ W2,
                       const float* __restrict__ b2, float* __restrict__ out) {
    int w = (blockIdx.x * blockDim.x + threadIdx.x) >> 5;
    int lane = threadIdx.x & 31;
    if (w >= N_MOLS) return;
    float acc = (lane < 12) ? b2[lane] : 0.f;
    const float* f = F + (size_t)w * NPAD;
    for (int j = 0; j < HIDDEN; j++) {
        float fv = __ldg(f + j);
        if (lane < 12) acc = fmaf(fv, W2[j * 12 + lane], acc);
    }
    if (lane < 12) out[w * 12 + lane] = acc;
}

// ------------------------- host launch -------------------------
static inline dim3 rep_grid(int n) { return dim3((n + 255) / 256); }

extern "C" void kernel_launch(void* const* d_in, const int* in_sizes, int n_in,
                              void* d_out, int out_size) {
    const float* x      = (const float*)d_in[0];
    const int*   ei     = (const int*)  d_in[1];   // [2, N_EDGES]
    const float* ea     = (const float*)d_in[2];
    const int*   batch  = (const int*)  d_in[3];
    const float* atom_W = (const float*)d_in[4];
    const float* atom_b = (const float*)d_in[5];
    // d_in[6], d_in[7]: bond_W / bond_b  -> dead code
    const float* Wi     = (const float*)d_in[8];
    // d_in[9]: Wh -> dead code
    const float* Wo     = (const float*)d_in[10];
    const float* Wo_b   = (const float*)d_in[11];
    const float* ffn1_W = (const float*)d_in[12];
    const float* ffn1_b = (const float*)d_in[13];
    const float* ffn2_W = (const float*)d_in[14];
    const float* ffn2_b = (const float*)d_in[15];
    float* out = (float*)d_out;

    float *p_xpad, *p_hv, *p_hv2, *p_P, *p_agg, *p_mol, *p_ffn;
    float *p_atomWp, *p_WiTopp, *p_Wop, *p_ffn1p, *p_WiBot;
    float *p_atomB, *p_WoB, *p_ffn1B, *p_zeros, *p_eacsr;
    int *p_counts, *p_rowptr, *p_cursor, *p_esrc, *p_eid, *p_molptr;
    cudaGetSymbolAddress((void**)&p_xpad,  g_xpad);
    cudaGetSymbolAddress((void**)&p_hv,    g_hv);
    cudaGetSymbolAddress((void**)&p_hv2,   g_hv2);
    cudaGetSymbolAddress((void**)&p_P,     g_P);
    cudaGetSymbolAddress((void**)&p_agg,   g_agg);
    cudaGetSymbolAddress((void**)&p_mol,   g_mol);
    cudaGetSymbolAddress((void**)&p_ffn,   g_ffn);
    cudaGetSymbolAddress((void**)&p_atomWp, g_atomWp);
    cudaGetSymbolAddress((void**)&p_WiTopp, g_WiTopp);
    cudaGetSymbolAddress((void**)&p_Wop,    g_Wop);
    cudaGetSymbolAddress((void**)&p_ffn1p,  g_ffn1p);
    cudaGetSymbolAddress((void**)&p_WiBot,  g_WiBot);
    cudaGetSymbolAddress((void**)&p_atomB, g_atomB);
    cudaGetSymbolAddress((void**)&p_WoB,   g_WoB);
    cudaGetSymbolAddress((void**)&p_ffn1B, g_ffn1B);
    cudaGetSymbolAddress((void**)&p_zeros, g_zeros);
    cudaGetSymbolAddress((void**)&p_eacsr, g_eacsr);
    cudaGetSymbolAddress((void**)&p_counts, g_counts);
    cudaGetSymbolAddress((void**)&p_rowptr, g_rowptr);
    cudaGetSymbolAddress((void**)&p_cursor, g_cursor);
    cudaGetSymbolAddress((void**)&p_esrc,   g_esrc);
    cudaGetSymbolAddress((void**)&p_eid,    g_eid);
    cudaGetSymbolAddress((void**)&p_molptr, g_molptr);

    const int* e_src = ei;
    const int* e_dst = ei + N_EDGES;

    dim3 gAtom((N_ATOMS + BM - 1) / BM, NPAD / BN);
    dim3 gMol ((N_MOLS  + BM - 1) / BM, NPAD / BN);
    int gather_blocks = (N_ATOMS * 32 + 255) / 256;

    // ---- diagnostic-ordered prologue: ncu (-s 5 -c 1) captures launch #6 = P-GEMM ----
    repack<<<rep_grid(N_ATOMS * KX), 256>>>(p_xpad, x, N_ATOMS, KX, N_ATOMS, ATOM_FDIM, 0, 1);      // 1
    repackP<<<rep_grid(KX / 2 * NPAD), 256>>>((float2*)p_atomWp, atom_W, KX, ATOM_FDIM, HIDDEN, 0); // 2
    repack<<<rep_grid(NPAD), 256>>>(p_atomB, atom_b, 1, NPAD, 1, HIDDEN, 0, 0);                     // 3
    repackP<<<rep_grid(KH / 2 * NPAD), 256>>>((float2*)p_WiTopp, Wi, KH, HIDDEN, HIDDEN, 0);        // 4
    // h_v = relu(x @ atom_W + atom_b)                                                              // 5
    gemm_tf32<<<gAtom, 128>>>(p_xpad, KX, KX, nullptr, 0, 0,
                              (const float2*)p_atomWp, p_atomB, p_hv, N_ATOMS, 1);
    // P = h_v @ Wi_top  (depth 0)  <-- ncu capture target                                          // 6
    gemm_tf32<<<gAtom, 128>>>(p_hv, NPAD, KH, nullptr, 0, 0,
                              (const float2*)p_WiTopp, p_zeros, p_P, N_ATOMS, 0);

    // ---- remaining repacks ----
    repackP<<<rep_grid(KH / 2 * NPAD), 256>>>((float2*)p_Wop, Wo, KH, HIDDEN, HIDDEN, 0);
    repackP<<<rep_grid(KH / 2 * NPAD), 256>>>((float2*)p_Wop + (KH / 8) * 4 * NPAD, Wo,
                                              KH, HIDDEN, HIDDEN, HIDDEN);
    repackP<<<rep_grid(KH / 2 * NPAD), 256>>>((float2*)p_ffn1p, ffn1_W, KH, HIDDEN, HIDDEN, 0);
    repack<<<rep_grid(KE * NPAD), 256>>>(p_WiBot, Wi, KE, NPAD, BOND_FDIM, HIDDEN, HIDDEN, 1);
    repack<<<rep_grid(NPAD), 256>>>(p_WoB, Wo_b, 1, NPAD, 1, HIDDEN, 0, 0);
    repack<<<rep_grid(NPAD), 256>>>(p_ffn1B, ffn1_b, 1, NPAD, 1, HIDDEN, 0, 0);

    // ---- CSR build (by dst) + ea permute + mol boundaries ----
    zeroI<<<rep_grid(N_ATOMS_PAD), 256>>>(p_counts, N_ATOMS_PAD);
    hist_dst<<<rep_grid(N_EDGES), 256>>>(e_dst, p_counts);
    scan_counts<<<1, 1024>>>(p_counts, p_rowptr);
    copy_cursor<<<rep_grid(N_ATOMS), 256>>>(p_rowptr, p_cursor);
    fill_csr<<<rep_grid(N_EDGES), 256>>>(e_src, e_dst, p_cursor, p_esrc, p_eid);
    permute_ea<<<rep_grid(N_EDGES * 16), 256>>>(ea, p_eid, p_eacsr);
    build_molptr<<<rep_grid(N_ATOMS), 256>>>(batch, p_molptr);

    // ---- depth 0 remainder ----
    gather_agg<<<gather_blocks, 256>>>(p_P, p_eacsr, p_WiBot, p_rowptr, p_esrc, p_agg);
    gemm_tf32<<<gAtom, 128>>>(p_hv, NPAD, KH, p_agg, NPAD, KH,
                              (const float2*)p_Wop, p_WoB, p_hv2, N_ATOMS, 1);

    // ---- depths 1..2 ----
    float* cur = p_hv2;
    float* nxt = p_hv;
    for (int d = 1; d < 3; d++) {
        gemm_tf32<<<gAtom, 128>>>(cur, NPAD, KH, nullptr, 0, 0,
                                  (const float2*)p_WiTopp, p_zeros, p_P, N_ATOMS, 0);
        gather_agg<<<gather_blocks, 256>>>(p_P, p_eacsr, p_WiBot, p_rowptr, p_esrc, p_agg);
        gemm_tf32<<<gAtom, 128>>>(cur, NPAD, KH, p_agg, NPAD, KH,
                                  (const float2*)p_Wop, p_WoB, nxt, N_ATOMS, 1);
        float* t = cur; cur = nxt; nxt = t;
    }

    // mol_repr = segment_sum(h_v, batch)
    mol_sum<<<(N_MOLS * 32 + 255) / 256, 256>>>(cur, p_molptr, p_mol);
    // ffn = relu(mol @ ffn1 + b1)
    gemm_tf32<<<gMol, 128>>>(p_mol, NPAD, KH, nullptr, 0, 0,
                             (const float2*)p_ffn1p, p_ffn1B, p_ffn, N_MOLS, 1);
    // out = ffn @ ffn2 + b2
    finalk<<<(N_MOLS * 32 + 255) / 256, 256>>>(p_ffn, ffn2_W, ffn2_b, out);
}

// round 12
// speedup vs baseline: 1.4479x; 1.1369x over previous
#include <cuda_runtime.h>
#include <cuda_fp16.h>
#include <cstdint>

#define N_ATOMS 100000
#define N_ATOMS_PAD 102400   // multiple of 4096 for the scan
#define N_EDGES 400000
#define N_MOLS  4096
#define ATOM_FDIM 133
#define BOND_FDIM 14
#define HIDDEN 300
#define N_LABELS 12
#define NPAD 320        // padded hidden width
#define KX 144          // padded atom feature dim (multiple of 16)
#define KE 16
#define KH 304          // padded hidden as K-dim (multiple of 16)
#define KWO 608         // concat K for Wo GEMM

#define BM 64
#define BN 160
#define BK 16
#define LDR 24          // SMEM row stride in halves (48B): 12r mod 32 distinct over 8 rows

// ------------------------- scratch (static, no allocs) -------------------------
__device__ __half g_xpad[(size_t)N_ATOMS * KX];
__device__ __half g_hv  [(size_t)N_ATOMS * NPAD];
__device__ __half g_hv2 [(size_t)N_ATOMS * NPAD];
__device__ __half g_P   [(size_t)N_ATOMS * NPAD];
__device__ __half g_agg [(size_t)N_ATOMS * NPAD];
__device__ __half g_mol [(size_t)N_MOLS * NPAD];
__device__ __half g_ffn [(size_t)N_MOLS * NPAD];

// transposed fp16 weights: Wt[n][Kld] (k contiguous)
__device__ __half g_atomWt[NPAD * KX];
__device__ __half g_WiTopT[NPAD * KH];
__device__ __half g_WoT   [NPAD * KWO];
__device__ __half g_ffn1T [NPAD * KH];
__device__ float  g_WiBot [KE * NPAD];     // fp32, row-major [k][320] for gather
__device__ float  g_atomB[NPAD];
__device__ float  g_WoB  [NPAD];
__device__ float  g_ffn1B[NPAD];

// CSR scratch
__device__ int g_counts[N_ATOMS_PAD];
__device__ int g_rowptr[N_ATOMS_PAD + 1];
__device__ int g_cursor[N_ATOMS];
__device__ int g_esrc[N_EDGES];
__device__ int g_eid [N_EDGES];
__device__ int g_molptr[N_MOLS + 1];
__device__ float g_eacsr[(size_t)N_EDGES * 16];

// ------------------------- helpers -------------------------
__device__ __forceinline__ uint32_t smem_u32(const void* p) {
    return (uint32_t)__cvta_generic_to_shared(p);
}

// ------------------------- repack kernels -------------------------
// float src -> half dst, zero-padded
__global__ void repackH(__half* __restrict__ dst, const float* __restrict__ src,
                        int dstR, int dstC, int srcR, int srcC, int srcRow0) {
    int idx = blockIdx.x * blockDim.x + threadIdx.x;
    if (idx >= dstR * dstC) return;
    int r = idx / dstC, c = idx - r * dstC;
    float v = 0.f;
    if (r < srcR && c < srcC) v = src[(size_t)(r + srcRow0) * srcC + c];
    dst[idx] = __float2half_rn(v);
}

// float src [K x srcC] -> half dst transposed [NPAD x Kld] slab at kOff
__global__ void repackTH(__half* __restrict__ dst, const float* __restrict__ src,
                         int Kld, int kOff, int kCnt, int kValid, int srcC, int srcRow0) {
    int idx = blockIdx.x * blockDim.x + threadIdx.x;
    if (idx >= NPAD * kCnt) return;
    int n = idx / kCnt, k = idx - n * kCnt;
    float v = 0.f;
    if (k < kValid && n < srcC) v = src[(size_t)(k + srcRow0) * srcC + n];
    dst[(size_t)n * Kld + kOff + k] = __float2half_rn(v);
}

// float->float zero-padded (biases, WiBot)
__global__ void repackF(float* __restrict__ dst, const float* __restrict__ src,
                        int dstR, int dstC, int srcR, int srcC, int srcRow0) {
    int idx = blockIdx.x * blockDim.x + threadIdx.x;
    if (idx >= dstR * dstC) return;
    int r = idx / dstC, c = idx - r * dstC;
    float v = 0.f;
    if (r < srcR && c < srcC) v = src[(size_t)(r + srcRow0) * srcC + c];
    dst[idx] = v;
}

__global__ void zeroI(int* __restrict__ p, int n) {
    int i = blockIdx.x * blockDim.x + threadIdx.x;
    if (i < n) p[i] = 0;
}

// ------------------------- CSR build -------------------------
__global__ void hist_dst(const int* __restrict__ dst, int* __restrict__ counts) {
    int e = blockIdx.x * blockDim.x + threadIdx.x;
    if (e < N_EDGES) atomicAdd(&counts[dst[e]], 1);
}

__global__ __launch_bounds__(1024)
void scan_counts(const int* __restrict__ counts, int* __restrict__ rowptr) {
    __shared__ int warp_sums[32];
    __shared__ int s_carry;
    const int tid = threadIdx.x;
    const int lane = tid & 31, wid = tid >> 5;
    if (tid == 0) s_carry = 0;
    __syncthreads();
    for (int base = 0; base < N_ATOMS_PAD; base += 4096) {
        int4 v = *(const int4*)(counts + base + tid * 4);
        int tsum = v.x + v.y + v.z + v.w;
        int val = tsum;
        #pragma unroll
        for (int off = 1; off < 32; off <<= 1) {
            int t = __shfl_up_sync(~0u, val, off);
            if (lane >= off) val += t;
        }
        if (lane == 31) warp_sums[wid] = val;
        __syncthreads();
        if (wid == 0) {
            int w = warp_sums[lane];
            #pragma unroll
            for (int off = 1; off < 32; off <<= 1) {
                int t = __shfl_up_sync(~0u, w, off);
                if (lane >= off) w += t;
            }
            warp_sums[lane] = w;
        }
        __syncthreads();
        int carry = s_carry;
        int excl = carry + (wid ? warp_sums[wid - 1] : 0) + (val - tsum);
        int idx = base + tid * 4;
        rowptr[idx + 0] = excl;
        rowptr[idx + 1] = excl + v.x;
        rowptr[idx + 2] = excl + v.x + v.y;
        rowptr[idx + 3] = excl + v.x + v.y + v.z;
        __syncthreads();
        if (tid == 0) s_carry = carry + warp_sums[31];
        __syncthreads();
    }
    if (threadIdx.x == 0) rowptr[N_ATOMS_PAD] = s_carry;
}

__global__ void copy_cursor(const int* __restrict__ rowptr, int* __restrict__ cursor) {
    int i = blockIdx.x * blockDim.x + threadIdx.x;
    if (i < N_ATOMS) cursor[i] = rowptr[i];
}

__global__ void fill_csr(const int* __restrict__ src, const int* __restrict__ dst,
                         int* __restrict__ cursor,
                         int* __restrict__ esrc, int* __restrict__ eid) {
    int e = blockIdx.x * blockDim.x + threadIdx.x;
    if (e >= N_EDGES) return;
    int d = dst[e];
    int pos = atomicAdd(&cursor[d], 1);
    esrc[pos] = src[e];
    eid[pos]  = e;
}

__global__ void permute_ea(const float* __restrict__ ea, const int* __restrict__ eid,
                           float* __restrict__ eacsr) {
    int idx = blockIdx.x * blockDim.x + threadIdx.x;
    if (idx >= N_EDGES * 16) return;
    int p = idx >> 4, c = idx & 15;
    float v = 0.f;
    if (c < BOND_FDIM) v = ea[(size_t)eid[p] * BOND_FDIM + c];
    eacsr[idx] = v;
}

__global__ void build_molptr(const int* __restrict__ batch, int* __restrict__ molptr) {
    int i = blockIdx.x * blockDim.x + threadIdx.x;
    if (i >= N_ATOMS) return;
    int b = batch[i];
    int bp = (i == 0) ? -1 : batch[i - 1];
    for (int m = bp + 1; m <= b; m++) molptr[m] = i;
    if (i == N_ATOMS - 1)
        for (int m = b + 1; m <= N_MOLS; m++) molptr[m] = N_ATOMS;
}

// ------------------------- fp16 tensor-core GEMM -------------------------
// C[M x 320](half) = half(relu?(A @ W + bias)), A = concat A1|A2 (half), W transposed Wt[n][Kld].
// Block 64x160, BK=16, triple-buffered cp.async, one sync/iter.
// 128 thr: 4 warps 1(m)x4(n); warp tile 64x40; mma.m16n8k16.f16 via ldmatrix.
__global__ __launch_bounds__(128)
void gemm_fp16(const __half* __restrict__ A1, int lda1, int K1,
               const __half* __restrict__ A2, int lda2,
               const __half* __restrict__ Wt, int Kld,
               const float* __restrict__ bias,
               __half* __restrict__ C, int M, int doRelu) {
    __shared__ __half As[3][BM][LDR];
    __shared__ __half Bs[3][BN][LDR];

    const int tid  = threadIdx.x;
    const int lane = tid & 31;
    const int wid  = tid >> 5;            // 0..3
    const int wn0  = wid * 40;
    const int row0 = blockIdx.x * BM;
    const int n0   = blockIdx.y * BN;
    const int fr = lane >> 2;
    const int fc = lane & 3;
    const int niter = Kld >> 4;

    // ldmatrix per-lane address components
    const int rA = ((lane >> 3) & 1) * 8 + (lane & 7);  // row within m16 block
    const int cA = (lane >> 4) * 8;                     // k half-offset
    const int rB = lane & 7;                            // row within n8 block
    const int cB = ((lane >> 3) & 1) * 8;               // k half-offset (lanes 0-15 used)

    float acc[4][5][4];
    #pragma unroll
    for (int mt = 0; mt < 4; mt++)
        #pragma unroll
        for (int nt = 0; nt < 5; nt++)
            #pragma unroll
            for (int i = 0; i < 4; i++) acc[mt][nt][i] = 0.f;

    auto stage = [&](int k0, int buf) {
        const __half* Asrc; int lda, kb;
        if (k0 < K1) { Asrc = A1; lda = lda1; kb = k0; }
        else         { Asrc = A2; lda = lda2; kb = k0 - K1; }
        // A tile: 64 rows x 16 halves = 128 16B-chunks, 1/thread
        {
            int m = tid >> 1, part = tid & 1;
            int g = row0 + m;
            const __half* src = Asrc + (size_t)g * lda + kb + part * 8;
            uint32_t dst = smem_u32(&As[buf][m][part * 8]);
            int ss = (g < M) ? 16 : 0;
            asm volatile("cp.async.cg.shared.global [%0], [%1], 16, %2;"
                         :: "r"(dst), "l"(src), "r"(ss));
        }
        // B tile: 160 rows x 16 halves = 320 16B-chunks
        #pragma unroll
        for (int j = 0; j < 3; j++) {
            int c = tid + j * 128;
            if (c < 320) {
                int n = c >> 1, part = c & 1;
                const __half* src = Wt + (size_t)(n0 + n) * Kld + k0 + part * 8;
                uint32_t dst = smem_u32(&Bs[buf][n][part * 8]);
                asm volatile("cp.async.cg.shared.global [%0], [%1], 16;"
                             :: "r"(dst), "l"(src));
            }
        }
        asm volatile("cp.async.commit_group;");
    };

    stage(0, 0);
    if (niter > 1) stage(BK, 1);

    for (int it = 0; it < niter; it++) {
        int buf = it % 3;
        if (it + 1 < niter) asm volatile("cp.async.wait_group 1;");
        else                asm volatile("cp.async.wait_group 0;");
        __syncthreads();
        if (it + 2 < niter) stage((it + 2) * BK, (it + 2) % 3);

        uint32_t a[4][4], b[5][2];
        #pragma unroll
        for (int mt = 0; mt < 4; mt++) {
            uint32_t addr = smem_u32(&As[buf][mt * 16 + rA][cA]);
            asm volatile("ldmatrix.sync.aligned.m8n8.x4.shared.b16 {%0,%1,%2,%3}, [%4];"
                         : "=r"(a[mt][0]), "=r"(a[mt][1]), "=r"(a[mt][2]), "=r"(a[mt][3])
                         : "r"(addr));
        }
        #pragma unroll
        for (int nt = 0; nt < 5; nt++) {
            uint32_t addr = smem_u32(&Bs[buf][wn0 + nt * 8 + rB][cB]);
            asm volatile("ldmatrix.sync.aligned.m8n8.x2.shared.b16 {%0,%1}, [%2];"
                         : "=r"(b[nt][0]), "=r"(b[nt][1]) : "r"(addr));
        }
        #pragma unroll
        for (int mt = 0; mt < 4; mt++)
            #pragma unroll
            for (int nt = 0; nt < 5; nt++)
                asm volatile(
                    "mma.sync.aligned.m16n8k16.row.col.f32.f16.f16.f32 "
                    "{%0,%1,%2,%3}, {%4,%5,%6,%7}, {%8,%9}, {%0,%1,%2,%3};"
                    : "+f"(acc[mt][nt][0]), "+f"(acc[mt][nt][1]),
                      "+f"(acc[mt][nt][2]), "+f"(acc[mt][nt][3])
                    : "r"(a[mt][0]), "r"(a[mt][1]), "r"(a[mt][2]), "r"(a[mt][3]),
                      "r"(b[nt][0]), "r"(b[nt][1]));
    }

    // epilogue: bias + relu? + fp16 round
    #pragma unroll
    for (int mt = 0; mt < 4; mt++) {
        int r = row0 + mt * 16 + fr;
        #pragma unroll
        for (int nt = 0; nt < 5; nt++) {
            int cbase = n0 + wn0 + nt * 8 + (fc << 1);
            float2 bv = *(const float2*)&bias[cbase];
            if (r < M) {
                float vx = acc[mt][nt][0] + bv.x, vy = acc[mt][nt][1] + bv.y;
                if (doRelu) { vx = fmaxf(vx, 0.f); vy = fmaxf(vy, 0.f); }
                *(__half2*)(C + (size_t)r * NPAD + cbase) = __floats2half2_rn(vx, vy);
            }
            if (r + 8 < M) {
                float vx = acc[mt][nt][2] + bv.x, vy = acc[mt][nt][3] + bv.y;
                if (doRelu) { vx = fmaxf(vx, 0.f); vy = fmaxf(vy, 0.f); }
                *(__half2*)(C + (size_t)(r + 8) * NPAD + cbase) = __floats2half2_rn(vx, vy);
            }
        }
    }
}

// ------------------------- CSR gather: agg[v] = sum_in relu(P[src] + eacsr[p] @ WiBot) -----
__global__ __launch_bounds__(256)
void gather_agg(const __half* __restrict__ P, const float* __restrict__ eacsr,
                const float* __restrict__ WiBot,
                const int* __restrict__ rowptr, const int* __restrict__ esrc,
                __half* __restrict__ agg) {
    __shared__ float Ws[14 * NPAD];
    for (int i = threadIdx.x; i < 14 * NPAD; i += 256) Ws[i] = WiBot[i];
    __syncthreads();

    int v = (blockIdx.x * 256 + threadIdx.x) >> 5;
    int lane = threadIdx.x & 31;
    if (v >= N_ATOMS) return;
    int beg = rowptr[v], end = rowptr[v + 1];

    float2 acc2[5];
    #pragma unroll
    for (int j = 0; j < 5; j++) acc2[j] = make_float2(0.f, 0.f);

    const float2* Ws2 = (const float2*)Ws;   // [14][160] float2

    for (int p = beg; p < end; p++) {
        int s = esrc[p];
        float eav = (lane < 16) ? eacsr[(size_t)p * 16 + lane] : 0.f;
        float ef[14];
        #pragma unroll
        for (int f = 0; f < 14; f++) ef[f] = __shfl_sync(~0u, eav, f);
        const __half2* Pr = (const __half2*)(P + (size_t)s * NPAD);
        #pragma unroll
        for (int j = 0; j < 5; j++) {
            int idx = lane + 32 * j;
            float2 m2 = __half22float2(Pr[idx]);
            #pragma unroll
            for (int f = 0; f < 14; f++) {
                float2 w = Ws2[f * 160 + idx];
                m2.x = fmaf(ef[f], w.x, m2.x);
                m2.y = fmaf(ef[f], w.y, m2.y);
            }
            acc2[j].x += fmaxf(m2.x, 0.f);
            acc2[j].y += fmaxf(m2.y, 0.f);
        }
    }
    __half2* ag = (__half2*)(agg + (size_t)v * NPAD);
    #pragma unroll
    for (int j = 0; j < 5; j++) ag[lane + 32 * j] = __floats2half2_rn(acc2[j].x, acc2[j].y);
}

// ------------------------- molecule pooling -------------------------
__global__ void mol_sum(const __half* __restrict__ hv, const int* __restrict__ molptr,
                        __half* __restrict__ mol) {
    int m = (blockIdx.x * blockDim.x + threadIdx.x) >> 5;
    int lane = threadIdx.x & 31;
    if (m >= N_MOLS) return;
    int beg = molptr[m], end = molptr[m + 1];
    float2 acc2[5];
    #pragma unroll
    for (int j = 0; j < 5; j++) acc2[j] = make_float2(0.f, 0.f);
    for (int a = beg; a < end; a++) {
        const __half2* hr = (const __half2*)(hv + (size_t)a * NPAD);
        #pragma unroll
        for (int j = 0; j < 5; j++) {
            float2 t = __half22float2(hr[lane + 32 * j]);
            acc2[j].x += t.x; acc2[j].y += t.y;
        }
    }
    __half2* mr = (__half2*)(mol + (size_t)m * NPAD);
    #pragma unroll
    for (int j = 0; j < 5; j++) mr[lane + 32 * j] = __floats2half2_rn(acc2[j].x, acc2[j].y);
}

// ------------------------- final: out = ffn @ ffn2 + b2 -------------------------
__global__ void finalk(const __half* __restrict__ F, const float* __restrict__ W2,
                       const float* __restrict__ b2, float* __restrict__ out) {
    int w = (blockIdx.x * blockDim.x + threadIdx.x) >> 5;
    int lane = threadIdx.x & 31;
    if (w >= N_MOLS) return;
    float acc = (lane < 12) ? b2[lane] : 0.f;
    const __half* f = F + (size_t)w * NPAD;
    for (int j = 0; j < HIDDEN; j++) {
        float fv = __half2float(f[j]);
        if (lane < 12) acc = fmaf(fv, W2[j * 12 + lane], acc);
    }
    if (lane < 12) out[w * 12 + lane] = acc;
}

// ------------------------- host launch -------------------------
static inline dim3 rep_grid(int n) { return dim3((n + 255) / 256); }

extern "C" void kernel_launch(void* const* d_in, const int* in_sizes, int n_in,
                              void* d_out, int out_size) {
    const float* x      = (const float*)d_in[0];
    const int*   ei     = (const int*)  d_in[1];
    const float* ea     = (const float*)d_in[2];
    const int*   batch  = (const int*)  d_in[3];
    const float* atom_W = (const float*)d_in[4];
    const float* atom_b = (const float*)d_in[5];
    // d_in[6], d_in[7]: bond_W / bond_b  -> dead code
    const float* Wi     = (const float*)d_in[8];
    // d_in[9]: Wh -> dead code
    const float* Wo     = (const float*)d_in[10];
    const float* Wo_b   = (const float*)d_in[11];
    const float* ffn1_W = (const float*)d_in[12];
    const float* ffn1_b = (const float*)d_in[13];
    const float* ffn2_W = (const float*)d_in[14];
    const float* ffn2_b = (const float*)d_in[15];
    float* out = (float*)d_out;

    __half *p_xpad, *p_hv, *p_hv2, *p_P, *p_agg, *p_mol, *p_ffn;
    __half *p_atomWt, *p_WiTopT, *p_WoT, *p_ffn1T;
    float *p_WiBot, *p_atomB, *p_WoB, *p_ffn1B, *p_eacsr;
    int *p_counts, *p_rowptr, *p_cursor, *p_esrc, *p_eid, *p_molptr;
    cudaGetSymbolAddress((void**)&p_xpad,  g_xpad);
    cudaGetSymbolAddress((void**)&p_hv,    g_hv);
    cudaGetSymbolAddress((void**)&p_hv2,   g_hv2);
    cudaGetSymbolAddress((void**)&p_P,     g_P);
    cudaGetSymbolAddress((void**)&p_agg,   g_agg);
    cudaGetSymbolAddress((void**)&p_mol,   g_mol);
    cudaGetSymbolAddress((void**)&p_ffn,   g_ffn);
    cudaGetSymbolAddress((void**)&p_atomWt, g_atomWt);
    cudaGetSymbolAddress((void**)&p_WiTopT, g_WiTopT);
    cudaGetSymbolAddress((void**)&p_WoT,    g_WoT);
    cudaGetSymbolAddress((void**)&p_ffn1T,  g_ffn1T);
    cudaGetSymbolAddress((void**)&p_WiBot,  g_WiBot);
    cudaGetSymbolAddress((void**)&p_atomB, g_atomB);
    cudaGetSymbolAddress((void**)&p_WoB,   g_WoB);
    cudaGetSymbolAddress((void**)&p_ffn1B, g_ffn1B);
    cudaGetSymbolAddress((void**)&p_eacsr, g_eacsr);
    cudaGetSymbolAddress((void**)&p_counts, g_counts);
    cudaGetSymbolAddress((void**)&p_rowptr, g_rowptr);
    cudaGetSymbolAddress((void**)&p_cursor, g_cursor);
    cudaGetSymbolAddress((void**)&p_esrc,   g_esrc);
    cudaGetSymbolAddress((void**)&p_eid,    g_eid);
    cudaGetSymbolAddress((void**)&p_molptr, g_molptr);

    const int* e_src = ei;
    const int* e_dst = ei + N_EDGES;

    dim3 gAtom((N_ATOMS + BM - 1) / BM, NPAD / BN);
    dim3 gMol ((N_MOLS  + BM - 1) / BM, NPAD / BN);
    int gather_blocks = (N_ATOMS * 32 + 255) / 256;

    // ---- diagnostic-ordered prologue (GEMMs early for ncu) ----
    repackH<<<rep_grid(N_ATOMS * KX), 256>>>(p_xpad, x, N_ATOMS, KX, N_ATOMS, ATOM_FDIM, 0);
    repackTH<<<rep_grid(NPAD * KX), 256>>>(p_atomWt, atom_W, KX, 0, KX, ATOM_FDIM, HIDDEN, 0);
    repackF<<<rep_grid(NPAD), 256>>>(p_atomB, atom_b, 1, NPAD, 1, HIDDEN, 0);
    repackTH<<<rep_grid(NPAD * KH), 256>>>(p_WiTopT, Wi, KH, 0, KH, HIDDEN, HIDDEN, 0);
    // h_v = relu(x @ atom_W + atom_b)
    gemm_fp16<<<gAtom, 128>>>(p_xpad, KX, KX, p_xpad, KX,
                              p_atomWt, KX, p_atomB, p_hv, N_ATOMS, 1);
    // P = h_v @ Wi_top (depth 0) — ncu capture target
    gemm_fp16<<<gAtom, 128>>>(p_hv, NPAD, KH, p_hv, NPAD,
                              p_WiTopT, KH, p_atomB /*unused cols ok? no: zeros needed*/, p_P, N_ATOMS, 0);

    // NOTE: P GEMM must use zero bias; re-issue with correct bias below is wrong.
    // Instead: p_atomB is NOT zero. Fix: use g_ffn1B before it's filled? Unsafe.
    // -> dedicated zero bias: reuse g_WoB before fill? Also unsafe. Use static zero array:
    // (declared below via g_eacsr? no). We keep a real zero vector:
    // g_WiBot is filled later; its first row is not zero either. Simplest correct:
    // launch a tiny kernel to zero a scratch bias BEFORE the P GEMM. Done above? No.
    // --- the two lines below replace the erroneous launch order ---

    // ---- remaining weight repacks ----
    repackTH<<<rep_grid(NPAD * KH), 256>>>(p_WoT, Wo, KWO, 0,  KH, HIDDEN, HIDDEN, 0);
    repackTH<<<rep_grid(NPAD * KH), 256>>>(p_WoT, Wo, KWO, KH, KH, HIDDEN, HIDDEN, HIDDEN);
    repackTH<<<rep_grid(NPAD * KH), 256>>>(p_ffn1T, ffn1_W, KH, 0, KH, HIDDEN, HIDDEN, 0);
    repackF<<<rep_grid(KE * NPAD), 256>>>(p_WiBot, Wi, KE, NPAD, BOND_FDIM, HIDDEN, HIDDEN);
    repackF<<<rep_grid(NPAD), 256>>>(p_WoB, Wo_b, 1, NPAD, 1, HIDDEN, 0);
    repackF<<<rep_grid(NPAD), 256>>>(p_ffn1B, ffn1_b, 1, NPAD, 1, HIDDEN, 0);

    // ---- CSR build + ea permute + mol boundaries ----
    zeroI<<<rep_grid(N_ATOMS_PAD), 256>>>(p_counts, N_ATOMS_PAD);
    hist_dst<<<rep_grid(N_EDGES), 256>>>(e_dst, p_counts);
    scan_counts<<<1, 1024>>>(p_counts, p_rowptr);
    copy_cursor<<<rep_grid(N_ATOMS), 256>>>(p_rowptr, p_cursor);
    fill_csr<<<rep_grid(N_EDGES), 256>>>(e_src, e_dst, p_cursor, p_esrc, p_eid);
    permute_ea<<<rep_grid(N_EDGES * 16), 256>>>(ea, p_eid, p_eacsr);
    build_molptr<<<rep_grid(N_ATOMS), 256>>>(batch, p_molptr);

    // Correct the depth-0 P: the early P-GEMM above used a wrong (nonzero) bias.
    // Recompute P with the true zero bias (g_eacsr row 15 is always zero? no).
    // Use the fact that relu-less GEMM with bias=0 is needed: zero 320 floats in g_counts
    // region is int... Simplest: reuse p_counts (already consumed by scan) as a zero
    // float bias: it was overwritten. Not zero. => zero it explicitly:
    zeroI<<<2, 256>>>(p_counts, NPAD);   // 320 ints == 320 zero floats bit-pattern
    gemm_fp16<<<gAtom, 128>>>(p_hv, NPAD, KH, p_hv, NPAD,
                              p_WiTopT, KH, (const float*)p_counts, p_P, N_ATOMS, 0);

    // ---- depth 0 remainder ----
    gather_agg<<<gather_blocks, 256>>>(p_P, p_eacsr, p_WiBot, p_rowptr, p_esrc, p_agg);
    gemm_fp16<<<gAtom, 128>>>(p_hv, NPAD, KH, p_agg, NPAD,
                              p_WoT, KWO, p_WoB, p_hv2, N_ATOMS, 1);

    // ---- depths 1..2 ----
    __half* cur = p_hv2;
    __half* nxt = p_hv;
    for (int d = 1; d < 3; d++) {
        gemm_fp16<<<gAtom, 128>>>(cur, NPAD, KH, cur, NPAD,
                                  p_WiTopT, KH, (const float*)p_counts, p_P, N_ATOMS, 0);
        gather_agg<<<gather_blocks, 256>>>(p_P, p_eacsr, p_WiBot, p_rowptr, p_esrc, p_agg);
        gemm_fp16<<<gAtom, 128>>>(cur, NPAD, KH, p_agg, NPAD,
                                  p_WoT, KWO, p_WoB, nxt, N_ATOMS, 1);
        __half* t = cur; cur = nxt; nxt = t;
    }

    // mol_repr = segment_sum(h_v, batch)
    mol_sum<<<(N_MOLS * 32 + 255) / 256, 256>>>(cur, p_molptr, p_mol);
    // ffn = relu(mol @ ffn1 + b1)
    gemm_fp16<<<gMol, 128>>>(p_mol, NPAD, KH, p_mol, NPAD,
                             p_ffn1T, KH, p_ffn1B, p_ffn, N_MOLS, 1);
    // out = ffn @ ffn2 + b2
    finalk<<<(N_MOLS * 32 + 255) / 256, 256>>>(p_ffn, ffn2_W, ffn2_b, out);
}

// round 13
// speedup vs baseline: 1.6497x; 1.1394x over previous
#include <cuda_runtime.h>
#include <cuda_fp16.h>
#include <cstdint>

#define N_ATOMS 100000
#define N_ATOMS_PAD 102400   // multiple of 4096 for the scan
#define N_EDGES 400000
#define N_MOLS  4096
#define ATOM_FDIM 133
#define BOND_FDIM 14
#define HIDDEN 300
#define N_LABELS 12
#define NPAD 320        // padded hidden width
#define KX 144          // padded atom feature dim (multiple of 16)
#define KE 16
#define KH 304          // padded hidden as K-dim (multiple of 16)
#define KWO 608         // concat K for Wo GEMM

#define BM 64
#define BN 160
#define BK 16
#define LDR 24          // SMEM row stride in halves (48B): 12r mod 32 distinct over 8 rows

// ------------------------- scratch (static, no allocs) -------------------------
__device__ __half g_xpad[(size_t)N_ATOMS * KX];
__device__ __half g_hv  [(size_t)N_ATOMS * NPAD];
__device__ __half g_hv2 [(size_t)N_ATOMS * NPAD];
__device__ __half g_P   [(size_t)N_ATOMS * NPAD];
__device__ __half g_agg [(size_t)N_ATOMS * NPAD];
__device__ __half g_mol [(size_t)N_MOLS * NPAD];
__device__ __half g_ffn [(size_t)N_MOLS * NPAD];

// transposed fp16 weights: Wt[n][Kld] (k contiguous)
__device__ __half g_atomWt[NPAD * KX];
__device__ __half g_WiTopT[NPAD * KH];
__device__ __half g_WoT   [NPAD * KWO];
__device__ __half g_ffn1T [NPAD * KH];
__device__ float  g_WiBot [KE * NPAD];     // fp32, row-major [k][320] for gather
__device__ float  g_atomB[NPAD];
__device__ float  g_WoB  [NPAD];
__device__ float  g_ffn1B[NPAD];
__device__ float  g_zeroB[NPAD];           // statically zero — zero-bias GEMMs

// CSR scratch
__device__ int g_counts[N_ATOMS_PAD];
__device__ int g_rowptr[N_ATOMS_PAD + 1];
__device__ int g_cursor[N_ATOMS];
__device__ int g_esrc[N_EDGES];
__device__ int g_eid [N_EDGES];
__device__ int g_molptr[N_MOLS + 1];
__device__ float g_eacsr[(size_t)N_EDGES * 16];

// ------------------------- helpers -------------------------
__device__ __forceinline__ uint32_t smem_u32(const void* p) {
    return (uint32_t)__cvta_generic_to_shared(p);
}

// ------------------------- repack kernels -------------------------
__global__ void repackH(__half* __restrict__ dst, const float* __restrict__ src,
                        int dstR, int dstC, int srcR, int srcC, int srcRow0) {
    int idx = blockIdx.x * blockDim.x + threadIdx.x;
    if (idx >= dstR * dstC) return;
    int r = idx / dstC, c = idx - r * dstC;
    float v = 0.f;
    if (r < srcR && c < srcC) v = src[(size_t)(r + srcRow0) * srcC + c];
    dst[idx] = __float2half_rn(v);
}

__global__ void repackTH(__half* __restrict__ dst, const float* __restrict__ src,
                         int Kld, int kOff, int kCnt, int kValid, int srcC, int srcRow0) {
    int idx = blockIdx.x * blockDim.x + threadIdx.x;
    if (idx >= NPAD * kCnt) return;
    int n = idx / kCnt, k = idx - n * kCnt;
    float v = 0.f;
    if (k < kValid && n < srcC) v = src[(size_t)(k + srcRow0) * srcC + n];
    dst[(size_t)n * Kld + kOff + k] = __float2half_rn(v);
}

__global__ void repackF(float* __restrict__ dst, const float* __restrict__ src,
                        int dstR, int dstC, int srcR, int srcC, int srcRow0) {
    int idx = blockIdx.x * blockDim.x + threadIdx.x;
    if (idx >= dstR * dstC) return;
    int r = idx / dstC, c = idx - r * dstC;
    float v = 0.f;
    if (r < srcR && c < srcC) v = src[(size_t)(r + srcRow0) * srcC + c];
    dst[idx] = v;
}

__global__ void zeroI(int* __restrict__ p, int n) {
    int i = blockIdx.x * blockDim.x + threadIdx.x;
    if (i < n) p[i] = 0;
}

// ------------------------- CSR build -------------------------
__global__ void hist_dst(const int* __restrict__ dst, int* __restrict__ counts) {
    int e = blockIdx.x * blockDim.x + threadIdx.x;
    if (e < N_EDGES) atomicAdd(&counts[dst[e]], 1);
}

__global__ __launch_bounds__(1024)
void scan_counts(const int* __restrict__ counts, int* __restrict__ rowptr) {
    __shared__ int warp_sums[32];
    __shared__ int s_carry;
    const int tid = threadIdx.x;
    const int lane = tid & 31, wid = tid >> 5;
    if (tid == 0) s_carry = 0;
    __syncthreads();
    for (int base = 0; base < N_ATOMS_PAD; base += 4096) {
        int4 v = *(const int4*)(counts + base + tid * 4);
        int tsum = v.x + v.y + v.z + v.w;
        int val = tsum;
        #pragma unroll
        for (int off = 1; off < 32; off <<= 1) {
            int t = __shfl_up_sync(~0u, val, off);
            if (lane >= off) val += t;
        }
        if (lane == 31) warp_sums[wid] = val;
        __syncthreads();
        if (wid == 0) {
            int w = warp_sums[lane];
            #pragma unroll
            for (int off = 1; off < 32; off <<= 1) {
                int t = __shfl_up_sync(~0u, w, off);
                if (lane >= off) w += t;
            }
            warp_sums[lane] = w;
        }
        __syncthreads();
        int carry = s_carry;
        int excl = carry + (wid ? warp_sums[wid - 1] : 0) + (val - tsum);
        int idx = base + tid * 4;
        rowptr[idx + 0] = excl;
        rowptr[idx + 1] = excl + v.x;
        rowptr[idx + 2] = excl + v.x + v.y;
        rowptr[idx + 3] = excl + v.x + v.y + v.z;
        __syncthreads();
        if (tid == 0) s_carry = carry + warp_sums[31];
        __syncthreads();
    }
    if (threadIdx.x == 0) rowptr[N_ATOMS_PAD] = s_carry;
}

__global__ void copy_cursor(const int* __restrict__ rowptr, int* __restrict__ cursor) {
    int i = blockIdx.x * blockDim.x + threadIdx.x;
    if (i < N_ATOMS) cursor[i] = rowptr[i];
}

__global__ void fill_csr(const int* __restrict__ src, const int* __restrict__ dst,
                         int* __restrict__ cursor,
                         int* __restrict__ esrc, int* __restrict__ eid) {
    int e = blockIdx.x * blockDim.x + threadIdx.x;
    if (e >= N_EDGES) return;
    int d = dst[e];
    int pos = atomicAdd(&cursor[d], 1);
    esrc[pos] = src[e];
    eid[pos]  = e;
}

__global__ void permute_ea(const float* __restrict__ ea, const int* __restrict__ eid,
                           float* __restrict__ eacsr) {
    int idx = blockIdx.x * blockDim.x + threadIdx.x;
    if (idx >= N_EDGES * 16) return;
    int p = idx >> 4, c = idx & 15;
    float v = 0.f;
    if (c < BOND_FDIM) v = ea[(size_t)eid[p] * BOND_FDIM + c];
    eacsr[idx] = v;
}

__global__ void build_molptr(const int* __restrict__ batch, int* __restrict__ molptr) {
    int i = blockIdx.x * blockDim.x + threadIdx.x;
    if (i >= N_ATOMS) return;
    int b = batch[i];
    int bp = (i == 0) ? -1 : batch[i - 1];
    for (int m = bp + 1; m <= b; m++) molptr[m] = i;
    if (i == N_ATOMS - 1)
        for (int m = b + 1; m <= N_MOLS; m++) molptr[m] = N_ATOMS;
}

// ------------------------- fp16 tensor-core GEMM -------------------------
// C[M x 320](half) = half(relu?(A @ W + bias)), A = concat A1|A2 (half), W transposed Wt[n][Kld].
// Block 64x160, BK=16, triple-buffered cp.async, one sync/iter.
// 128 thr: 4 warps 1(m)x4(n); warp tile 64x40; mma.m16n8k16.f16 via ldmatrix.
__global__ __launch_bounds__(128, 4)
void gemm_fp16(const __half* __restrict__ A1, int lda1, int K1,
               const __half* __restrict__ A2, int lda2,
               const __half* __restrict__ Wt, int Kld,
               const float* __restrict__ bias,
               __half* __restrict__ C, int M, int doRelu) {
    __shared__ __half As[3][BM][LDR];
    __shared__ __half Bs[3][BN][LDR];

    const int tid  = threadIdx.x;
    const int lane = tid & 31;
    const int wid  = tid >> 5;            // 0..3
    const int wn0  = wid * 40;
    const int row0 = blockIdx.x * BM;
    const int n0   = blockIdx.y * BN;
    const int fr = lane >> 2;
    const int fc = lane & 3;
    const int niter = Kld >> 4;

    const int rA = ((lane >> 3) & 1) * 8 + (lane & 7);
    const int cA = (lane >> 4) * 8;
    const int rB = lane & 7;
    const int cB = ((lane >> 3) & 1) * 8;

    float acc[4][5][4];
    #pragma unroll
    for (int mt = 0; mt < 4; mt++)
        #pragma unroll
        for (int nt = 0; nt < 5; nt++)
            #pragma unroll
            for (int i = 0; i < 4; i++) acc[mt][nt][i] = 0.f;

    auto stage = [&](int k0, int buf) {
        const __half* Asrc; int lda, kb;
        if (k0 < K1) { Asrc = A1; lda = lda1; kb = k0; }
        else         { Asrc = A2; lda = lda2; kb = k0 - K1; }
        {
            int m = tid >> 1, part = tid & 1;
            int g = row0 + m;
            const __half* src = Asrc + (size_t)g * lda + kb + part * 8;
            uint32_t dst = smem_u32(&As[buf][m][part * 8]);
            int ss = (g < M) ? 16 : 0;
            asm volatile("cp.async.cg.shared.global [%0], [%1], 16, %2;"
                         :: "r"(dst), "l"(src), "r"(ss));
        }
        #pragma unroll
        for (int j = 0; j < 3; j++) {
            int c = tid + j * 128;
            if (c < 320) {
                int n = c >> 1, part = c & 1;
                const __half* src = Wt + (size_t)(n0 + n) * Kld + k0 + part * 8;
                uint32_t dst = smem_u32(&Bs[buf][n][part * 8]);
                asm volatile("cp.async.cg.shared.global [%0], [%1], 16;"
                             :: "r"(dst), "l"(src));
            }
        }
        asm volatile("cp.async.commit_group;");
    };

    stage(0, 0);
    if (niter > 1) stage(BK, 1);

    for (int it = 0; it < niter; it++) {
        int buf = it % 3;
        if (it + 1 < niter) asm volatile("cp.async.wait_group 1;");
        else                asm volatile("cp.async.wait_group 0;");
        __syncthreads();
        if (it + 2 < niter) stage((it + 2) * BK, (it + 2) % 3);

        uint32_t a[4][4], b[5][2];
        #pragma unroll
        for (int mt = 0; mt < 4; mt++) {
            uint32_t addr = smem_u32(&As[buf][mt * 16 + rA][cA]);
            asm volatile("ldmatrix.sync.aligned.m8n8.x4.shared.b16 {%0,%1,%2,%3}, [%4];"
                         : "=r"(a[mt][0]), "=r"(a[mt][1]), "=r"(a[mt][2]), "=r"(a[mt][3])
                         : "r"(addr));
        }
        #pragma unroll
        for (int nt = 0; nt < 5; nt++) {
            uint32_t addr = smem_u32(&Bs[buf][wn0 + nt * 8 + rB][cB]);
            asm volatile("ldmatrix.sync.aligned.m8n8.x2.shared.b16 {%0,%1}, [%2];"
                         : "=r"(b[nt][0]), "=r"(b[nt][1]) : "r"(addr));
        }
        #pragma unroll
        for (int mt = 0; mt < 4; mt++)
            #pragma unroll
            for (int nt = 0; nt < 5; nt++)
                asm volatile(
                    "mma.sync.aligned.m16n8k16.row.col.f32.f16.f16.f32 "
                    "{%0,%1,%2,%3}, {%4,%5,%6,%7}, {%8,%9}, {%0,%1,%2,%3};"
                    : "+f"(acc[mt][nt][0]), "+f"(acc[mt][nt][1]),
                      "+f"(acc[mt][nt][2]), "+f"(acc[mt][nt][3])
                    : "r"(a[mt][0]), "r"(a[mt][1]), "r"(a[mt][2]), "r"(a[mt][3]),
                      "r"(b[nt][0]), "r"(b[nt][1]));
    }

    // epilogue: bias + relu? + fp16 round
    #pragma unroll
    for (int mt = 0; mt < 4; mt++) {
        int r = row0 + mt * 16 + fr;
        #pragma unroll
        for (int nt = 0; nt < 5; nt++) {
            int cbase = n0 + wn0 + nt * 8 + (fc << 1);
            float2 bv = *(const float2*)&bias[cbase];
            if (r < M) {
                float vx = acc[mt][nt][0] + bv.x, vy = acc[mt][nt][1] + bv.y;
                if (doRelu) { vx = fmaxf(vx, 0.f); vy = fmaxf(vy, 0.f); }
                *(__half2*)(C + (size_t)r * NPAD + cbase) = __floats2half2_rn(vx, vy);
            }
            if (r + 8 < M) {
                float vx = acc[mt][nt][2] + bv.x, vy = acc[mt][nt][3] + bv.y;
                if (doRelu) { vx = fmaxf(vx, 0.f); vy = fmaxf(vy, 0.f); }
                *(__half2*)(C + (size_t)(r + 8) * NPAD + cbase) = __floats2half2_rn(vx, vy);
            }
        }
    }
}

// ------------------------- CSR gather: agg[v] = sum_in relu(P[src] + eacsr[p] @ WiBot) -----
// edge loop unrolled by 2 for memory-level parallelism
__global__ __launch_bounds__(256)
void gather_agg(const __half* __restrict__ P, const float* __restrict__ eacsr,
                const float* __restrict__ WiBot,
                const int* __restrict__ rowptr, const int* __restrict__ esrc,
                __half* __restrict__ agg) {
    __shared__ float Ws[14 * NPAD];
    for (int i = threadIdx.x; i < 14 * NPAD; i += 256) Ws[i] = WiBot[i];
    __syncthreads();

    int v = (blockIdx.x * 256 + threadIdx.x) >> 5;
    int lane = threadIdx.x & 31;
    if (v >= N_ATOMS) return;
    int beg = rowptr[v], end = rowptr[v + 1];

    float2 acc2[5];
    #pragma unroll
    for (int j = 0; j < 5; j++) acc2[j] = make_float2(0.f, 0.f);

    const float2* Ws2 = (const float2*)Ws;   // [14][160] float2

    int p = beg;
    for (; p + 2 <= end; p += 2) {
        int s0 = esrc[p], s1 = esrc[p + 1];
        float eav0 = (lane < 16) ? eacsr[(size_t)p * 16 + lane] : 0.f;
        float eav1 = (lane < 16) ? eacsr[(size_t)(p + 1) * 16 + lane] : 0.f;
        const __half2* Pr0 = (const __half2*)(P + (size_t)s0 * NPAD);
        const __half2* Pr1 = (const __half2*)(P + (size_t)s1 * NPAD);
        float ef0[14], ef1[14];
        #pragma unroll
        for (int f = 0; f < 14; f++) {
            ef0[f] = __shfl_sync(~0u, eav0, f);
            ef1[f] = __shfl_sync(~0u, eav1, f);
        }
        #pragma unroll
        for (int j = 0; j < 5; j++) {
            int idx = lane + 32 * j;
            float2 m0 = __half22float2(Pr0[idx]);
            float2 m1 = __half22float2(Pr1[idx]);
            #pragma unroll
            for (int f = 0; f < 14; f++) {
                float2 w = Ws2[f * 160 + idx];
                m0.x = fmaf(ef0[f], w.x, m0.x);
                m0.y = fmaf(ef0[f], w.y, m0.y);
                m1.x = fmaf(ef1[f], w.x, m1.x);
                m1.y = fmaf(ef1[f], w.y, m1.y);
            }
            acc2[j].x += fmaxf(m0.x, 0.f) + fmaxf(m1.x, 0.f);
            acc2[j].y += fmaxf(m0.y, 0.f) + fmaxf(m1.y, 0.f);
        }
    }
    for (; p < end; p++) {
        int s = esrc[p];
        float eav = (lane < 16) ? eacsr[(size_t)p * 16 + lane] : 0.f;
        float ef[14];
        #pragma unroll
        for (int f = 0; f < 14; f++) ef[f] = __shfl_sync(~0u, eav, f);
        const __half2* Pr = (const __half2*)(P + (size_t)s * NPAD);
        #pragma unroll
        for (int j = 0; j < 5; j++) {
            int idx = lane + 32 * j;
            float2 m2 = __half22float2(Pr[idx]);
            #pragma unroll
            for (int f = 0; f < 14; f++) {
                float2 w = Ws2[f * 160 + idx];
                m2.x = fmaf(ef[f], w.x, m2.x);
                m2.y = fmaf(ef[f], w.y, m2.y);
            }
            acc2[j].x += fmaxf(m2.x, 0.f);
            acc2[j].y += fmaxf(m2.y, 0.f);
        }
    }
    __half2* ag = (__half2*)(agg + (size_t)v * NPAD);
    #pragma unroll
    for (int j = 0; j < 5; j++) ag[lane + 32 * j] = __floats2half2_rn(acc2[j].x, acc2[j].y);
}

// ------------------------- molecule pooling -------------------------
__global__ void mol_sum(const __half* __restrict__ hv, const int* __restrict__ molptr,
                        __half* __restrict__ mol) {
    int m = (blockIdx.x * blockDim.x + threadIdx.x) >> 5;
    int lane = threadIdx.x & 31;
    if (m >= N_MOLS) return;
    int beg = molptr[m], end = molptr[m + 1];
    float2 acc2[5];
    #pragma unroll
    for (int j = 0; j < 5; j++) acc2[j] = make_float2(0.f, 0.f);
    for (int a = beg; a < end; a++) {
        const __half2* hr = (const __half2*)(hv + (size_t)a * NPAD);
        #pragma unroll
        for (int j = 0; j < 5; j++) {
            float2 t = __half22float2(hr[lane + 32 * j]);
            acc2[j].x += t.x; acc2[j].y += t.y;
        }
    }
    __half2* mr = (__half2*)(mol + (size_t)m * NPAD);
    #pragma unroll
    for (int j = 0; j < 5; j++) mr[lane + 32 * j] = __floats2half2_rn(acc2[j].x, acc2[j].y);
}

// ------------------------- final: out = ffn @ ffn2 + b2 -------------------------
__global__ void finalk(const __half* __restrict__ F, const float* __restrict__ W2,
                       const float* __restrict__ b2, float* __restrict__ out) {
    int w = (blockIdx.x * blockDim.x + threadIdx.x) >> 5;
    int lane = threadIdx.x & 31;
    if (w >= N_MOLS) return;
    float acc = (lane < 12) ? b2[lane] : 0.f;
    const __half* f = F + (size_t)w * NPAD;
    for (int j = 0; j < HIDDEN; j++) {
        float fv = __half2float(f[j]);
        if (lane < 12) acc = fmaf(fv, W2[j * 12 + lane], acc);
    }
    if (lane < 12) out[w * 12 + lane] = acc;
}

// ------------------------- host launch -------------------------
static inline dim3 rep_grid(int n) { return dim3((n + 255) / 256); }

extern "C" void kernel_launch(void* const* d_in, const int* in_sizes, int n_in,
                              void* d_out, int out_size) {
    const float* x      = (const float*)d_in[0];
    const int*   ei     = (const int*)  d_in[1];
    const float* ea     = (const float*)d_in[2];
    const int*   batch  = (const int*)  d_in[3];
    const float* atom_W = (const float*)d_in[4];
    const float* atom_b = (const float*)d_in[5];
    // d_in[6], d_in[7]: bond_W / bond_b  -> dead code
    const float* Wi     = (const float*)d_in[8];
    // d_in[9]: Wh -> dead code
    const float* Wo     = (const float*)d_in[10];
    const float* Wo_b   = (const float*)d_in[11];
    const float* ffn1_W = (const float*)d_in[12];
    const float* ffn1_b = (const float*)d_in[13];
    const float* ffn2_W = (const float*)d_in[14];
    const float* ffn2_b = (const float*)d_in[15];
    float* out = (float*)d_out;

    __half *p_xpad, *p_hv, *p_hv2, *p_P, *p_agg, *p_mol, *p_ffn;
    __half *p_atomWt, *p_WiTopT, *p_WoT, *p_ffn1T;
    float *p_WiBot, *p_atomB, *p_WoB, *p_ffn1B, *p_zeroB, *p_eacsr;
    int *p_counts, *p_rowptr, *p_cursor, *p_esrc, *p_eid, *p_molptr;
    cudaGetSymbolAddress((void**)&p_xpad,  g_xpad);
    cudaGetSymbolAddress((void**)&p_hv,    g_hv);
    cudaGetSymbolAddress((void**)&p_hv2,   g_hv2);
    cudaGetSymbolAddress((void**)&p_P,     g_P);
    cudaGetSymbolAddress((void**)&p_agg,   g_agg);
    cudaGetSymbolAddress((void**)&p_mol,   g_mol);
    cudaGetSymbolAddress((void**)&p_ffn,   g_ffn);
    cudaGetSymbolAddress((void**)&p_atomWt, g_atomWt);
    cudaGetSymbolAddress((void**)&p_WiTopT, g_WiTopT);
    cudaGetSymbolAddress((void**)&p_WoT,    g_WoT);
    cudaGetSymbolAddress((void**)&p_ffn1T,  g_ffn1T);
    cudaGetSymbolAddress((void**)&p_WiBot,  g_WiBot);
    cudaGetSymbolAddress((void**)&p_atomB, g_atomB);
    cudaGetSymbolAddress((void**)&p_WoB,   g_WoB);
    cudaGetSymbolAddress((void**)&p_ffn1B, g_ffn1B);
    cudaGetSymbolAddress((void**)&p_zeroB, g_zeroB);
    cudaGetSymbolAddress((void**)&p_eacsr, g_eacsr);
    cudaGetSymbolAddress((void**)&p_counts, g_counts);
    cudaGetSymbolAddress((void**)&p_rowptr, g_rowptr);
    cudaGetSymbolAddress((void**)&p_cursor, g_cursor);
    cudaGetSymbolAddress((void**)&p_esrc,   g_esrc);
    cudaGetSymbolAddress((void**)&p_eid,    g_eid);
    cudaGetSymbolAddress((void**)&p_molptr, g_molptr);

    const int* e_src = ei;
    const int* e_dst = ei + N_EDGES;

    dim3 gAtom((N_ATOMS + BM - 1) / BM, NPAD / BN);
    dim3 gMol ((N_MOLS  + BM - 1) / BM, NPAD / BN);
    int gather_blocks = (N_ATOMS * 32 + 255) / 256;

    // ---- repacks ----
    repackH<<<rep_grid(N_ATOMS * KX), 256>>>(p_xpad, x, N_ATOMS, KX, N_ATOMS, ATOM_FDIM, 0);
    repackTH<<<rep_grid(NPAD * KX), 256>>>(p_atomWt, atom_W, KX, 0, KX, ATOM_FDIM, HIDDEN, 0);
    repackTH<<<rep_grid(NPAD * KH), 256>>>(p_WiTopT, Wi, KH, 0, KH, HIDDEN, HIDDEN, 0);
    repackTH<<<rep_grid(NPAD * KH), 256>>>(p_WoT, Wo, KWO, 0,  KH, HIDDEN, HIDDEN, 0);
    repackTH<<<rep_grid(NPAD * KH), 256>>>(p_WoT, Wo, KWO, KH, KH, HIDDEN, HIDDEN, HIDDEN);
    repackTH<<<rep_grid(NPAD * KH), 256>>>(p_ffn1T, ffn1_W, KH, 0, KH, HIDDEN, HIDDEN, 0);
    repackF<<<rep_grid(KE * NPAD), 256>>>(p_WiBot, Wi, KE, NPAD, BOND_FDIM, HIDDEN, HIDDEN);
    repackF<<<rep_grid(NPAD), 256>>>(p_atomB, atom_b, 1, NPAD, 1, HIDDEN, 0);
    repackF<<<rep_grid(NPAD), 256>>>(p_WoB, Wo_b, 1, NPAD, 1, HIDDEN, 0);
    repackF<<<rep_grid(NPAD), 256>>>(p_ffn1B, ffn1_b, 1, NPAD, 1, HIDDEN, 0);

    // ---- CSR build + ea permute + mol boundaries ----
    zeroI<<<rep_grid(N_ATOMS_PAD), 256>>>(p_counts, N_ATOMS_PAD);
    hist_dst<<<rep_grid(N_EDGES), 256>>>(e_dst, p_counts);
    scan_counts<<<1, 1024>>>(p_counts, p_rowptr);
    copy_cursor<<<rep_grid(N_ATOMS), 256>>>(p_rowptr, p_cursor);
    fill_csr<<<rep_grid(N_EDGES), 256>>>(e_src, e_dst, p_cursor, p_esrc, p_eid);
    permute_ea<<<rep_grid(N_EDGES * 16), 256>>>(ea, p_eid, p_eacsr);
    build_molptr<<<rep_grid(N_ATOMS), 256>>>(batch, p_molptr);

    // h_v = relu(x @ atom_W + atom_b)
    gemm_fp16<<<gAtom, 128>>>(p_xpad, KX, KX, p_xpad, KX,
                              p_atomWt, KX, p_atomB, p_hv, N_ATOMS, 1);

    // ---- depths 0..2 ----
    __half* cur = p_hv;
    __half* nxt = p_hv2;
    for (int d = 0; d < 3; d++) {
        // P = h_v @ Wi_top  (zero bias)
        gemm_fp16<<<gAtom, 128>>>(cur, NPAD, KH, cur, NPAD,
                                  p_WiTopT, KH, p_zeroB, p_P, N_ATOMS, 0);
        // agg[v] = sum over in-edges of relu(P[src] + edge_attr @ WiBot)
        gather_agg<<<gather_blocks, 256>>>(p_P, p_eacsr, p_WiBot, p_rowptr, p_esrc, p_agg);
        // h_v = relu([h_v, agg] @ Wo + Wo_b)
        gemm_fp16<<<gAtom, 128>>>(cur, NPAD, KH, p_agg, NPAD,
                                  p_WoT, KWO, p_WoB, nxt, N_ATOMS, 1);
        __half* t = cur; cur = nxt; nxt = t;
    }

    // mol_repr = segment_sum(h_v, batch)
    mol_sum<<<(N_MOLS * 32 + 255) / 256, 256>>>(cur, p_molptr, p_mol);
    // ffn = relu(mol @ ffn1 + b1)
    gemm_fp16<<<gMol, 128>>>(p_mol, NPAD, KH, p_mol, NPAD,
                             p_ffn1T, KH, p_ffn1B, p_ffn, N_MOLS, 1);
    // out = ffn @ ffn2 + b2
    finalk<<<(N_MOLS * 32 + 255) / 256, 256>>>(p_ffn, ffn2_W, ffn2_b, out);
}

// round 14
// speedup vs baseline: 1.6533x; 1.0022x over previous
#include <cuda_runtime.h>
#include <cuda_fp16.h>
#include <cstdint>

#define N_ATOMS 100000
#define N_ATOMS_PAD 102400   // multiple of 4096 for the scan
#define N_EDGES 400000
#define N_MOLS  4096
#define ATOM_FDIM 133
#define BOND_FDIM 14
#define HIDDEN 300
#define N_LABELS 12
#define NPAD 320        // padded hidden width
#define KX 144          // padded atom feature dim (multiple of 16)
#define KE 16
#define KH 304          // padded hidden as K-dim (multiple of 16)
#define KWO 608         // concat K for Wo GEMM

#define BM 64
#define BN 320
#define BK 16
#define LDR 24          // SMEM row stride in halves (48B): 12r mod 32 distinct over 8 rows

// ------------------------- scratch (static, no allocs) -------------------------
__device__ __half g_xpad[(size_t)N_ATOMS * KX];
__device__ __half g_hv  [(size_t)N_ATOMS * NPAD];
__device__ __half g_hv2 [(size_t)N_ATOMS * NPAD];
__device__ __half g_P   [(size_t)N_ATOMS * NPAD];
__device__ __half g_agg [(size_t)N_ATOMS * NPAD];
__device__ __half g_mol [(size_t)N_MOLS * NPAD];
__device__ __half g_ffn [(size_t)N_MOLS * NPAD];

// transposed fp16 weights: Wt[n][Kld] (k contiguous)
__device__ __half g_atomWt[NPAD * KX];
__device__ __half g_WiTopT[NPAD * KH];
__device__ __half g_WoT   [NPAD * KWO];
__device__ __half g_ffn1T [NPAD * KH];
__device__ float  g_WiBot [KE * NPAD];     // fp32, row-major [k][320] for gather
__device__ float  g_atomB[NPAD];
__device__ float  g_WoB  [NPAD];
__device__ float  g_ffn1B[NPAD];
__device__ float  g_zeroB[NPAD];           // statically zero — zero-bias GEMMs

// CSR scratch
__device__ int g_counts[N_ATOMS_PAD];
__device__ int g_rowptr[N_ATOMS_PAD + 1];
__device__ int g_cursor[N_ATOMS];
__device__ int g_esrc[N_EDGES];
__device__ int g_eid [N_EDGES];
__device__ int g_molptr[N_MOLS + 1];
__device__ float g_eacsr[(size_t)N_EDGES * 16];

// ------------------------- helpers -------------------------
__device__ __forceinline__ uint32_t smem_u32(const void* p) {
    return (uint32_t)__cvta_generic_to_shared(p);
}

// ------------------------- repack kernels -------------------------
__global__ void repackH(__half* __restrict__ dst, const float* __restrict__ src,
                        int dstR, int dstC, int srcR, int srcC, int srcRow0) {
    int idx = blockIdx.x * blockDim.x + threadIdx.x;
    if (idx >= dstR * dstC) return;
    int r = idx / dstC, c = idx - r * dstC;
    float v = 0.f;
    if (r < srcR && c < srcC) v = src[(size_t)(r + srcRow0) * srcC + c];
    dst[idx] = __float2half_rn(v);
}

__global__ void repackTH(__half* __restrict__ dst, const float* __restrict__ src,
                         int Kld, int kOff, int kCnt, int kValid, int srcC, int srcRow0) {
    int idx = blockIdx.x * blockDim.x + threadIdx.x;
    if (idx >= NPAD * kCnt) return;
    int n = idx / kCnt, k = idx - n * kCnt;
    float v = 0.f;
    if (k < kValid && n < srcC) v = src[(size_t)(k + srcRow0) * srcC + n];
    dst[(size_t)n * Kld + kOff + k] = __float2half_rn(v);
}

__global__ void repackF(float* __restrict__ dst, const float* __restrict__ src,
                        int dstR, int dstC, int srcR, int srcC, int srcRow0) {
    int idx = blockIdx.x * blockDim.x + threadIdx.x;
    if (idx >= dstR * dstC) return;
    int r = idx / dstC, c = idx - r * dstC;
    float v = 0.f;
    if (r < srcR && c < srcC) v = src[(size_t)(r + srcRow0) * srcC + c];
    dst[idx] = v;
}

__global__ void zeroI(int* __restrict__ p, int n) {
    int i = blockIdx.x * blockDim.x + threadIdx.x;
    if (i < n) p[i] = 0;
}

// ------------------------- CSR build -------------------------
__global__ void hist_dst(const int* __restrict__ dst, int* __restrict__ counts) {
    int e = blockIdx.x * blockDim.x + threadIdx.x;
    if (e < N_EDGES) atomicAdd(&counts[dst[e]], 1);
}

__global__ __launch_bounds__(1024)
void scan_counts(const int* __restrict__ counts, int* __restrict__ rowptr) {
    __shared__ int warp_sums[32];
    __shared__ int s_carry;
    const int tid = threadIdx.x;
    const int lane = tid & 31, wid = tid >> 5;
    if (tid == 0) s_carry = 0;
    __syncthreads();
    for (int base = 0; base < N_ATOMS_PAD; base += 4096) {
        int4 v = *(const int4*)(counts + base + tid * 4);
        int tsum = v.x + v.y + v.z + v.w;
        int val = tsum;
        #pragma unroll
        for (int off = 1; off < 32; off <<= 1) {
            int t = __shfl_up_sync(~0u, val, off);
            if (lane >= off) val += t;
        }
        if (lane == 31) warp_sums[wid] = val;
        __syncthreads();
        if (wid == 0) {
            int w = warp_sums[lane];
            #pragma unroll
            for (int off = 1; off < 32; off <<= 1) {
                int t = __shfl_up_sync(~0u, w, off);
                if (lane >= off) w += t;
            }
            warp_sums[lane] = w;
        }
        __syncthreads();
        int carry = s_carry;
        int excl = carry + (wid ? warp_sums[wid - 1] : 0) + (val - tsum);
        int idx = base + tid * 4;
        rowptr[idx + 0] = excl;
        rowptr[idx + 1] = excl + v.x;
        rowptr[idx + 2] = excl + v.x + v.y;
        rowptr[idx + 3] = excl + v.x + v.y + v.z;
        __syncthreads();
        if (tid == 0) s_carry = carry + warp_sums[31];
        __syncthreads();
    }
    if (threadIdx.x == 0) rowptr[N_ATOMS_PAD] = s_carry;
}

__global__ void copy_cursor(const int* __restrict__ rowptr, int* __restrict__ cursor) {
    int i = blockIdx.x * blockDim.x + threadIdx.x;
    if (i < N_ATOMS) cursor[i] = rowptr[i];
}

__global__ void fill_csr(const int* __restrict__ src, const int* __restrict__ dst,
                         int* __restrict__ cursor,
                         int* __restrict__ esrc, int* __restrict__ eid) {
    int e = blockIdx.x * blockDim.x + threadIdx.x;
    if (e >= N_EDGES) return;
    int d = dst[e];
    int pos = atomicAdd(&cursor[d], 1);
    esrc[pos] = src[e];
    eid[pos]  = e;
}

__global__ void permute_ea(const float* __restrict__ ea, const int* __restrict__ eid,
                           float* __restrict__ eacsr) {
    int idx = blockIdx.x * blockDim.x + threadIdx.x;
    if (idx >= N_EDGES * 16) return;
    int p = idx >> 4, c = idx & 15;
    float v = 0.f;
    if (c < BOND_FDIM) v = ea[(size_t)eid[p] * BOND_FDIM + c];
    eacsr[idx] = v;
}

__global__ void build_molptr(const int* __restrict__ batch, int* __restrict__ molptr) {
    int i = blockIdx.x * blockDim.x + threadIdx.x;
    if (i >= N_ATOMS) return;
    int b = batch[i];
    int bp = (i == 0) ? -1 : batch[i - 1];
    for (int m = bp + 1; m <= b; m++) molptr[m] = i;
    if (i == N_ATOMS - 1)
        for (int m = b + 1; m <= N_MOLS; m++) molptr[m] = N_ATOMS;
}

// ------------------------- fp16 tensor-core GEMM -------------------------
// C[M x 320](half) = half(relu?(A @ W + bias)), A = concat A1|A2 (half), W transposed Wt[n][Kld].
// Block tile 64x320 (FULL N in one CTA -> A staged once), BK=16, double-buffered,
// single sync per k-iter (sync -> stage(it+1) -> wait -> compute(it)).
// 256 thr: 8 warps 1(m)x8(n); warp tile 64x40; mma.m16n8k16.f16 via ldmatrix.
__global__ __launch_bounds__(256, 2)
void gemm_fp16(const __half* __restrict__ A1, int lda1, int K1,
               const __half* __restrict__ A2, int lda2,
               const __half* __restrict__ Wt, int Kld,
               const float* __restrict__ bias,
               __half* __restrict__ C, int M, int doRelu) {
    __shared__ __half As[2][BM][LDR];
    __shared__ __half Bs[2][BN][LDR];

    const int tid  = threadIdx.x;
    const int lane = tid & 31;
    const int wid  = tid >> 5;            // 0..7
    const int wn0  = wid * 40;            // 0..280
    const int row0 = blockIdx.x * BM;
    const int fr = lane >> 2;
    const int fc = lane & 3;
    const int niter = Kld >> 4;

    const int rA = ((lane >> 3) & 1) * 8 + (lane & 7);
    const int cA = (lane >> 4) * 8;
    const int rB = lane & 7;
    const int cB = ((lane >> 3) & 1) * 8;

    float acc[4][5][4];
    #pragma unroll
    for (int mt = 0; mt < 4; mt++)
        #pragma unroll
        for (int nt = 0; nt < 5; nt++)
            #pragma unroll
            for (int i = 0; i < 4; i++) acc[mt][nt][i] = 0.f;

    auto stage = [&](int k0, int buf) {
        const __half* Asrc; int lda, kb;
        if (k0 < K1) { Asrc = A1; lda = lda1; kb = k0; }
        else         { Asrc = A2; lda = lda2; kb = k0 - K1; }
        // A tile: 64 rows x 16 halves = 128 16B-chunks (threads 0-127)
        if (tid < 128) {
            int m = tid >> 1, part = tid & 1;
            int g = row0 + m;
            const __half* src = Asrc + (size_t)g * lda + kb + part * 8;
            uint32_t dst = smem_u32(&As[buf][m][part * 8]);
            int ss = (g < M) ? 16 : 0;
            asm volatile("cp.async.cg.shared.global [%0], [%1], 16, %2;"
                         :: "r"(dst), "l"(src), "r"(ss));
        }
        // B tile: 320 rows x 16 halves = 640 16B-chunks
        #pragma unroll
        for (int j = 0; j < 3; j++) {
            int c = tid + j * 256;
            if (c < 640) {
                int n = c >> 1, part = c & 1;
                const __half* src = Wt + (size_t)n * Kld + k0 + part * 8;
                uint32_t dst = smem_u32(&Bs[buf][n][part * 8]);
                asm volatile("cp.async.cg.shared.global [%0], [%1], 16;"
                             :: "r"(dst), "l"(src));
            }
        }
        asm volatile("cp.async.commit_group;");
    };

    stage(0, 0);

    for (int it = 0; it < niter; it++) {
        int buf = it & 1;
        __syncthreads();   // all warps done with compute(it-1); buffer buf^1 free
        if (it + 1 < niter) {
            stage(it * BK + BK, buf ^ 1);
            asm volatile("cp.async.wait_group 1;");   // tile `it` resident
        } else {
            asm volatile("cp.async.wait_group 0;");
        }
        __syncthreads();   // staging visibility for ldmatrix across warps

        uint32_t a[4][4], b[5][2];
        #pragma unroll
        for (int mt = 0; mt < 4; mt++) {
            uint32_t addr = smem_u32(&As[buf][mt * 16 + rA][cA]);
            asm volatile("ldmatrix.sync.aligned.m8n8.x4.shared.b16 {%0,%1,%2,%3}, [%4];"
                         : "=r"(a[mt][0]), "=r"(a[mt][1]), "=r"(a[mt][2]), "=r"(a[mt][3])
                         : "r"(addr));
        }
        #pragma unroll
        for (int nt = 0; nt < 5; nt++) {
            uint32_t addr = smem_u32(&Bs[buf][wn0 + nt * 8 + rB][cB]);
            asm volatile("ldmatrix.sync.aligned.m8n8.x2.shared.b16 {%0,%1}, [%2];"
                         : "=r"(b[nt][0]), "=r"(b[nt][1]) : "r"(addr));
        }
        #pragma unroll
        for (int mt = 0; mt < 4; mt++)
            #pragma unroll
            for (int nt = 0; nt < 5; nt++)
                asm volatile(
                    "mma.sync.aligned.m16n8k16.row.col.f32.f16.f16.f32 "
                    "{%0,%1,%2,%3}, {%4,%5,%6,%7}, {%8,%9}, {%0,%1,%2,%3};"
                    : "+f"(acc[mt][nt][0]), "+f"(acc[mt][nt][1]),
                      "+f"(acc[mt][nt][2]), "+f"(acc[mt][nt][3])
                    : "r"(a[mt][0]), "r"(a[mt][1]), "r"(a[mt][2]), "r"(a[mt][3]),
                      "r"(b[nt][0]), "r"(b[nt][1]));
    }

    // epilogue: bias + relu? + fp16 round
    #pragma unroll
    for (int mt = 0; mt < 4; mt++) {
        int r = row0 + mt * 16 + fr;
        #pragma unroll
        for (int nt = 0; nt < 5; nt++) {
            int cbase = wn0 + nt * 8 + (fc << 1);
            float2 bv = *(const float2*)&bias[cbase];
            if (r < M) {
                float vx = acc[mt][nt][0] + bv.x, vy = acc[mt][nt][1] + bv.y;
                if (doRelu) { vx = fmaxf(vx, 0.f); vy = fmaxf(vy, 0.f); }
                *(__half2*)(C + (size_t)r * NPAD + cbase) = __floats2half2_rn(vx, vy);
            }
            if (r + 8 < M) {
                float vx = acc[mt][nt][2] + bv.x, vy = acc[mt][nt][3] + bv.y;
                if (doRelu) { vx = fmaxf(vx, 0.f); vy = fmaxf(vy, 0.f); }
                *(__half2*)(C + (size_t)(r + 8) * NPAD + cbase) = __floats2half2_rn(vx, vy);
            }
        }
    }
}

// ------------------------- CSR gather: agg[v] = sum_in relu(P[src] + eacsr[p] @ WiBot) -----
__global__ __launch_bounds__(256)
void gather_agg(const __half* __restrict__ P, const float* __restrict__ eacsr,
                const float* __restrict__ WiBot,
                const int* __restrict__ rowptr, const int* __restrict__ esrc,
                __half* __restrict__ agg) {
    __shared__ float Ws[14 * NPAD];
    for (int i = threadIdx.x; i < 14 * NPAD; i += 256) Ws[i] = WiBot[i];
    __syncthreads();

    int v = (blockIdx.x * 256 + threadIdx.x) >> 5;
    int lane = threadIdx.x & 31;
    if (v >= N_ATOMS) return;
    int beg = rowptr[v], end = rowptr[v + 1];

    float2 acc2[5];
    #pragma unroll
    for (int j = 0; j < 5; j++) acc2[j] = make_float2(0.f, 0.f);

    const float2* Ws2 = (const float2*)Ws;

    int p = beg;
    for (; p + 2 <= end; p += 2) {
        int s0 = esrc[p], s1 = esrc[p + 1];
        float eav0 = (lane < 16) ? eacsr[(size_t)p * 16 + lane] : 0.f;
        float eav1 = (lane < 16) ? eacsr[(size_t)(p + 1) * 16 + lane] : 0.f;
        const __half2* Pr0 = (const __half2*)(P + (size_t)s0 * NPAD);
        const __half2* Pr1 = (const __half2*)(P + (size_t)s1 * NPAD);
        float ef0[14], ef1[14];
        #pragma unroll
        for (int f = 0; f < 14; f++) {
            ef0[f] = __shfl_sync(~0u, eav0, f);
            ef1[f] = __shfl_sync(~0u, eav1, f);
        }
        #pragma unroll
        for (int j = 0; j < 5; j++) {
            int idx = lane + 32 * j;
            float2 m0 = __half22float2(Pr0[idx]);
            float2 m1 = __half22float2(Pr1[idx]);
            #pragma unroll
            for (int f = 0; f < 14; f++) {
                float2 w = Ws2[f * 160 + idx];
                m0.x = fmaf(ef0[f], w.x, m0.x);
                m0.y = fmaf(ef0[f], w.y, m0.y);
                m1.x = fmaf(ef1[f], w.x, m1.x);
                m1.y = fmaf(ef1[f], w.y, m1.y);
            }
            acc2[j].x += fmaxf(m0.x, 0.f) + fmaxf(m1.x, 0.f);
            acc2[j].y += fmaxf(m0.y, 0.f) + fmaxf(m1.y, 0.f);
        }
    }
    for (; p < end; p++) {
        int s = esrc[p];
        float eav = (lane < 16) ? eacsr[(size_t)p * 16 + lane] : 0.f;
        float ef[14];
        #pragma unroll
        for (int f = 0; f < 14; f++) ef[f] = __shfl_sync(~0u, eav, f);
        const __half2* Pr = (const __half2*)(P + (size_t)s * NPAD);
        #pragma unroll
        for (int j = 0; j < 5; j++) {
            int idx = lane + 32 * j;
            float2 m2 = __half22float2(Pr[idx]);
            #pragma unroll
            for (int f = 0; f < 14; f++) {
                float2 w = Ws2[f * 160 + idx];
                m2.x = fmaf(ef[f], w.x, m2.x);
                m2.y = fmaf(ef[f], w.y, m2.y);
            }
            acc2[j].x += fmaxf(m2.x, 0.f);
            acc2[j].y += fmaxf(m2.y, 0.f);
        }
    }
    __half2* ag = (__half2*)(agg + (size_t)v * NPAD);
    #pragma unroll
    for (int j = 0; j < 5; j++) ag[lane + 32 * j] = __floats2half2_rn(acc2[j].x, acc2[j].y);
}

// ------------------------- molecule pooling -------------------------
__global__ void mol_sum(const __half* __restrict__ hv, const int* __restrict__ molptr,
                        __half* __restrict__ mol) {
    int m = (blockIdx.x * blockDim.x + threadIdx.x) >> 5;
    int lane = threadIdx.x & 31;
    if (m >= N_MOLS) return;
    int beg = molptr[m], end = molptr[m + 1];
    float2 acc2[5];
    #pragma unroll
    for (int j = 0; j < 5; j++) acc2[j] = make_float2(0.f, 0.f);
    for (int a = beg; a < end; a++) {
        const __half2* hr = (const __half2*)(hv + (size_t)a * NPAD);
        #pragma unroll
        for (int j = 0; j < 5; j++) {
            float2 t = __half22float2(hr[lane + 32 * j]);
            acc2[j].x += t.x; acc2[j].y += t.y;
        }
    }
    __half2* mr = (__half2*)(mol + (size_t)m * NPAD);
    #pragma unroll
    for (int j = 0; j < 5; j++) mr[lane + 32 * j] = __floats2half2_rn(acc2[j].x, acc2[j].y);
}

// ------------------------- final: out = ffn @ ffn2 + b2 -------------------------
__global__ void finalk(const __half* __restrict__ F, const float* __restrict__ W2,
                       const float* __restrict__ b2, float* __restrict__ out) {
    int w = (blockIdx.x * blockDim.x + threadIdx.x) >> 5;
    int lane = threadIdx.x & 31;
    if (w >= N_MOLS) return;
    float acc = (lane < 12) ? b2[lane] : 0.f;
    const __half* f = F + (size_t)w * NPAD;
    for (int j = 0; j < HIDDEN; j++) {
        float fv = __half2float(f[j]);
        if (lane < 12) acc = fmaf(fv, W2[j * 12 + lane], acc);
    }
    if (lane < 12) out[w * 12 + lane] = acc;
}

// ------------------------- host launch -------------------------
static inline dim3 rep_grid(int n) { return dim3((n + 255) / 256); }

extern "C" void kernel_launch(void* const* d_in, const int* in_sizes, int n_in,
                              void* d_out, int out_size) {
    const float* x      = (const float*)d_in[0];
    const int*   ei     = (const int*)  d_in[1];
    const float* ea     = (const float*)d_in[2];
    const int*   batch  = (const int*)  d_in[3];
    const float* atom_W = (const float*)d_in[4];
    const float* atom_b = (const float*)d_in[5];
    // d_in[6], d_in[7]: bond_W / bond_b  -> dead code
    const float* Wi     = (const float*)d_in[8];
    // d_in[9]: Wh -> dead code
    const float* Wo     = (const float*)d_in[10];
    const float* Wo_b   = (const float*)d_in[11];
    const float* ffn1_W = (const float*)d_in[12];
    const float* ffn1_b = (const float*)d_in[13];
    const float* ffn2_W = (const float*)d_in[14];
    const float* ffn2_b = (const float*)d_in[15];
    float* out = (float*)d_out;

    __half *p_xpad, *p_hv, *p_hv2, *p_P, *p_agg, *p_mol, *p_ffn;
    __half *p_atomWt, *p_WiTopT, *p_WoT, *p_ffn1T;
    float *p_WiBot, *p_atomB, *p_WoB, *p_ffn1B, *p_zeroB, *p_eacsr;
    int *p_counts, *p_rowptr, *p_cursor, *p_esrc, *p_eid, *p_molptr;
    cudaGetSymbolAddress((void**)&p_xpad,  g_xpad);
    cudaGetSymbolAddress((void**)&p_hv,    g_hv);
    cudaGetSymbolAddress((void**)&p_hv2,   g_hv2);
    cudaGetSymbolAddress((void**)&p_P,     g_P);
    cudaGetSymbolAddress((void**)&p_agg,   g_agg);
    cudaGetSymbolAddress((void**)&p_mol,   g_mol);
    cudaGetSymbolAddress((void**)&p_ffn,   g_ffn);
    cudaGetSymbolAddress((void**)&p_atomWt, g_atomWt);
    cudaGetSymbolAddress((void**)&p_WiTopT, g_WiTopT);
    cudaGetSymbolAddress((void**)&p_WoT,    g_WoT);
    cudaGetSymbolAddress((void**)&p_ffn1T,  g_ffn1T);
    cudaGetSymbolAddress((void**)&p_WiBot,  g_WiBot);
    cudaGetSymbolAddress((void**)&p_atomB, g_atomB);
    cudaGetSymbolAddress((void**)&p_WoB,   g_WoB);
    cudaGetSymbolAddress((void**)&p_ffn1B, g_ffn1B);
    cudaGetSymbolAddress((void**)&p_zeroB, g_zeroB);
    cudaGetSymbolAddress((void**)&p_eacsr, g_eacsr);
    cudaGetSymbolAddress((void**)&p_counts, g_counts);
    cudaGetSymbolAddress((void**)&p_rowptr, g_rowptr);
    cudaGetSymbolAddress((void**)&p_cursor, g_cursor);
    cudaGetSymbolAddress((void**)&p_esrc,   g_esrc);
    cudaGetSymbolAddress((void**)&p_eid,    g_eid);
    cudaGetSymbolAddress((void**)&p_molptr, g_molptr);

    const int* e_src = ei;
    const int* e_dst = ei + N_EDGES;

    dim3 gAtom((N_ATOMS + BM - 1) / BM);   // full N=320 per CTA
    dim3 gMol ((N_MOLS  + BM - 1) / BM);
    int gather_blocks = (N_ATOMS * 32 + 255) / 256;

    // ---- repacks ----
    repackH<<<rep_grid(N_ATOMS * KX), 256>>>(p_xpad, x, N_ATOMS, KX, N_ATOMS, ATOM_FDIM, 0);
    repackTH<<<rep_grid(NPAD * KX), 256>>>(p_atomWt, atom_W, KX, 0, KX, ATOM_FDIM, HIDDEN, 0);
    repackTH<<<rep_grid(NPAD * KH), 256>>>(p_WiTopT, Wi, KH, 0, KH, HIDDEN, HIDDEN, 0);
    repackTH<<<rep_grid(NPAD * KH), 256>>>(p_WoT, Wo, KWO, 0,  KH, HIDDEN, HIDDEN, 0);
    repackTH<<<rep_grid(NPAD * KH), 256>>>(p_WoT, Wo, KWO, KH, KH, HIDDEN, HIDDEN, HIDDEN);
    repackTH<<<rep_grid(NPAD * KH), 256>>>(p_ffn1T, ffn1_W, KH, 0, KH, HIDDEN, HIDDEN, 0);
    repackF<<<rep_grid(KE * NPAD), 256>>>(p_WiBot, Wi, KE, NPAD, BOND_FDIM, HIDDEN, HIDDEN);
    repackF<<<rep_grid(NPAD), 256>>>(p_atomB, atom_b, 1, NPAD, 1, HIDDEN, 0);
    repackF<<<rep_grid(NPAD), 256>>>(p_WoB, Wo_b, 1, NPAD, 1, HIDDEN, 0);
    repackF<<<rep_grid(NPAD), 256>>>(p_ffn1B, ffn1_b, 1, NPAD, 1, HIDDEN, 0);

    // ---- CSR build + ea permute + mol boundaries ----
    zeroI<<<rep_grid(N_ATOMS_PAD), 256>>>(p_counts, N_ATOMS_PAD);
    hist_dst<<<rep_grid(N_EDGES), 256>>>(e_dst, p_counts);
    scan_counts<<<1, 1024>>>(p_counts, p_rowptr);
    copy_cursor<<<rep_grid(N_ATOMS), 256>>>(p_rowptr, p_cursor);
    fill_csr<<<rep_grid(N_EDGES), 256>>>(e_src, e_dst, p_cursor, p_esrc, p_eid);
    permute_ea<<<rep_grid(N_EDGES * 16), 256>>>(ea, p_eid, p_eacsr);
    build_molptr<<<rep_grid(N_ATOMS), 256>>>(batch, p_molptr);

    // h_v = relu(x @ atom_W + atom_b)
    gemm_fp16<<<gAtom, 256>>>(p_xpad, KX, KX, p_xpad, KX,
                              p_atomWt, KX, p_atomB, p_hv, N_ATOMS, 1);

    // ---- depths 0..2 ----
    __half* cur = p_hv;
    __half* nxt = p_hv2;
    for (int d = 0; d < 3; d++) {
        // P = h_v @ Wi_top  (zero bias)
        gemm_fp16<<<gAtom, 256>>>(cur, NPAD, KH, cur, NPAD,
                                  p_WiTopT, KH, p_zeroB, p_P, N_ATOMS, 0);
        // agg[v] = sum over in-edges of relu(P[src] + edge_attr @ WiBot)
        gather_agg<<<gather_blocks, 256>>>(p_P, p_eacsr, p_WiBot, p_rowptr, p_esrc, p_agg);
        // h_v = relu([h_v, agg] @ Wo + Wo_b)
        gemm_fp16<<<gAtom, 256>>>(cur, NPAD, KH, p_agg, NPAD,
                                  p_WoT, KWO, p_WoB, nxt, N_ATOMS, 1);
        __half* t = cur; cur = nxt; nxt = t;
    }

    // mol_repr = segment_sum(h_v, batch)
    mol_sum<<<(N_MOLS * 32 + 255) / 256, 256>>>(cur, p_molptr, p_mol);
    // ffn = relu(mol @ ffn1 + b1)
    gemm_fp16<<<gMol, 256>>>(p_mol, NPAD, KH, p_mol, NPAD,
                             p_ffn1T, KH, p_ffn1B, p_ffn, N_MOLS, 1);
    // out = ffn @ ffn2 + b2
    finalk<<<(N_MOLS * 32 + 255) / 256, 256>>>(p_ffn, ffn2_W, ffn2_b, out);
}

// round 15
// speedup vs baseline: 1.6850x; 1.0191x over previous
#include <cuda_runtime.h>
#include <cuda_fp16.h>
#include <cstdint>

#define N_ATOMS 100000
#define N_ATOMS_PAD 102400   // multiple of 4096 for the scan
#define N_EDGES 400000
#define N_MOLS  4096
#define ATOM_FDIM 133
#define BOND_FDIM 14
#define HIDDEN 300
#define N_LABELS 12
#define NPAD 320        // padded hidden width
#define KX 144          // padded atom feature dim (multiple of 16)
#define KE 16
#define KH 304          // padded hidden as K-dim (multiple of 16)
#define KWO 608         // concat K for Wo GEMM

#define BM 64
#define BN 320
#define BK 16
#define LDR 24          // SMEM row stride in halves (48B): 12r mod 32 distinct over 8 rows
#define GSMEM_BYTES (3 * (BM + BN) * LDR * 2)   // 55296

// ------------------------- scratch (static, no allocs) -------------------------
__device__ __half g_xpad[(size_t)N_ATOMS * KX];
__device__ __half g_hv  [(size_t)N_ATOMS * NPAD];
__device__ __half g_hv2 [(size_t)N_ATOMS * NPAD];
__device__ __half g_P   [(size_t)N_ATOMS * NPAD];
__device__ __half g_agg [(size_t)N_ATOMS * NPAD];
__device__ __half g_mol [(size_t)N_MOLS * NPAD];
__device__ __half g_ffn [(size_t)N_MOLS * NPAD];

// transposed fp16 weights: Wt[n][Kld] (k contiguous)
__device__ __half g_atomWt[NPAD * KX];
__device__ __half g_WiTopT[NPAD * KH];
__device__ __half g_WoT   [NPAD * KWO];
__device__ __half g_ffn1T [NPAD * KH];
__device__ float  g_WiBot [KE * NPAD];     // fp32, row-major [k][320] for gather
__device__ float  g_atomB[NPAD];
__device__ float  g_WoB  [NPAD];
__device__ float  g_ffn1B[NPAD];
__device__ float  g_zeroB[NPAD];           // statically zero — zero-bias GEMMs

// CSR scratch
__device__ int g_counts[N_ATOMS_PAD];
__device__ int g_rowptr[N_ATOMS_PAD + 1];
__device__ int g_cursor[N_ATOMS];
__device__ int g_esrc[N_EDGES];
__device__ int g_eid [N_EDGES];
__device__ int g_molptr[N_MOLS + 1];
__device__ float g_eacsr[(size_t)N_EDGES * 16];

// ------------------------- helpers -------------------------
__device__ __forceinline__ uint32_t smem_u32(const void* p) {
    return (uint32_t)__cvta_generic_to_shared(p);
}

// ------------------------- repack kernels -------------------------
__global__ void repackH(__half* __restrict__ dst, const float* __restrict__ src,
                        int dstR, int dstC, int srcR, int srcC, int srcRow0) {
    int idx = blockIdx.x * blockDim.x + threadIdx.x;
    if (idx >= dstR * dstC) return;
    int r = idx / dstC, c = idx - r * dstC;
    float v = 0.f;
    if (r < srcR && c < srcC) v = src[(size_t)(r + srcRow0) * srcC + c];
    dst[idx] = __float2half_rn(v);
}

__global__ void repackTH(__half* __restrict__ dst, const float* __restrict__ src,
                         int Kld, int kOff, int kCnt, int kValid, int srcC, int srcRow0) {
    int idx = blockIdx.x * blockDim.x + threadIdx.x;
    if (idx >= NPAD * kCnt) return;
    int n = idx / kCnt, k = idx - n * kCnt;
    float v = 0.f;
    if (k < kValid && n < srcC) v = src[(size_t)(k + srcRow0) * srcC + n];
    dst[(size_t)n * Kld + kOff + k] = __float2half_rn(v);
}

__global__ void repackF(float* __restrict__ dst, const float* __restrict__ src,
                        int dstR, int dstC, int srcR, int srcC, int srcRow0) {
    int idx = blockIdx.x * blockDim.x + threadIdx.x;
    if (idx >= dstR * dstC) return;
    int r = idx / dstC, c = idx - r * dstC;
    float v = 0.f;
    if (r < srcR && c < srcC) v = src[(size_t)(r + srcRow0) * srcC + c];
    dst[idx] = v;
}

__global__ void zeroI(int* __restrict__ p, int n) {
    int i = blockIdx.x * blockDim.x + threadIdx.x;
    if (i < n) p[i] = 0;
}

// ------------------------- CSR build -------------------------
__global__ void hist_dst(const int* __restrict__ dst, int* __restrict__ counts) {
    int e = blockIdx.x * blockDim.x + threadIdx.x;
    if (e < N_EDGES) atomicAdd(&counts[dst[e]], 1);
}

__global__ __launch_bounds__(1024)
void scan_counts(const int* __restrict__ counts, int* __restrict__ rowptr) {
    __shared__ int warp_sums[32];
    __shared__ int s_carry;
    const int tid = threadIdx.x;
    const int lane = tid & 31, wid = tid >> 5;
    if (tid == 0) s_carry = 0;
    __syncthreads();
    for (int base = 0; base < N_ATOMS_PAD; base += 4096) {
        int4 v = *(const int4*)(counts + base + tid * 4);
        int tsum = v.x + v.y + v.z + v.w;
        int val = tsum;
        #pragma unroll
        for (int off = 1; off < 32; off <<= 1) {
            int t = __shfl_up_sync(~0u, val, off);
            if (lane >= off) val += t;
        }
        if (lane == 31) warp_sums[wid] = val;
        __syncthreads();
        if (wid == 0) {
            int w = warp_sums[lane];
            #pragma unroll
            for (int off = 1; off < 32; off <<= 1) {
                int t = __shfl_up_sync(~0u, w, off);
                if (lane >= off) w += t;
            }
            warp_sums[lane] = w;
        }
        __syncthreads();
        int carry = s_carry;
        int excl = carry + (wid ? warp_sums[wid - 1] : 0) + (val - tsum);
        int idx = base + tid * 4;
        rowptr[idx + 0] = excl;
        rowptr[idx + 1] = excl + v.x;
        rowptr[idx + 2] = excl + v.x + v.y;
        rowptr[idx + 3] = excl + v.x + v.y + v.z;
        __syncthreads();
        if (tid == 0) s_carry = carry + warp_sums[31];
        __syncthreads();
    }
    if (threadIdx.x == 0) rowptr[N_ATOMS_PAD] = s_carry;
}

__global__ void copy_cursor(const int* __restrict__ rowptr, int* __restrict__ cursor) {
    int i = blockIdx.x * blockDim.x + threadIdx.x;
    if (i < N_ATOMS) cursor[i] = rowptr[i];
}

__global__ void fill_csr(const int* __restrict__ src, const int* __restrict__ dst,
                         int* __restrict__ cursor,
                         int* __restrict__ esrc, int* __restrict__ eid) {
    int e = blockIdx.x * blockDim.x + threadIdx.x;
    if (e >= N_EDGES) return;
    int d = dst[e];
    int pos = atomicAdd(&cursor[d], 1);
    esrc[pos] = src[e];
    eid[pos]  = e;
}

__global__ void permute_ea(const float* __restrict__ ea, const int* __restrict__ eid,
                           float* __restrict__ eacsr) {
    int idx = blockIdx.x * blockDim.x + threadIdx.x;
    if (idx >= N_EDGES * 16) return;
    int p = idx >> 4, c = idx & 15;
    float v = 0.f;
    if (c < BOND_FDIM) v = ea[(size_t)eid[p] * BOND_FDIM + c];
    eacsr[idx] = v;
}

__global__ void build_molptr(const int* __restrict__ batch, int* __restrict__ molptr) {
    int i = blockIdx.x * blockDim.x + threadIdx.x;
    if (i >= N_ATOMS) return;
    int b = batch[i];
    int bp = (i == 0) ? -1 : batch[i - 1];
    for (int m = bp + 1; m <= b; m++) molptr[m] = i;
    if (i == N_ATOMS - 1)
        for (int m = b + 1; m <= N_MOLS; m++) molptr[m] = N_ATOMS;
}

// ------------------------- fp16 tensor-core GEMM -------------------------
// C[M x 320](half) = half(relu?(A @ W + bias)), A = concat A1|A2 (half), W transposed Wt[n][Kld].
// Block tile 64x320 (full N), BK=16, TRIPLE-buffered dynamic SMEM (prefetch depth 2),
// one sync per k-iter. 256 thr: 8 warps 1(m)x8(n); warp tile 64x40; mma.m16n8k16 via ldmatrix.
__global__ __launch_bounds__(256, 2)
void gemm_fp16(const __half* __restrict__ A1, int lda1, int K1,
               const __half* __restrict__ A2, int lda2,
               const __half* __restrict__ Wt, int Kld,
               const float* __restrict__ bias,
               __half* __restrict__ C, int M, int doRelu) {
    extern __shared__ __half dsm[];
    __half (*As)[BM][LDR] = (__half(*)[BM][LDR])dsm;                     // 3 x 64 x 24
    __half (*Bs)[BN][LDR] = (__half(*)[BN][LDR])(dsm + 3 * BM * LDR);    // 3 x 320 x 24

    const int tid  = threadIdx.x;
    const int lane = tid & 31;
    const int wid  = tid >> 5;            // 0..7
    const int wn0  = wid * 40;            // 0..280
    const int row0 = blockIdx.x * BM;
    const int fr = lane >> 2;
    const int fc = lane & 3;
    const int niter = Kld >> 4;

    const int rA = ((lane >> 3) & 1) * 8 + (lane & 7);
    const int cA = (lane >> 4) * 8;
    const int rB = lane & 7;
    const int cB = ((lane >> 3) & 1) * 8;

    float acc[4][5][4];
    #pragma unroll
    for (int mt = 0; mt < 4; mt++)
        #pragma unroll
        for (int nt = 0; nt < 5; nt++)
            #pragma unroll
            for (int i = 0; i < 4; i++) acc[mt][nt][i] = 0.f;

    auto stage = [&](int k0, int buf) {
        const __half* Asrc; int lda, kb;
        if (k0 < K1) { Asrc = A1; lda = lda1; kb = k0; }
        else         { Asrc = A2; lda = lda2; kb = k0 - K1; }
        // A tile: 64 rows x 16 halves = 128 16B-chunks (threads 0-127)
        if (tid < 128) {
            int m = tid >> 1, part = tid & 1;
            int g = row0 + m;
            const __half* src = Asrc + (size_t)g * lda + kb + part * 8;
            uint32_t dst = smem_u32(&As[buf][m][part * 8]);
            int ss = (g < M) ? 16 : 0;
            asm volatile("cp.async.cg.shared.global [%0], [%1], 16, %2;"
                         :: "r"(dst), "l"(src), "r"(ss));
        }
        // B tile: 320 rows x 16 halves = 640 16B-chunks
        #pragma unroll
        for (int j = 0; j < 3; j++) {
            int c = tid + j * 256;
            if (c < 640) {
                int n = c >> 1, part = c & 1;
                const __half* src = Wt + (size_t)n * Kld + k0 + part * 8;
                uint32_t dst = smem_u32(&Bs[buf][n][part * 8]);
                asm volatile("cp.async.cg.shared.global [%0], [%1], 16;"
                             :: "r"(dst), "l"(src));
            }
        }
        asm volatile("cp.async.commit_group;");
    };

    stage(0, 0);
    if (niter > 1) stage(BK, 1);

    for (int it = 0; it < niter; it++) {
        int buf = it % 3;
        if (it + 1 < niter) asm volatile("cp.async.wait_group 1;");
        else                asm volatile("cp.async.wait_group 0;");
        __syncthreads();   // all warps done with compute(it-1); buffer (it+2)%3 free
        if (it + 2 < niter) stage((it + 2) * BK, (it + 2) % 3);

        uint32_t a[4][4], b[5][2];
        #pragma unroll
        for (int mt = 0; mt < 4; mt++) {
            uint32_t addr = smem_u32(&As[buf][mt * 16 + rA][cA]);
            asm volatile("ldmatrix.sync.aligned.m8n8.x4.shared.b16 {%0,%1,%2,%3}, [%4];"
                         : "=r"(a[mt][0]), "=r"(a[mt][1]), "=r"(a[mt][2]), "=r"(a[mt][3])
                         : "r"(addr));
        }
        #pragma unroll
        for (int nt = 0; nt < 5; nt++) {
            uint32_t addr = smem_u32(&Bs[buf][wn0 + nt * 8 + rB][cB]);
            asm volatile("ldmatrix.sync.aligned.m8n8.x2.shared.b16 {%0,%1}, [%2];"
                         : "=r"(b[nt][0]), "=r"(b[nt][1]) : "r"(addr));
        }
        #pragma unroll
        for (int mt = 0; mt < 4; mt++)
            #pragma unroll
            for (int nt = 0; nt < 5; nt++)
                asm volatile(
                    "mma.sync.aligned.m16n8k16.row.col.f32.f16.f16.f32 "
                    "{%0,%1,%2,%3}, {%4,%5,%6,%7}, {%8,%9}, {%0,%1,%2,%3};"
                    : "+f"(acc[mt][nt][0]), "+f"(acc[mt][nt][1]),
                      "+f"(acc[mt][nt][2]), "+f"(acc[mt][nt][3])
                    : "r"(a[mt][0]), "r"(a[mt][1]), "r"(a[mt][2]), "r"(a[mt][3]),
                      "r"(b[nt][0]), "r"(b[nt][1]));
    }

    // epilogue: bias + relu? + fp16 round
    #pragma unroll
    for (int mt = 0; mt < 4; mt++) {
        int r = row0 + mt * 16 + fr;
        #pragma unroll
        for (int nt = 0; nt < 5; nt++) {
            int cbase = wn0 + nt * 8 + (fc << 1);
            float2 bv = *(const float2*)&bias[cbase];
            if (r < M) {
                float vx = acc[mt][nt][0] + bv.x, vy = acc[mt][nt][1] + bv.y;
                if (doRelu) { vx = fmaxf(vx, 0.f); vy = fmaxf(vy, 0.f); }
                *(__half2*)(C + (size_t)r * NPAD + cbase) = __floats2half2_rn(vx, vy);
            }
            if (r + 8 < M) {
                float vx = acc[mt][nt][2] + bv.x, vy = acc[mt][nt][3] + bv.y;
                if (doRelu) { vx = fmaxf(vx, 0.f); vy = fmaxf(vy, 0.f); }
                *(__half2*)(C + (size_t)(r + 8) * NPAD + cbase) = __floats2half2_rn(vx, vy);
            }
        }
    }
}

// ------------------------- CSR gather: agg[v] = sum_in relu(P[src] + eacsr[p] @ WiBot) -----
__global__ __launch_bounds__(256)
void gather_agg(const __half* __restrict__ P, const float* __restrict__ eacsr,
                const float* __restrict__ WiBot,
                const int* __restrict__ rowptr, const int* __restrict__ esrc,
                __half* __restrict__ agg) {
    __shared__ float Ws[14 * NPAD];
    for (int i = threadIdx.x; i < 14 * NPAD; i += 256) Ws[i] = WiBot[i];
    __syncthreads();

    int v = (blockIdx.x * 256 + threadIdx.x) >> 5;
    int lane = threadIdx.x & 31;
    if (v >= N_ATOMS) return;
    int beg = rowptr[v], end = rowptr[v + 1];

    float2 acc2[5];
    #pragma unroll
    for (int j = 0; j < 5; j++) acc2[j] = make_float2(0.f, 0.f);

    const float2* Ws2 = (const float2*)Ws;

    int p = beg;
    for (; p + 2 <= end; p += 2) {
        int s0 = esrc[p], s1 = esrc[p + 1];
        float eav0 = (lane < 16) ? eacsr[(size_t)p * 16 + lane] : 0.f;
        float eav1 = (lane < 16) ? eacsr[(size_t)(p + 1) * 16 + lane] : 0.f;
        const __half2* Pr0 = (const __half2*)(P + (size_t)s0 * NPAD);
        const __half2* Pr1 = (const __half2*)(P + (size_t)s1 * NPAD);
        float ef0[14], ef1[14];
        #pragma unroll
        for (int f = 0; f < 14; f++) {
            ef0[f] = __shfl_sync(~0u, eav0, f);
            ef1[f] = __shfl_sync(~0u, eav1, f);
        }
        #pragma unroll
        for (int j = 0; j < 5; j++) {
            int idx = lane + 32 * j;
            float2 m0 = __half22float2(Pr0[idx]);
            float2 m1 = __half22float2(Pr1[idx]);
            #pragma unroll
            for (int f = 0; f < 14; f++) {
                float2 w = Ws2[f * 160 + idx];
                m0.x = fmaf(ef0[f], w.x, m0.x);
                m0.y = fmaf(ef0[f], w.y, m0.y);
                m1.x = fmaf(ef1[f], w.x, m1.x);
                m1.y = fmaf(ef1[f], w.y, m1.y);
            }
            acc2[j].x += fmaxf(m0.x, 0.f) + fmaxf(m1.x, 0.f);
            acc2[j].y += fmaxf(m0.y, 0.f) + fmaxf(m1.y, 0.f);
        }
    }
    for (; p < end; p++) {
        int s = esrc[p];
        float eav = (lane < 16) ? eacsr[(size_t)p * 16 + lane] : 0.f;
        float ef[14];
        #pragma unroll
        for (int f = 0; f < 14; f++) ef[f] = __shfl_sync(~0u, eav, f);
        const __half2* Pr = (const __half2*)(P + (size_t)s * NPAD);
        #pragma unroll
        for (int j = 0; j < 5; j++) {
            int idx = lane + 32 * j;
            float2 m2 = __half22float2(Pr[idx]);
            #pragma unroll
            for (int f = 0; f < 14; f++) {
                float2 w = Ws2[f * 160 + idx];
                m2.x = fmaf(ef[f], w.x, m2.x);
                m2.y = fmaf(ef[f], w.y, m2.y);
            }
            acc2[j].x += fmaxf(m2.x, 0.f);
            acc2[j].y += fmaxf(m2.y, 0.f);
        }
    }
    __half2* ag = (__half2*)(agg + (size_t)v * NPAD);
    #pragma unroll
    for (int j = 0; j < 5; j++) ag[lane + 32 * j] = __floats2half2_rn(acc2[j].x, acc2[j].y);
}

// ------------------------- molecule pooling -------------------------
__global__ void mol_sum(const __half* __restrict__ hv, const int* __restrict__ molptr,
                        __half* __restrict__ mol) {
    int m = (blockIdx.x * blockDim.x + threadIdx.x) >> 5;
    int lane = threadIdx.x & 31;
    if (m >= N_MOLS) return;
    int beg = molptr[m], end = molptr[m + 1];
    float2 acc2[5];
    #pragma unroll
    for (int j = 0; j < 5; j++) acc2[j] = make_float2(0.f, 0.f);
    for (int a = beg; a < end; a++) {
        const __half2* hr = (const __half2*)(hv + (size_t)a * NPAD);
        #pragma unroll
        for (int j = 0; j < 5; j++) {
            float2 t = __half22float2(hr[lane + 32 * j]);
            acc2[j].x += t.x; acc2[j].y += t.y;
        }
    }
    __half2* mr = (__half2*)(mol + (size_t)m * NPAD);
    #pragma unroll
    for (int j = 0; j < 5; j++) mr[lane + 32 * j] = __floats2half2_rn(acc2[j].x, acc2[j].y);
}

// ------------------------- final: out = ffn @ ffn2 + b2 -------------------------
__global__ void finalk(const __half* __restrict__ F, const float* __restrict__ W2,
                       const float* __restrict__ b2, float* __restrict__ out) {
    int w = (blockIdx.x * blockDim.x + threadIdx.x) >> 5;
    int lane = threadIdx.x & 31;
    if (w >= N_MOLS) return;
    float acc = (lane < 12) ? b2[lane] : 0.f;
    const __half* f = F + (size_t)w * NPAD;
    for (int j = 0; j < HIDDEN; j++) {
        float fv = __half2float(f[j]);
        if (lane < 12) acc = fmaf(fv, W2[j * 12 + lane], acc);
    }
    if (lane < 12) out[w * 12 + lane] = acc;
}

// ------------------------- host launch -------------------------
static inline dim3 rep_grid(int n) { return dim3((n + 255) / 256); }

extern "C" void kernel_launch(void* const* d_in, const int* in_sizes, int n_in,
                              void* d_out, int out_size) {
    const float* x      = (const float*)d_in[0];
    const int*   ei     = (const int*)  d_in[1];
    const float* ea     = (const float*)d_in[2];
    const int*   batch  = (const int*)  d_in[3];
    const float* atom_W = (const float*)d_in[4];
    const float* atom_b = (const float*)d_in[5];
    // d_in[6], d_in[7]: bond_W / bond_b  -> dead code
    const float* Wi     = (const float*)d_in[8];
    // d_in[9]: Wh -> dead code
    const float* Wo     = (const float*)d_in[10];
    const float* Wo_b   = (const float*)d_in[11];
    const float* ffn1_W = (const float*)d_in[12];
    const float* ffn1_b = (const float*)d_in[13];
    const float* ffn2_W = (const float*)d_in[14];
    const float* ffn2_b = (const float*)d_in[15];
    float* out = (float*)d_out;

    __half *p_xpad, *p_hv, *p_hv2, *p_P, *p_agg, *p_mol, *p_ffn;
    __half *p_atomWt, *p_WiTopT, *p_WoT, *p_ffn1T;
    float *p_WiBot, *p_atomB, *p_WoB, *p_ffn1B, *p_zeroB, *p_eacsr;
    int *p_counts, *p_rowptr, *p_cursor, *p_esrc, *p_eid, *p_molptr;
    cudaGetSymbolAddress((void**)&p_xpad,  g_xpad);
    cudaGetSymbolAddress((void**)&p_hv,    g_hv);
    cudaGetSymbolAddress((void**)&p_hv2,   g_hv2);
    cudaGetSymbolAddress((void**)&p_P,     g_P);
    cudaGetSymbolAddress((void**)&p_agg,   g_agg);
    cudaGetSymbolAddress((void**)&p_mol,   g_mol);
    cudaGetSymbolAddress((void**)&p_ffn,   g_ffn);
    cudaGetSymbolAddress((void**)&p_atomWt, g_atomWt);
    cudaGetSymbolAddress((void**)&p_WiTopT, g_WiTopT);
    cudaGetSymbolAddress((void**)&p_WoT,    g_WoT);
    cudaGetSymbolAddress((void**)&p_ffn1T,  g_ffn1T);
    cudaGetSymbolAddress((void**)&p_WiBot,  g_WiBot);
    cudaGetSymbolAddress((void**)&p_atomB, g_atomB);
    cudaGetSymbolAddress((void**)&p_WoB,   g_WoB);
    cudaGetSymbolAddress((void**)&p_ffn1B, g_ffn1B);
    cudaGetSymbolAddress((void**)&p_zeroB, g_zeroB);
    cudaGetSymbolAddress((void**)&p_eacsr, g_eacsr);
    cudaGetSymbolAddress((void**)&p_counts, g_counts);
    cudaGetSymbolAddress((void**)&p_rowptr, g_rowptr);
    cudaGetSymbolAddress((void**)&p_cursor, g_cursor);
    cudaGetSymbolAddress((void**)&p_esrc,   g_esrc);
    cudaGetSymbolAddress((void**)&p_eid,    g_eid);
    cudaGetSymbolAddress((void**)&p_molptr, g_molptr);

    cudaFuncSetAttribute(gemm_fp16, cudaFuncAttributeMaxDynamicSharedMemorySize, GSMEM_BYTES);

    const int* e_src = ei;
    const int* e_dst = ei + N_EDGES;

    dim3 gAtom((N_ATOMS + BM - 1) / BM);   // full N=320 per CTA
    dim3 gMol ((N_MOLS  + BM - 1) / BM);
    int gather_blocks = (N_ATOMS * 32 + 255) / 256;

    // ---- prologue ordered so the atom GEMM is my 4th launch (ncu capture target) ----
    repackH<<<rep_grid(N_ATOMS * KX), 256>>>(p_xpad, x, N_ATOMS, KX, N_ATOMS, ATOM_FDIM, 0);  // 1
    repackTH<<<rep_grid(NPAD * KX), 256>>>(p_atomWt, atom_W, KX, 0, KX, ATOM_FDIM, HIDDEN, 0); // 2
    repackF<<<rep_grid(NPAD), 256>>>(p_atomB, atom_b, 1, NPAD, 1, HIDDEN, 0);                  // 3
    // h_v = relu(x @ atom_W + atom_b)                                                         // 4
    gemm_fp16<<<gAtom, 256, GSMEM_BYTES>>>(p_xpad, KX, KX, p_xpad, KX,
                                           p_atomWt, KX, p_atomB, p_hv, N_ATOMS, 1);

    // ---- remaining repacks ----
    repackTH<<<rep_grid(NPAD * KH), 256>>>(p_WiTopT, Wi, KH, 0, KH, HIDDEN, HIDDEN, 0);
    repackTH<<<rep_grid(NPAD * KH), 256>>>(p_WoT, Wo, KWO, 0,  KH, HIDDEN, HIDDEN, 0);
    repackTH<<<rep_grid(NPAD * KH), 256>>>(p_WoT, Wo, KWO, KH, KH, HIDDEN, HIDDEN, HIDDEN);
    repackTH<<<rep_grid(NPAD * KH), 256>>>(p_ffn1T, ffn1_W, KH, 0, KH, HIDDEN, HIDDEN, 0);
    repackF<<<rep_grid(KE * NPAD), 256>>>(p_WiBot, Wi, KE, NPAD, BOND_FDIM, HIDDEN, HIDDEN);
    repackF<<<rep_grid(NPAD), 256>>>(p_WoB, Wo_b, 1, NPAD, 1, HIDDEN, 0);
    repackF<<<rep_grid(NPAD), 256>>>(p_ffn1B, ffn1_b, 1, NPAD, 1, HIDDEN, 0);

    // ---- CSR build + ea permute + mol boundaries ----
    zeroI<<<rep_grid(N_ATOMS_PAD), 256>>>(p_counts, N_ATOMS_PAD);
    hist_dst<<<rep_grid(N_EDGES), 256>>>(e_dst, p_counts);
    scan_counts<<<1, 1024>>>(p_counts, p_rowptr);
    copy_cursor<<<rep_grid(N_ATOMS), 256>>>(p_rowptr, p_cursor);
    fill_csr<<<rep_grid(N_EDGES), 256>>>(e_src, e_dst, p_cursor, p_esrc, p_eid);
    permute_ea<<<rep_grid(N_EDGES * 16), 256>>>(ea, p_eid, p_eacsr);
    build_molptr<<<rep_grid(N_ATOMS), 256>>>(batch, p_molptr);

    // ---- depths 0..2 ----
    __half* cur = p_hv;
    __half* nxt = p_hv2;
    for (int d = 0; d < 3; d++) {
        // P = h_v @ Wi_top  (zero bias)
        gemm_fp16<<<gAtom, 256, GSMEM_BYTES>>>(cur, NPAD, KH, cur, NPAD,
                                               p_WiTopT, KH, p_zeroB, p_P, N_ATOMS, 0);
        // agg[v] = sum over in-edges of relu(P[src] + edge_attr @ WiBot)
        gather_agg<<<gather_blocks, 256>>>(p_P, p_eacsr, p_WiBot, p_rowptr, p_esrc, p_agg);
        // h_v = relu([h_v, agg] @ Wo + Wo_b)
        gemm_fp16<<<gAtom, 256, GSMEM_BYTES>>>(cur, NPAD, KH, p_agg, NPAD,
                                               p_WoT, KWO, p_WoB, nxt, N_ATOMS, 1);
        __half* t = cur; cur = nxt; nxt = t;
    }

    // mol_repr = segment_sum(h_v, batch)
    mol_sum<<<(N_MOLS * 32 + 255) / 256, 256>>>(cur, p_molptr, p_mol);
    // ffn = relu(mol @ ffn1 + b1)
    gemm_fp16<<<gMol, 256, GSMEM_BYTES>>>(p_mol, NPAD, KH, p_mol, NPAD,
                                          p_ffn1T, KH, p_ffn1B, p_ffn, N_MOLS, 1);
    // out = ffn @ ffn2 + b2
    finalk<<<(N_MOLS * 32 + 255) / 256, 256>>>(p_ffn, ffn2_W, ffn2_b, out);
}

// round 16
// speedup vs baseline: 1.8111x; 1.0749x over previous
#include <cuda_runtime.h>
#include <cuda_fp16.h>
#include <cstdint>

#define N_ATOMS 100000
#define N_ATOMS_PAD 102400   // multiple of 4096 for the scan
#define N_EDGES 400000
#define N_MOLS  4096
#define ATOM_FDIM 133
#define BOND_FDIM 14
#define HIDDEN 300
#define N_LABELS 12
#define NPAD 320        // padded hidden width
#define KX 160          // padded atom feature dim (multiple of 32)
#define KE 16
#define KH 320          // padded hidden as K-dim (multiple of 32)
#define KWO 640         // concat K for Wo GEMM

#define BM 64
#define BN 320
#define BK 32
#define LDR 40          // SMEM row stride in halves (80B): 20r mod 32 distinct over 8 rows
#define GSMEM_BYTES (3 * (BM + BN) * LDR * 2)   // 92160

// ------------------------- scratch (static, no allocs) -------------------------
__device__ __half g_xpad[(size_t)N_ATOMS * KX];
__device__ __half g_hv  [(size_t)N_ATOMS * NPAD];
__device__ __half g_hv2 [(size_t)N_ATOMS * NPAD];
__device__ __half g_P   [(size_t)N_ATOMS * NPAD];
__device__ __half g_agg [(size_t)N_ATOMS * NPAD];
__device__ __half g_mol [(size_t)N_MOLS * NPAD];
__device__ __half g_ffn [(size_t)N_MOLS * NPAD];

// transposed fp16 weights: Wt[n][Kld] (k contiguous)
__device__ __half g_atomWt[NPAD * KX];
__device__ __half g_WiTopT[NPAD * KH];
__device__ __half g_WoT   [NPAD * KWO];
__device__ __half g_ffn1T [NPAD * KH];
__device__ float  g_WiBot [KE * NPAD];     // fp32, row-major [k][320] for gather
__device__ float  g_atomB[NPAD];
__device__ float  g_WoB  [NPAD];
__device__ float  g_ffn1B[NPAD];
__device__ float  g_zeroB[NPAD];           // statically zero — zero-bias GEMMs

// CSR scratch
__device__ int g_counts[N_ATOMS_PAD];
__device__ int g_rowptr[N_ATOMS_PAD + 1];
__device__ int g_cursor[N_ATOMS];
__device__ int g_esrc[N_EDGES];
__device__ int g_eid [N_EDGES];
__device__ int g_molptr[N_MOLS + 1];
__device__ float g_eacsr[(size_t)N_EDGES * 16];

// ------------------------- helpers -------------------------
__device__ __forceinline__ uint32_t smem_u32(const void* p) {
    return (uint32_t)__cvta_generic_to_shared(p);
}

// ------------------------- repack kernels -------------------------
__global__ void repackH(__half* __restrict__ dst, const float* __restrict__ src,
                        int dstR, int dstC, int srcR, int srcC, int srcRow0) {
    int idx = blockIdx.x * blockDim.x + threadIdx.x;
    if (idx >= dstR * dstC) return;
    int r = idx / dstC, c = idx - r * dstC;
    float v = 0.f;
    if (r < srcR && c < srcC) v = src[(size_t)(r + srcRow0) * srcC + c];
    dst[idx] = __float2half_rn(v);
}

__global__ void repackTH(__half* __restrict__ dst, const float* __restrict__ src,
                         int Kld, int kOff, int kCnt, int kValid, int srcC, int srcRow0) {
    int idx = blockIdx.x * blockDim.x + threadIdx.x;
    if (idx >= NPAD * kCnt) return;
    int n = idx / kCnt, k = idx - n * kCnt;
    float v = 0.f;
    if (k < kValid && n < srcC) v = src[(size_t)(k + srcRow0) * srcC + n];
    dst[(size_t)n * Kld + kOff + k] = __float2half_rn(v);
}

__global__ void repackF(float* __restrict__ dst, const float* __restrict__ src,
                        int dstR, int dstC, int srcR, int srcC, int srcRow0) {
    int idx = blockIdx.x * blockDim.x + threadIdx.x;
    if (idx >= dstR * dstC) return;
    int r = idx / dstC, c = idx - r * dstC;
    float v = 0.f;
    if (r < srcR && c < srcC) v = src[(size_t)(r + srcRow0) * srcC + c];
    dst[idx] = v;
}

__global__ void zeroI(int* __restrict__ p, int n) {
    int i = blockIdx.x * blockDim.x + threadIdx.x;
    if (i < n) p[i] = 0;
}

// ------------------------- CSR build -------------------------
__global__ void hist_dst(const int* __restrict__ dst, int* __restrict__ counts) {
    int e = blockIdx.x * blockDim.x + threadIdx.x;
    if (e < N_EDGES) atomicAdd(&counts[dst[e]], 1);
}

__global__ __launch_bounds__(1024)
void scan_counts(const int* __restrict__ counts, int* __restrict__ rowptr) {
    __shared__ int warp_sums[32];
    __shared__ int s_carry;
    const int tid = threadIdx.x;
    const int lane = tid & 31, wid = tid >> 5;
    if (tid == 0) s_carry = 0;
    __syncthreads();
    for (int base = 0; base < N_ATOMS_PAD; base += 4096) {
        int4 v = *(const int4*)(counts + base + tid * 4);
        int tsum = v.x + v.y + v.z + v.w;
        int val = tsum;
        #pragma unroll
        for (int off = 1; off < 32; off <<= 1) {
            int t = __shfl_up_sync(~0u, val, off);
            if (lane >= off) val += t;
        }
        if (lane == 31) warp_sums[wid] = val;
        __syncthreads();
        if (wid == 0) {
            int w = warp_sums[lane];
            #pragma unroll
            for (int off = 1; off < 32; off <<= 1) {
                int t = __shfl_up_sync(~0u, w, off);
                if (lane >= off) w += t;
            }
            warp_sums[lane] = w;
        }
        __syncthreads();
        int carry = s_carry;
        int excl = carry + (wid ? warp_sums[wid - 1] : 0) + (val - tsum);
        int idx = base + tid * 4;
        rowptr[idx + 0] = excl;
        rowptr[idx + 1] = excl + v.x;
        rowptr[idx + 2] = excl + v.x + v.y;
        rowptr[idx + 3] = excl + v.x + v.y + v.z;
        __syncthreads();
        if (tid == 0) s_carry = carry + warp_sums[31];
        __syncthreads();
    }
    if (threadIdx.x == 0) rowptr[N_ATOMS_PAD] = s_carry;
}

__global__ void copy_cursor(const int* __restrict__ rowptr, int* __restrict__ cursor) {
    int i = blockIdx.x * blockDim.x + threadIdx.x;
    if (i < N_ATOMS) cursor[i] = rowptr[i];
}

__global__ void fill_csr(const int* __restrict__ src, const int* __restrict__ dst,
                         int* __restrict__ cursor,
                         int* __restrict__ esrc, int* __restrict__ eid) {
    int e = blockIdx.x * blockDim.x + threadIdx.x;
    if (e >= N_EDGES) return;
    int d = dst[e];
    int pos = atomicAdd(&cursor[d], 1);
    esrc[pos] = src[e];
    eid[pos]  = e;
}

__global__ void permute_ea(const float* __restrict__ ea, const int* __restrict__ eid,
                           float* __restrict__ eacsr) {
    int idx = blockIdx.x * blockDim.x + threadIdx.x;
    if (idx >= N_EDGES * 16) return;
    int p = idx >> 4, c = idx & 15;
    float v = 0.f;
    if (c < BOND_FDIM) v = ea[(size_t)eid[p] * BOND_FDIM + c];
    eacsr[idx] = v;
}

__global__ void build_molptr(const int* __restrict__ batch, int* __restrict__ molptr) {
    int i = blockIdx.x * blockDim.x + threadIdx.x;
    if (i >= N_ATOMS) return;
    int b = batch[i];
    int bp = (i == 0) ? -1 : batch[i - 1];
    for (int m = bp + 1; m <= b; m++) molptr[m] = i;
    if (i == N_ATOMS - 1)
        for (int m = b + 1; m <= N_MOLS; m++) molptr[m] = N_ATOMS;
}

// ------------------------- fp16 tensor-core GEMM -------------------------
// C[M x 320](half) = half(relu?(A @ W + bias)), A = concat A1|A2 (half), W transposed Wt[n][Kld].
// Block tile 64x320 (full N), BK=32 (2 k16 steps per iter -> half the syncs),
// TRIPLE-buffered dynamic SMEM (prefetch depth 2), one sync per k-iter.
// 256 thr: 8 warps 1(m)x8(n); warp tile 64x40; mma.m16n8k16 via ldmatrix.
__global__ __launch_bounds__(256, 2)
void gemm_fp16(const __half* __restrict__ A1, int lda1, int K1,
               const __half* __restrict__ A2, int lda2,
               const __half* __restrict__ Wt, int Kld,
               const float* __restrict__ bias,
               __half* __restrict__ C, int M, int doRelu) {
    extern __shared__ __half dsm[];
    __half (*As)[BM][LDR] = (__half(*)[BM][LDR])dsm;                     // 3 x 64 x 40
    __half (*Bs)[BN][LDR] = (__half(*)[BN][LDR])(dsm + 3 * BM * LDR);    // 3 x 320 x 40

    const int tid  = threadIdx.x;
    const int lane = tid & 31;
    const int wid  = tid >> 5;            // 0..7
    const int wn0  = wid * 40;            // 0..280
    const int row0 = blockIdx.x * BM;
    const int fr = lane >> 2;
    const int fc = lane & 3;
    const int niter = Kld >> 5;

    const int rA = ((lane >> 3) & 1) * 8 + (lane & 7);
    const int cA = (lane >> 4) * 8;
    const int rB = lane & 7;
    const int cB = ((lane >> 3) & 1) * 8;

    float acc[4][5][4];
    #pragma unroll
    for (int mt = 0; mt < 4; mt++)
        #pragma unroll
        for (int nt = 0; nt < 5; nt++)
            #pragma unroll
            for (int i = 0; i < 4; i++) acc[mt][nt][i] = 0.f;

    auto stage = [&](int k0, int buf) {
        const __half* Asrc; int lda, kb;
        if (k0 < K1) { Asrc = A1; lda = lda1; kb = k0; }
        else         { Asrc = A2; lda = lda2; kb = k0 - K1; }
        // A tile: 64 rows x 32 halves = 256 16B-chunks, 1 per thread
        {
            int m = tid >> 2, part = tid & 3;
            int g = row0 + m;
            const __half* src = Asrc + (size_t)g * lda + kb + part * 8;
            uint32_t dst = smem_u32(&As[buf][m][part * 8]);
            int ss = (g < M) ? 16 : 0;
            asm volatile("cp.async.cg.shared.global [%0], [%1], 16, %2;"
                         :: "r"(dst), "l"(src), "r"(ss));
        }
        // B tile: 320 rows x 32 halves = 1280 16B-chunks, 5 per thread
        #pragma unroll
        for (int j = 0; j < 5; j++) {
            int c = tid + j * 256;
            int n = c >> 2, part = c & 3;
            const __half* src = Wt + (size_t)n * Kld + k0 + part * 8;
            uint32_t dst = smem_u32(&Bs[buf][n][part * 8]);
            asm volatile("cp.async.cg.shared.global [%0], [%1], 16;"
                         :: "r"(dst), "l"(src));
        }
        asm volatile("cp.async.commit_group;");
    };

    stage(0, 0);
    if (niter > 1) stage(BK, 1);

    for (int it = 0; it < niter; it++) {
        int buf = it % 3;
        if (it + 1 < niter) asm volatile("cp.async.wait_group 1;");
        else                asm volatile("cp.async.wait_group 0;");
        __syncthreads();   // all warps done with compute(it-1); buffer (it+2)%3 free
        if (it + 2 < niter) stage((it + 2) * BK, (it + 2) % 3);

        #pragma unroll
        for (int ks = 0; ks < 2; ks++) {
            const int kk = ks * 16;
            uint32_t a[4][4], b[5][2];
            #pragma unroll
            for (int mt = 0; mt < 4; mt++) {
                uint32_t addr = smem_u32(&As[buf][mt * 16 + rA][kk + cA]);
                asm volatile("ldmatrix.sync.aligned.m8n8.x4.shared.b16 {%0,%1,%2,%3}, [%4];"
                             : "=r"(a[mt][0]), "=r"(a[mt][1]), "=r"(a[mt][2]), "=r"(a[mt][3])
                             : "r"(addr));
            }
            #pragma unroll
            for (int nt = 0; nt < 5; nt++) {
                uint32_t addr = smem_u32(&Bs[buf][wn0 + nt * 8 + rB][kk + cB]);
                asm volatile("ldmatrix.sync.aligned.m8n8.x2.shared.b16 {%0,%1}, [%2];"
                             : "=r"(b[nt][0]), "=r"(b[nt][1]) : "r"(addr));
            }
            #pragma unroll
            for (int mt = 0; mt < 4; mt++)
                #pragma unroll
                for (int nt = 0; nt < 5; nt++)
                    asm volatile(
                        "mma.sync.aligned.m16n8k16.row.col.f32.f16.f16.f32 "
                        "{%0,%1,%2,%3}, {%4,%5,%6,%7}, {%8,%9}, {%0,%1,%2,%3};"
                        : "+f"(acc[mt][nt][0]), "+f"(acc[mt][nt][1]),
                          "+f"(acc[mt][nt][2]), "+f"(acc[mt][nt][3])
                        : "r"(a[mt][0]), "r"(a[mt][1]), "r"(a[mt][2]), "r"(a[mt][3]),
                          "r"(b[nt][0]), "r"(b[nt][1]));
        }
    }

    // epilogue: bias + relu? + fp16 round
    #pragma unroll
    for (int mt = 0; mt < 4; mt++) {
        int r = row0 + mt * 16 + fr;
        #pragma unroll
        for (int nt = 0; nt < 5; nt++) {
            int cbase = wn0 + nt * 8 + (fc << 1);
            float2 bv = *(const float2*)&bias[cbase];
            if (r < M) {
                float vx = acc[mt][nt][0] + bv.x, vy = acc[mt][nt][1] + bv.y;
                if (doRelu) { vx = fmaxf(vx, 0.f); vy = fmaxf(vy, 0.f); }
                *(__half2*)(C + (size_t)r * NPAD + cbase) = __floats2half2_rn(vx, vy);
            }
            if (r + 8 < M) {
                float vx = acc[mt][nt][2] + bv.x, vy = acc[mt][nt][3] + bv.y;
                if (doRelu) { vx = fmaxf(vx, 0.f); vy = fmaxf(vy, 0.f); }
                *(__half2*)(C + (size_t)(r + 8) * NPAD + cbase) = __floats2half2_rn(vx, vy);
            }
        }
    }
}

// ------------------------- CSR gather: agg[v] = sum_in relu(P[src] + eacsr[p] @ WiBot) -----
__global__ __launch_bounds__(256)
void gather_agg(const __half* __restrict__ P, const float* __restrict__ eacsr,
                const float* __restrict__ WiBot,
                const int* __restrict__ rowptr, const int* __restrict__ esrc,
                __half* __restrict__ agg) {
    __shared__ float Ws[14 * NPAD];
    for (int i = threadIdx.x; i < 14 * NPAD; i += 256) Ws[i] = WiBot[i];
    __syncthreads();

    int v = (blockIdx.x * 256 + threadIdx.x) >> 5;
    int lane = threadIdx.x & 31;
    if (v >= N_ATOMS) return;
    int beg = rowptr[v], end = rowptr[v + 1];

    float2 acc2[5];
    #pragma unroll
    for (int j = 0; j < 5; j++) acc2[j] = make_float2(0.f, 0.f);

    const float2* Ws2 = (const float2*)Ws;

    int p = beg;
    for (; p + 2 <= end; p += 2) {
        int s0 = esrc[p], s1 = esrc[p + 1];
        float eav0 = (lane < 16) ? eacsr[(size_t)p * 16 + lane] : 0.f;
        float eav1 = (lane < 16) ? eacsr[(size_t)(p + 1) * 16 + lane] : 0.f;
        const __half2* Pr0 = (const __half2*)(P + (size_t)s0 * NPAD);
        const __half2* Pr1 = (const __half2*)(P + (size_t)s1 * NPAD);
        float ef0[14], ef1[14];
        #pragma unroll
        for (int f = 0; f < 14; f++) {
            ef0[f] = __shfl_sync(~0u, eav0, f);
            ef1[f] = __shfl_sync(~0u, eav1, f);
        }
        #pragma unroll
        for (int j = 0; j < 5; j++) {
            int idx = lane + 32 * j;
            float2 m0 = __half22float2(Pr0[idx]);
            float2 m1 = __half22float2(Pr1[idx]);
            #pragma unroll
            for (int f = 0; f < 14; f++) {
                float2 w = Ws2[f * 160 + idx];
                m0.x = fmaf(ef0[f], w.x, m0.x);
                m0.y = fmaf(ef0[f], w.y, m0.y);
                m1.x = fmaf(ef1[f], w.x, m1.x);
                m1.y = fmaf(ef1[f], w.y, m1.y);
            }
            acc2[j].x += fmaxf(m0.x, 0.f) + fmaxf(m1.x, 0.f);
            acc2[j].y += fmaxf(m0.y, 0.f) + fmaxf(m1.y, 0.f);
        }
    }
    for (; p < end; p++) {
        int s = esrc[p];
        float eav = (lane < 16) ? eacsr[(size_t)p * 16 + lane] : 0.f;
        float ef[14];
        #pragma unroll
        for (int f = 0; f < 14; f++) ef[f] = __shfl_sync(~0u, eav, f);
        const __half2* Pr = (const __half2*)(P + (size_t)s * NPAD);
        #pragma unroll
        for (int j = 0; j < 5; j++) {
            int idx = lane + 32 * j;
            float2 m2 = __half22float2(Pr[idx]);
            #pragma unroll
            for (int f = 0; f < 14; f++) {
                float2 w = Ws2[f * 160 + idx];
                m2.x = fmaf(ef[f], w.x, m2.x);
                m2.y = fmaf(ef[f], w.y, m2.y);
            }
            acc2[j].x += fmaxf(m2.x, 0.f);
            acc2[j].y += fmaxf(m2.y, 0.f);
        }
    }
    __half2* ag = (__half2*)(agg + (size_t)v * NPAD);
    #pragma unroll
    for (int j = 0; j < 5; j++) ag[lane + 32 * j] = __floats2half2_rn(acc2[j].x, acc2[j].y);
}

// ------------------------- molecule pooling -------------------------
__global__ void mol_sum(const __half* __restrict__ hv, const int* __restrict__ molptr,
                        __half* __restrict__ mol) {
    int m = (blockIdx.x * blockDim.x + threadIdx.x) >> 5;
    int lane = threadIdx.x & 31;
    if (m >= N_MOLS) return;
    int beg = molptr[m], end = molptr[m + 1];
    float2 acc2[5];
    #pragma unroll
    for (int j = 0; j < 5; j++) acc2[j] = make_float2(0.f, 0.f);
    for (int a = beg; a < end; a++) {
        const __half2* hr = (const __half2*)(hv + (size_t)a * NPAD);
        #pragma unroll
        for (int j = 0; j < 5; j++) {
            float2 t = __half22float2(hr[lane + 32 * j]);
            acc2[j].x += t.x; acc2[j].y += t.y;
        }
    }
    __half2* mr = (__half2*)(mol + (size_t)m * NPAD);
    #pragma unroll
    for (int j = 0; j < 5; j++) mr[lane + 32 * j] = __floats2half2_rn(acc2[j].x, acc2[j].y);
}

// ------------------------- final: out = ffn @ ffn2 + b2 -------------------------
__global__ void finalk(const __half* __restrict__ F, const float* __restrict__ W2,
                       const float* __restrict__ b2, float* __restrict__ out) {
    int w = (blockIdx.x * blockDim.x + threadIdx.x) >> 5;
    int lane = threadIdx.x & 31;
    if (w >= N_MOLS) return;
    float acc = (lane < 12) ? b2[lane] : 0.f;
    const __half* f = F + (size_t)w * NPAD;
    for (int j = 0; j < HIDDEN; j++) {
        float fv = __half2float(f[j]);
        if (lane < 12) acc = fmaf(fv, W2[j * 12 + lane], acc);
    }
    if (lane < 12) out[w * 12 + lane] = acc;
}

// ------------------------- host launch -------------------------
static inline dim3 rep_grid(int n) { return dim3((n + 255) / 256); }

extern "C" void kernel_launch(void* const* d_in, const int* in_sizes, int n_in,
                              void* d_out, int out_size) {
    const float* x      = (const float*)d_in[0];
    const int*   ei     = (const int*)  d_in[1];
    const float* ea     = (const float*)d_in[2];
    const int*   batch  = (const int*)  d_in[3];
    const float* atom_W = (const float*)d_in[4];
    const float* atom_b = (const float*)d_in[5];
    // d_in[6], d_in[7]: bond_W / bond_b  -> dead code
    const float* Wi     = (const float*)d_in[8];
    // d_in[9]: Wh -> dead code
    const float* Wo     = (const float*)d_in[10];
    const float* Wo_b   = (const float*)d_in[11];
    const float* ffn1_W = (const float*)d_in[12];
    const float* ffn1_b = (const float*)d_in[13];
    const float* ffn2_W = (const float*)d_in[14];
    const float* ffn2_b = (const float*)d_in[15];
    float* out = (float*)d_out;

    __half *p_xpad, *p_hv, *p_hv2, *p_P, *p_agg, *p_mol, *p_ffn;
    __half *p_atomWt, *p_WiTopT, *p_WoT, *p_ffn1T;
    float *p_WiBot, *p_atomB, *p_WoB, *p_ffn1B, *p_zeroB, *p_eacsr;
    int *p_counts, *p_rowptr, *p_cursor, *p_esrc, *p_eid, *p_molptr;
    cudaGetSymbolAddress((void**)&p_xpad,  g_xpad);
    cudaGetSymbolAddress((void**)&p_hv,    g_hv);
    cudaGetSymbolAddress((void**)&p_hv2,   g_hv2);
    cudaGetSymbolAddress((void**)&p_P,     g_P);
    cudaGetSymbolAddress((void**)&p_agg,   g_agg);
    cudaGetSymbolAddress((void**)&p_mol,   g_mol);
    cudaGetSymbolAddress((void**)&p_ffn,   g_ffn);
    cudaGetSymbolAddress((void**)&p_atomWt, g_atomWt);
    cudaGetSymbolAddress((void**)&p_WiTopT, g_WiTopT);
    cudaGetSymbolAddress((void**)&p_WoT,    g_WoT);
    cudaGetSymbolAddress((void**)&p_ffn1T,  g_ffn1T);
    cudaGetSymbolAddress((void**)&p_WiBot,  g_WiBot);
    cudaGetSymbolAddress((void**)&p_atomB, g_atomB);
    cudaGetSymbolAddress((void**)&p_WoB,   g_WoB);
    cudaGetSymbolAddress((void**)&p_ffn1B, g_ffn1B);
    cudaGetSymbolAddress((void**)&p_zeroB, g_zeroB);
    cudaGetSymbolAddress((void**)&p_eacsr, g_eacsr);
    cudaGetSymbolAddress((void**)&p_counts, g_counts);
    cudaGetSymbolAddress((void**)&p_rowptr, g_rowptr);
    cudaGetSymbolAddress((void**)&p_cursor, g_cursor);
    cudaGetSymbolAddress((void**)&p_esrc,   g_esrc);
    cudaGetSymbolAddress((void**)&p_eid,    g_eid);
    cudaGetSymbolAddress((void**)&p_molptr, g_molptr);

    cudaFuncSetAttribute(gemm_fp16, cudaFuncAttributeMaxDynamicSharedMemorySize, GSMEM_BYTES);

    const int* e_src = ei;
    const int* e_dst = ei + N_EDGES;

    dim3 gAtom((N_ATOMS + BM - 1) / BM);   // full N=320 per CTA
    dim3 gMol ((N_MOLS  + BM - 1) / BM);
    int gather_blocks = (N_ATOMS * 32 + 255) / 256;

    // ---- prologue ordered so the atom GEMM is my 4th launch (ncu capture target) ----
    repackH<<<rep_grid(N_ATOMS * KX), 256>>>(p_xpad, x, N_ATOMS, KX, N_ATOMS, ATOM_FDIM, 0);   // 1
    repackTH<<<rep_grid(NPAD * KX), 256>>>(p_atomWt, atom_W, KX, 0, KX, ATOM_FDIM, HIDDEN, 0); // 2
    repackF<<<rep_grid(NPAD), 256>>>(p_atomB, atom_b, 1, NPAD, 1, HIDDEN, 0);                  // 3
    // h_v = relu(x @ atom_W + atom_b)                                                         // 4
    gemm_fp16<<<gAtom, 256, GSMEM_BYTES>>>(p_xpad, KX, KX, p_xpad, KX,
                                           p_atomWt, KX, p_atomB, p_hv, N_ATOMS, 1);

    // ---- remaining repacks ----
    repackTH<<<rep_grid(NPAD * KH), 256>>>(p_WiTopT, Wi, KH, 0, KH, HIDDEN, HIDDEN, 0);
    repackTH<<<rep_grid(NPAD * KH), 256>>>(p_WoT, Wo, KWO, 0,  KH, HIDDEN, HIDDEN, 0);
    repackTH<<<rep_grid(NPAD * KH), 256>>>(p_WoT, Wo, KWO, KH, KH, HIDDEN, HIDDEN, HIDDEN);
    repackTH<<<rep_grid(NPAD * KH), 256>>>(p_ffn1T, ffn1_W, KH, 0, KH, HIDDEN, HIDDEN, 0);
    repackF<<<rep_grid(KE * NPAD), 256>>>(p_WiBot, Wi, KE, NPAD, BOND_FDIM, HIDDEN, HIDDEN);
    repackF<<<rep_grid(NPAD), 256>>>(p_WoB, Wo_b, 1, NPAD, 1, HIDDEN, 0);
    repackF<<<rep_grid(NPAD), 256>>>(p_ffn1B, ffn1_b, 1, NPAD, 1, HIDDEN, 0);

    // ---- CSR build + ea permute + mol boundaries ----
    zeroI<<<rep_grid(N_ATOMS_PAD), 256>>>(p_counts, N_ATOMS_PAD);
    hist_dst<<<rep_grid(N_EDGES), 256>>>(e_dst, p_counts);
    scan_counts<<<1, 1024>>>(p_counts, p_rowptr);
    copy_cursor<<<rep_grid(N_ATOMS), 256>>>(p_rowptr, p_cursor);
    fill_csr<<<rep_grid(N_EDGES), 256>>>(e_src, e_dst, p_cursor, p_esrc, p_eid);
    permute_ea<<<rep_grid(N_EDGES * 16), 256>>>(ea, p_eid, p_eacsr);
    build_molptr<<<rep_grid(N_ATOMS), 256>>>(batch, p_molptr);

    // ---- depths 0..2 ----
    __half* cur = p_hv;
    __half* nxt = p_hv2;
    for (int d = 0; d < 3; d++) {
        // P = h_v @ Wi_top  (zero bias)
        gemm_fp16<<<gAtom, 256, GSMEM_BYTES>>>(cur, NPAD, KH, cur, NPAD,
                                               p_WiTopT, KH, p_zeroB, p_P, N_ATOMS, 0);
        // agg[v] = sum over in-edges of relu(P[src] + edge_attr @ WiBot)
        gather_agg<<<gather_blocks, 256>>>(p_P, p_eacsr, p_WiBot, p_rowptr, p_esrc, p_agg);
        // h_v = relu([h_v, agg] @ Wo + Wo_b)
        gemm_fp16<<<gAtom, 256, GSMEM_BYTES>>>(cur, NPAD, KH, p_agg, NPAD,
                                               p_WoT, KWO, p_WoB, nxt, N_ATOMS, 1);
        __half* t = cur; cur = nxt; nxt = t;
    }

    // mol_repr = segment_sum(h_v, batch)
    mol_sum<<<(N_MOLS * 32 + 255) / 256, 256>>>(cur, p_molptr, p_mol);
    // ffn = relu(mol @ ffn1 + b1)
    gemm_fp16<<<gMol, 256, GSMEM_BYTES>>>(p_mol, NPAD, KH, p_mol, NPAD,
                                          p_ffn1T, KH, p_ffn1B, p_ffn, N_MOLS, 1);
    // out = ffn @ ffn2 + b2
    finalk<<<(N_MOLS * 32 + 255) / 256, 256>>>(p_ffn, ffn2_W, ffn2_b, out);
}